// round 7
// baseline (speedup 1.0000x reference)
#include <cuda_runtime.h>
#include <cuda_bf16.h>
#include <cstdint>

// Problem constants
#define B_   1024
#define T_   200
#define E_   100
#define H_   200
#define G3_  600      // 3*H
#define NITEMS 100000

#define KPAD 256             // K padded for output GEMM
#define NT2  782             // ceil(100000/128)
#define NPADW (NT2*128)      // 100096

#define GI_KP 112            // K pad for GI GEMM (7 x 16)
#define GI_NP 640            // N pad for GI GEMM (5 x 128)

// Scratch (device globals; allocation is forbidden)
__device__ float g_GI[(size_t)T_ * B_ * G3_]; // gi = x@Wi+bi  [t][b][600] (~492 MB)
__device__ float g_hT[B_ * H_];               // final hidden state [b][200]

// bf16 hi/lo operands for the mma.sync output GEMM
__device__ __nv_bfloat16 g_w_hi[(size_t)KPAD * NPADW];  // [k][n]
__device__ __nv_bfloat16 g_w_lo[(size_t)KPAD * NPADW];
__device__ __nv_bfloat16 g_h_hi[B_ * KPAD];             // [m][k]
__device__ __nv_bfloat16 g_h_lo[B_ * KPAD];
// bf16 hi/lo Wi for the GI GEMM: [t][112][640]
__device__ __nv_bfloat16 g_wi_hi[(size_t)T_ * GI_KP * GI_NP];
__device__ __nv_bfloat16 g_wi_lo[(size_t)T_ * GI_KP * GI_NP];

typedef unsigned long long ull;

static __device__ __forceinline__ ull pack2(float x, float y) {
    ull r; asm("mov.b64 %0, {%1,%2};" : "=l"(r) : "f"(x), "f"(y)); return r;
}
static __device__ __forceinline__ float2 unpack2(ull v) {
    float2 r; asm("mov.b64 {%0,%1}, %2;" : "=f"(r.x), "=f"(r.y) : "l"(v)); return r;
}
static __device__ __forceinline__ void fma2(ull& d, ull a, ull b) {
    asm("fma.rn.f32x2 %0, %1, %2, %0;" : "+l"(d) : "l"(a), "l"(b));
}
static __device__ __forceinline__ float fast_sigmoid(float x) {
    return __fdividef(1.f, 1.f + __expf(-x));
}
static __device__ __forceinline__ float fast_tanh(float x) {
    x = fminf(fmaxf(x, -15.f), 15.f);
    float p = __expf(2.f * x);
    return __fdividef(p - 1.f, p + 1.f);
}
static __device__ __forceinline__ uint32_t smem_u32(const void* p) {
    uint32_t a;
    asm("{ .reg .u64 t; cvta.to.shared.u64 t, %1; cvt.u32.u64 %0, t; }" : "=r"(a) : "l"(p));
    return a;
}

// ---------------- mma.sync helpers (portable HMMA, sm_80+) ----------------
static __device__ __forceinline__ void ldmA(uint32_t* r, uint32_t addr) {
    asm volatile("ldmatrix.sync.aligned.m8n8.x4.shared.b16 {%0,%1,%2,%3}, [%4];"
        : "=r"(r[0]), "=r"(r[1]), "=r"(r[2]), "=r"(r[3]) : "r"(addr));
}
static __device__ __forceinline__ void ldmBT(uint32_t* r, uint32_t addr) {
    asm volatile("ldmatrix.sync.aligned.m8n8.x4.trans.shared.b16 {%0,%1,%2,%3}, [%4];"
        : "=r"(r[0]), "=r"(r[1]), "=r"(r[2]), "=r"(r[3]) : "r"(addr));
}
static __device__ __forceinline__ void mma_bf16(float* c, const uint32_t* a, const uint32_t* b) {
    asm volatile("mma.sync.aligned.m16n8k16.row.col.f32.bf16.bf16.f32 "
        "{%0,%1,%2,%3}, {%4,%5,%6,%7}, {%8,%9}, {%0,%1,%2,%3};"
        : "+f"(c[0]), "+f"(c[1]), "+f"(c[2]), "+f"(c[3])
        : "r"(a[0]), "r"(a[1]), "r"(a[2]), "r"(a[3]), "r"(b[0]), "r"(b[1]));
}
static __device__ __forceinline__ void bf_split(float v, unsigned short& h, unsigned short& l) {
    __nv_bfloat16 hh = __float2bfloat16(v);
    h = __bfloat16_as_ushort(hh);
    l = __bfloat16_as_ushort(__float2bfloat16(v - __bfloat162float(hh)));
}

// ---------------------------------------------------------------------------
// Wi conversion: [200][100][600] fp32 -> [200][112][640] bf16 hi/lo (padded)
// ---------------------------------------------------------------------------
__global__ void k_cvt_wi(const float* __restrict__ Wi) {
    int idx = blockIdx.x * 256 + threadIdx.x;   // 200*112*80
    if (idx >= T_ * GI_KP * 80) return;
    int n8 = idx % 80;
    int k  = (idx / 80) % GI_KP;
    int t  = idx / (80 * GI_KP);
    int n  = n8 * 8;

    union { unsigned short u[8]; uint4 v; } ph, pl;
    #pragma unroll
    for (int j = 0; j < 8; ++j) {
        float v = (k < E_ && n + j < G3_) ? __ldg(Wi + ((size_t)t * E_ + k) * G3_ + n + j) : 0.f;
        bf_split(v, ph.u[j], pl.u[j]);
    }
    size_t dst = ((size_t)t * GI_KP + k) * GI_NP + n;
    *(uint4*)(g_wi_hi + dst) = ph.v;
    *(uint4*)(g_wi_lo + dst) = pl.v;
}

// ---------------------------------------------------------------------------
// K2 tensor: GI[t][b][n] = sum_e (eq[q]*ef[f]) * Wi[t][e][n] + bi[t][n]
// M=128 (batch) x N=128 x K=112, 8 warps (2m x 4n), 3-pass bf16 hi/lo.
// grid = (bt 8, nt 5, t 200), 256 threads.
// ---------------------------------------------------------------------------
#define GI_ASTR 120
#define GI_BSTR 136
#define GI_SMEM ((2*128*GI_ASTR + 2*GI_KP*GI_BSTR) * 2)

__global__ void __launch_bounds__(256, 1)
k_gi_mma(const int* __restrict__ q, const int* __restrict__ f,
         const float* __restrict__ eq, const float* __restrict__ ef,
         const float* __restrict__ bi) {
    extern __shared__ __nv_bfloat16 smem_bf[];
    __nv_bfloat16* sAh = smem_bf;                       // [128][GI_ASTR]
    __nv_bfloat16* sAl = sAh + 128 * GI_ASTR;
    __nv_bfloat16* sBh = sAl + 128 * GI_ASTR;           // [112][GI_BSTR]
    __nv_bfloat16* sBl = sBh + GI_KP * GI_BSTR;
    __shared__ int sq[128], sf[128];

    const int tid  = threadIdx.x;
    const int wid  = tid >> 5, lane = tid & 31;
    const int bt   = blockIdx.x;       // 0..7
    const int nt   = blockIdx.y;       // 0..4
    const int t    = blockIdx.z;       // 0..199
    const int wm   = wid & 1;
    const int wn   = wid >> 1;
    const int b_base = bt * 128;

    if (tid < 128) {
        sq[tid] = __ldg(q + (b_base + tid) * T_ + t);
        sf[tid] = __ldg(f + (b_base + tid) * T_ + t);
    }
    __syncthreads();

    // A fill: fused gather+product -> bf16 hi/lo
    for (int i = tid; i < 128 * GI_KP; i += 256) {
        int m = i / GI_KP, k = i - m * GI_KP;
        float v = (k < E_) ? __ldg(eq + sq[m] * E_ + k) * __ldg(ef + sf[m] * E_ + k) : 0.f;
        unsigned short h, l;
        bf_split(v, h, l);
        sAh[m * GI_ASTR + k] = __ushort_as_bfloat16(h);
        sAl[m * GI_ASTR + k] = __ushort_as_bfloat16(l);
    }
    // B fill: pre-converted Wi tiles, straight uint4 copy
    for (int i = tid; i < GI_KP * 16; i += 256) {
        int k = i >> 4, nb = i & 15;
        size_t src = ((size_t)t * GI_KP + k) * GI_NP + nt * 128 + nb * 8;
        *(uint4*)(sBh + k * GI_BSTR + nb * 8) = *(const uint4*)(g_wi_hi + src);
        *(uint4*)(sBl + k * GI_BSTR + nb * 8) = *(const uint4*)(g_wi_lo + src);
    }
    __syncthreads();

    float acc[4][4][4];
    #pragma unroll
    for (int i = 0; i < 4; ++i)
        #pragma unroll
        for (int j = 0; j < 4; ++j)
            #pragma unroll
            for (int c = 0; c < 4; ++c) acc[i][j][c] = 0.f;

    const uint32_t sAh32 = smem_u32(sAh), sAl32 = smem_u32(sAl);
    const uint32_t sBh32 = smem_u32(sBh), sBl32 = smem_u32(sBl);

    #pragma unroll
    for (int ks = 0; ks < 7; ++ks) {
        uint32_t Ah[4][4], Al[4][4];
        #pragma unroll
        for (int fm = 0; fm < 4; ++fm) {
            uint32_t off = ((wm * 64 + fm * 16 + (lane & 15)) * GI_ASTR
                            + ks * 16 + (lane >> 4) * 8) * 2;
            ldmA(Ah[fm], sAh32 + off);
            ldmA(Al[fm], sAl32 + off);
        }
        uint32_t Bh[4][2], Bl[4][2];
        #pragma unroll
        for (int fb = 0; fb < 2; ++fb) {
            uint32_t off = ((ks * 16 + (lane & 15)) * GI_BSTR
                            + wn * 32 + fb * 16 + (lane >> 4) * 8) * 2;
            uint32_t r[4];
            ldmBT(r, sBh32 + off);
            Bh[fb*2][0] = r[0]; Bh[fb*2][1] = r[1];
            Bh[fb*2+1][0] = r[2]; Bh[fb*2+1][1] = r[3];
            ldmBT(r, sBl32 + off);
            Bl[fb*2][0] = r[0]; Bl[fb*2][1] = r[1];
            Bl[fb*2+1][0] = r[2]; Bl[fb*2+1][1] = r[3];
        }
        #pragma unroll
        for (int fm = 0; fm < 4; ++fm)
            #pragma unroll
            for (int fn = 0; fn < 4; ++fn) {
                mma_bf16(acc[fm][fn], Ah[fm], Bh[fn]);
                mma_bf16(acc[fm][fn], Ah[fm], Bl[fn]);
                mma_bf16(acc[fm][fn], Al[fm], Bh[fn]);
            }
    }

    // Epilogue: add bi, store to g_GI (guard col < 600)
    #pragma unroll
    for (int fm = 0; fm < 4; ++fm) {
        int gm = b_base + wm * 64 + fm * 16 + (lane >> 2);
        #pragma unroll
        for (int fn = 0; fn < 4; ++fn) {
            int gn = nt * 128 + wn * 32 + fn * 8 + (lane & 3) * 2;
            if (gn < G3_) {   // gn even, G3_ even -> pair valid
                float2 bv = __ldg((const float2*)(bi + t * G3_ + gn));
                float2 o0 = make_float2(acc[fm][fn][0] + bv.x, acc[fm][fn][1] + bv.y);
                float2 o1 = make_float2(acc[fm][fn][2] + bv.x, acc[fm][fn][3] + bv.y);
                *(float2*)(g_GI + ((size_t)t * B_ + gm) * G3_ + gn) = o0;
                *(float2*)(g_GI + ((size_t)t * B_ + gm + 8) * G3_ + gn) = o1;
            }
        }
    }
}

// ---------------------------------------------------------------------------
// K3: GRU scan v3. 128 CTAs x 8 rows, 960 threads.
// 900 GEMM threads: col = tid%300 (pair col), qr = tid/300 (k thirds 68/68/64).
// Partial reduction: qr0 -> bufA store, qr2 -> bufB store, qr1 -> bufA add.
// ---------------------------------------------------------------------------
#define SCAN_SMEM (1600*8 + 2*4800*4)   // sh_h2 + bufA + bufB = 51200 B

__global__ void __launch_bounds__(960, 1)
k_scan(const float* __restrict__ Wh, const float* __restrict__ bhn,
       const float* __restrict__ init_carry) {
    extern __shared__ char sdyn[];
    ull*   sh_h2 = (ull*)sdyn;                  // [200][8] duplicated pairs
    float* bufA  = (float*)(sdyn + 1600*8);     // [8][600]
    float* bufB  = bufA + 4800;

    const int tid = threadIdx.x;      // 0..959
    const int b0  = blockIdx.x * 8;

    for (int i = tid; i < 8 * H_; i += 960) {
        float v = __ldg(init_carry + (i >> 3));
        sh_h2[i] = pack2(v, v);
    }
    __syncthreads();

    const int  col   = tid % 300;
    const int  qr    = tid / 300;     // 0,1,2 (3 => idle)
    const bool gemm  = (tid < 900);
    const int  kbase = qr * 68;       // 0, 68, 136
    const int  kcnt  = (qr < 2) ? 68 : 64;

    for (int t = 0; t < T_; ++t) {
        ull acc[8];
        if (gemm) {
            #pragma unroll
            for (int b = 0; b < 8; ++b) acc[b] = 0ULL;

            const ull* wp = (const ull*)(Wh + (size_t)t * (H_ * G3_)) + (size_t)kbase * 300 + col;
            ull wc0 = __ldg(wp);
            ull wc1 = __ldg(wp + 300);
            const ull* wpp = wp + 600;

            #pragma unroll 2
            for (int k0 = 0; k0 < kcnt; k0 += 2) {
                ull wn0 = 0, wn1 = 0;
                if (k0 + 2 < kcnt) {
                    wn0 = __ldg(wpp);
                    wn1 = __ldg(wpp + 300);
                    wpp += 600;
                }
                const ulonglong2* hp = (const ulonglong2*)&sh_h2[(kbase + k0) * 8];
                {
                    ulonglong2 hA = hp[0], hB = hp[1], hC = hp[2], hD = hp[3];
                    fma2(acc[0], hA.x, wc0); fma2(acc[1], hA.y, wc0);
                    fma2(acc[2], hB.x, wc0); fma2(acc[3], hB.y, wc0);
                    fma2(acc[4], hC.x, wc0); fma2(acc[5], hC.y, wc0);
                    fma2(acc[6], hD.x, wc0); fma2(acc[7], hD.y, wc0);
                }
                {
                    ulonglong2 hA = hp[4], hB = hp[5], hC = hp[6], hD = hp[7];
                    fma2(acc[0], hA.x, wc1); fma2(acc[1], hA.y, wc1);
                    fma2(acc[2], hB.x, wc1); fma2(acc[3], hB.y, wc1);
                    fma2(acc[4], hC.x, wc1); fma2(acc[5], hC.y, wc1);
                    fma2(acc[6], hD.x, wc1); fma2(acc[7], hD.y, wc1);
                }
                wc0 = wn0; wc1 = wn1;
            }

            if (qr == 0) {
                #pragma unroll
                for (int b = 0; b < 8; ++b)
                    *(float2*)&bufA[b * G3_ + 2 * col] = unpack2(acc[b]);
            } else if (qr == 2) {
                #pragma unroll
                for (int b = 0; b < 8; ++b)
                    *(float2*)&bufB[b * G3_ + 2 * col] = unpack2(acc[b]);
            }
        }
        __syncthreads();

        if (gemm && qr == 1) {
            #pragma unroll
            for (int b = 0; b < 8; ++b) {
                float2* p = (float2*)&bufA[b * G3_ + 2 * col];
                float2 o = *p;
                float2 m = unpack2(acc[b]);
                o.x += m.x; o.y += m.y;
                *p = o;
            }
        }
        __syncthreads();

        // gate phase: 1600 elements over 960 threads
        for (int i = tid; i < 8 * H_; i += 960) {
            int b = i / H_, j = i - b * H_;
            const float* gi = g_GI + ((size_t)t * B_ + b0 + b) * G3_;
            float ghr = bufA[b * G3_ + j]        + bufB[b * G3_ + j];
            float ghz = bufA[b * G3_ + H_ + j]   + bufB[b * G3_ + H_ + j];
            float ghn = bufA[b * G3_ + 2*H_ + j] + bufB[b * G3_ + 2*H_ + j];
            float r = fast_sigmoid(__ldg(gi + j) + ghr);
            float z = fast_sigmoid(__ldg(gi + H_ + j) + ghz);
            float n = fast_tanh(__ldg(gi + 2 * H_ + j) + r * (ghn + __ldg(bhn + t * H_ + j)));
            float hold = unpack2(sh_h2[j * 8 + b]).x;
            float hnew = (1.f - z) * n + z * hold;
            sh_h2[j * 8 + b] = pack2(hnew, hnew);
        }
        __syncthreads();
    }

    for (int i = tid; i < 8 * H_; i += 960) {
        int b = i / H_, j = i - b * H_;
        g_hT[(b0 + b) * H_ + j] = unpack2(sh_h2[j * 8 + b]).x;
    }
}

// ---------------------------------------------------------------------------
// Conversions to bf16 hi/lo for the output GEMM
// ---------------------------------------------------------------------------
__global__ void k_cvt_w(const float* __restrict__ Wout) {
    int nb = blockIdx.x * 256 + threadIdx.x;
    int k  = blockIdx.y;
    if (nb >= NPADW / 8) return;
    int n = nb * 8;

    union { unsigned short u[8]; uint4 v; } ph, pl;
    if (k < H_ && n + 7 < NITEMS) {
        const float4* src = (const float4*)(Wout + (size_t)k * NITEMS + n);
        float4 v0 = __ldg(src), v1 = __ldg(src + 1);
        float vv[8] = {v0.x, v0.y, v0.z, v0.w, v1.x, v1.y, v1.z, v1.w};
        #pragma unroll
        for (int j = 0; j < 8; ++j) bf_split(vv[j], ph.u[j], pl.u[j]);
    } else {
        #pragma unroll
        for (int j = 0; j < 8; ++j) {
            float v = (k < H_ && n + j < NITEMS) ? __ldg(Wout + (size_t)k * NITEMS + n + j) : 0.f;
            bf_split(v, ph.u[j], pl.u[j]);
        }
    }
    *(uint4*)(g_w_hi + (size_t)k * NPADW + n) = ph.v;
    *(uint4*)(g_w_lo + (size_t)k * NPADW + n) = pl.v;
}

__global__ void k_cvt_h() {
    int idx = blockIdx.x * 256 + threadIdx.x;
    if (idx >= B_ * 32) return;
    int m = idx >> 5, k0 = (idx & 31) * 8;

    union { unsigned short u[8]; uint4 v; } ph, pl;
    #pragma unroll
    for (int j = 0; j < 8; ++j) {
        int k = k0 + j;
        float v = (k < H_) ? g_hT[m * H_ + k] : 0.f;
        bf_split(v, ph.u[j], pl.u[j]);
    }
    *(uint4*)(g_h_hi + m * KPAD + k0) = ph.v;
    *(uint4*)(g_h_lo + m * KPAD + k0) = pl.v;
}

// ---------------------------------------------------------------------------
// K4 mma.sync: out = hT @ Wout + bout, bf16 hi/lo 3-pass (round-6 version)
// ---------------------------------------------------------------------------
#define ASTR 72
#define BSTR 136
#define MMA_SMEM ((2*128*ASTR + 2*64*BSTR) * 2)

__global__ void __launch_bounds__(256, 1)
k_out_mma(const float* __restrict__ bout, float* __restrict__ out) {
    extern __shared__ __nv_bfloat16 smem_bf[];
    __nv_bfloat16* sAh = smem_bf;
    __nv_bfloat16* sAl = sAh + 128 * ASTR;
    __nv_bfloat16* sBh = sAl + 128 * ASTR;
    __nv_bfloat16* sBl = sBh + 64 * BSTR;

    const int tid  = threadIdx.x;
    const int wid  = tid >> 5, lane = tid & 31;
    const int mt   = blockIdx.x;
    const int nt   = blockIdx.y;
    const int wm   = wid & 1;
    const int wn   = wid >> 1;

    float acc[4][4][4];
    #pragma unroll
    for (int i = 0; i < 4; ++i)
        #pragma unroll
        for (int j = 0; j < 4; ++j)
            #pragma unroll
            for (int c = 0; c < 4; ++c) acc[i][j][c] = 0.f;

    const uint32_t sAh32 = smem_u32(sAh), sAl32 = smem_u32(sAl);
    const uint32_t sBh32 = smem_u32(sBh), sBl32 = smem_u32(sBl);

    for (int kc = 0; kc < 4; ++kc) {
        for (int i = tid; i < 1024; i += 256) {
            int m = i >> 3, kb = i & 7;
            size_t src = (size_t)(mt * 128 + m) * KPAD + kc * 64 + kb * 8;
            *(uint4*)(sAh + m * ASTR + kb * 8) = *(const uint4*)(g_h_hi + src);
            *(uint4*)(sAl + m * ASTR + kb * 8) = *(const uint4*)(g_h_lo + src);
        }
        for (int i = tid; i < 1024; i += 256) {
            int k = i >> 4, nb = i & 15;
            size_t src = (size_t)(kc * 64 + k) * NPADW + nt * 128 + nb * 8;
            *(uint4*)(sBh + k * BSTR + nb * 8) = *(const uint4*)(g_w_hi + src);
            *(uint4*)(sBl + k * BSTR + nb * 8) = *(const uint4*)(g_w_lo + src);
        }
        __syncthreads();

        #pragma unroll
        for (int ks = 0; ks < 4; ++ks) {
            uint32_t Ah[4][4], Al[4][4];
            #pragma unroll
            for (int fm = 0; fm < 4; ++fm) {
                uint32_t off = ((wm * 64 + fm * 16 + (lane & 15)) * ASTR
                                + ks * 16 + (lane >> 4) * 8) * 2;
                ldmA(Ah[fm], sAh32 + off);
                ldmA(Al[fm], sAl32 + off);
            }
            uint32_t Bh[4][2], Bl[4][2];
            #pragma unroll
            for (int fb = 0; fb < 2; ++fb) {
                uint32_t off = ((ks * 16 + (lane & 15)) * BSTR
                                + wn * 32 + fb * 16 + (lane >> 4) * 8) * 2;
                uint32_t r[4];
                ldmBT(r, sBh32 + off);
                Bh[fb*2][0] = r[0]; Bh[fb*2][1] = r[1];
                Bh[fb*2+1][0] = r[2]; Bh[fb*2+1][1] = r[3];
                ldmBT(r, sBl32 + off);
                Bl[fb*2][0] = r[0]; Bl[fb*2][1] = r[1];
                Bl[fb*2+1][0] = r[2]; Bl[fb*2+1][1] = r[3];
            }
            #pragma unroll
            for (int fm = 0; fm < 4; ++fm)
                #pragma unroll
                for (int fn = 0; fn < 4; ++fn) {
                    mma_bf16(acc[fm][fn], Ah[fm], Bh[fn]);
                    mma_bf16(acc[fm][fn], Ah[fm], Bl[fn]);
                    mma_bf16(acc[fm][fn], Al[fm], Bh[fn]);
                }
        }
        __syncthreads();
    }

    #pragma unroll
    for (int fm = 0; fm < 4; ++fm) {
        int gm = mt * 128 + wm * 64 + fm * 16 + (lane >> 2);
        #pragma unroll
        for (int fn = 0; fn < 4; ++fn) {
            int gn = nt * 128 + wn * 32 + fn * 8 + (lane & 3) * 2;
            if (gn < NITEMS) {
                float2 bv = __ldg((const float2*)(bout + gn));
                float2 o0 = make_float2(acc[fm][fn][0] + bv.x, acc[fm][fn][1] + bv.y);
                float2 o1 = make_float2(acc[fm][fn][2] + bv.x, acc[fm][fn][3] + bv.y);
                *(float2*)(out + (size_t)gm * NITEMS + gn) = o0;
                *(float2*)(out + (size_t)(gm + 8) * NITEMS + gn) = o1;
            }
        }
    }
}

// ---------------------------------------------------------------------------
extern "C" void kernel_launch(void* const* d_in, const int* in_sizes, int n_in,
                              void* d_out, int out_size) {
    const int*   q    = (const int*)  d_in[0];
    const int*   f    = (const int*)  d_in[1];
    const float* eq   = (const float*)d_in[2];
    const float* ef   = (const float*)d_in[3];
    const float* ic   = (const float*)d_in[4];
    const float* Wi   = (const float*)d_in[5];
    const float* bi   = (const float*)d_in[6];
    const float* Wh   = (const float*)d_in[7];
    const float* bhn  = (const float*)d_in[8];
    const float* Wout = (const float*)d_in[9];
    const float* bout = (const float*)d_in[10];
    float* out = (float*)d_out;

    static bool attr_done = false;
    if (!attr_done) {
        cudaFuncSetAttribute(k_gi_mma,  cudaFuncAttributeMaxDynamicSharedMemorySize, GI_SMEM);
        cudaFuncSetAttribute(k_scan,    cudaFuncAttributeMaxDynamicSharedMemorySize, SCAN_SMEM);
        cudaFuncSetAttribute(k_out_mma, cudaFuncAttributeMaxDynamicSharedMemorySize, MMA_SMEM);
        attr_done = true;
    }

    // Wout -> bf16 hi/lo (independent)
    {
        dim3 grid((NPADW / 8 + 255) / 256, KPAD);
        k_cvt_w<<<grid, 256>>>(Wout);
    }
    // Wi -> padded bf16 hi/lo
    k_cvt_wi<<<(T_ * GI_KP * 80 + 255) / 256, 256>>>(Wi);
    // GI = (gathered state) @ Wi + bi (tensor cores)
    {
        dim3 grid(8, 5, 200);
        k_gi_mma<<<grid, 256, GI_SMEM>>>(q, f, eq, ef, bi);
    }
    // GRU scan
    k_scan<<<128, 960, SCAN_SMEM>>>(Wh, bhn, ic);
    // hT -> bf16 hi/lo
    k_cvt_h<<<(B_ * 32 + 255) / 256, 256>>>();
    // out = hT @ Wout + bout (tensor cores)
    {
        dim3 grid(8, NT2);
        k_out_mma<<<grid, 256, MMA_SMEM>>>(bout, out);
    }
}

// round 8
// speedup vs baseline: 1.2153x; 1.2153x over previous
#include <cuda_runtime.h>
#include <cuda_bf16.h>
#include <cstdint>

// Problem constants
#define B_   1024
#define T_   200
#define E_   100
#define H_   200
#define G3_  600      // 3*H
#define NITEMS 100000

#define KPAD 256             // K padded for output GEMM
#define NT2  782             // ceil(100000/128)
#define NPADW (NT2*128)      // 100096

// Scratch (device globals; allocation is forbidden)
__device__ float g_GI[(size_t)T_ * B_ * G3_]; // gi = x@Wi+bi  [t][b][600]
__device__ float g_hT[B_ * H_];               // final hidden state [b][200]

// bf16 hi/lo operands for the mma.sync output GEMM
__device__ __nv_bfloat16 g_w_hi[(size_t)KPAD * NPADW];  // [k][n]
__device__ __nv_bfloat16 g_w_lo[(size_t)KPAD * NPADW];
__device__ __nv_bfloat16 g_h_hi[B_ * KPAD];             // [m][k]
__device__ __nv_bfloat16 g_h_lo[B_ * KPAD];
// Wh pre-fragged for scan mma: [t][mt 40][ks 13][lane 32] uint4 (a0..a3 bf16 pairs)
__device__ uint4 g_whf_hi[(size_t)T_ * 40 * 13 * 32];
__device__ uint4 g_whf_lo[(size_t)T_ * 40 * 13 * 32];

typedef unsigned long long ull;

static __device__ __forceinline__ ull pack2(float x, float y) {
    ull r; asm("mov.b64 %0, {%1,%2};" : "=l"(r) : "f"(x), "f"(y)); return r;
}
static __device__ __forceinline__ float2 unpack2(ull v) {
    float2 r; asm("mov.b64 {%0,%1}, %2;" : "=f"(r.x), "=f"(r.y) : "l"(v)); return r;
}
static __device__ __forceinline__ void fma2(ull& d, ull a, ull b) {
    asm("fma.rn.f32x2 %0, %1, %2, %0;" : "+l"(d) : "l"(a), "l"(b));
}
static __device__ __forceinline__ float fast_sigmoid(float x) {
    return __fdividef(1.f, 1.f + __expf(-x));
}
static __device__ __forceinline__ float fast_tanh(float x) {
    x = fminf(fmaxf(x, -15.f), 15.f);
    float p = __expf(2.f * x);
    return __fdividef(p - 1.f, p + 1.f);
}
static __device__ __forceinline__ uint32_t smem_u32(const void* p) {
    uint32_t a;
    asm("{ .reg .u64 t; cvta.to.shared.u64 t, %1; cvt.u32.u64 %0, t; }" : "=r"(a) : "l"(p));
    return a;
}

// ---------------- mma.sync helpers (portable HMMA, sm_80+) ----------------
static __device__ __forceinline__ void ldmA(uint32_t* r, uint32_t addr) {
    asm volatile("ldmatrix.sync.aligned.m8n8.x4.shared.b16 {%0,%1,%2,%3}, [%4];"
        : "=r"(r[0]), "=r"(r[1]), "=r"(r[2]), "=r"(r[3]) : "r"(addr));
}
static __device__ __forceinline__ void ldmBT(uint32_t* r, uint32_t addr) {
    asm volatile("ldmatrix.sync.aligned.m8n8.x4.trans.shared.b16 {%0,%1,%2,%3}, [%4];"
        : "=r"(r[0]), "=r"(r[1]), "=r"(r[2]), "=r"(r[3]) : "r"(addr));
}
static __device__ __forceinline__ void mma_bf16(float* c, const uint32_t* a, const uint32_t* b) {
    asm volatile("mma.sync.aligned.m16n8k16.row.col.f32.bf16.bf16.f32 "
        "{%0,%1,%2,%3}, {%4,%5,%6,%7}, {%8,%9}, {%0,%1,%2,%3};"
        : "+f"(c[0]), "+f"(c[1]), "+f"(c[2]), "+f"(c[3])
        : "r"(a[0]), "r"(a[1]), "r"(a[2]), "r"(a[3]), "r"(b[0]), "r"(b[1]));
}
static __device__ __forceinline__ void bf_split(float v, unsigned short& h, unsigned short& l) {
    __nv_bfloat16 hh = __float2bfloat16(v);
    h = __bfloat16_as_ushort(hh);
    l = __bfloat16_as_ushort(__float2bfloat16(v - __bfloat162float(hh)));
}
// pack two floats -> bf16x2 hi and lo-residual bf16x2 (low half = v0)
static __device__ __forceinline__ void pack_split2(float v0, float v1, uint32_t& hi2, uint32_t& lo2) {
    asm("cvt.rn.bf16x2.f32 %0, %1, %2;" : "=r"(hi2) : "f"(v1), "f"(v0));
    float h0 = __uint_as_float(hi2 << 16);
    float h1 = __uint_as_float((hi2 >> 16) << 16);
    asm("cvt.rn.bf16x2.f32 %0, %1, %2;" : "=r"(lo2) : "f"(v1 - h1), "f"(v0 - h0));
}

// ---------------------------------------------------------------------------
// K2 SIMT (fused embed+GI)
// ---------------------------------------------------------------------------
#define K2_AP 136
#define K2_BP 124
#define K2_SMEM ((100*K2_AP + 100*K2_BP) * 4 + 128*2*4)

__global__ void __launch_bounds__(256, 2)
k_gi(const int* __restrict__ q, const int* __restrict__ f,
     const float* __restrict__ eq, const float* __restrict__ ef,
     const float* __restrict__ Wi, const float* __restrict__ bi) {
    extern __shared__ float smem[];
    float* As = smem;
    float* Bs = smem + 100 * K2_AP;
    int*   sq = (int*)(smem + 100 * K2_AP + 100 * K2_BP);
    int*   sf = sq + 128;

    const int bt = blockIdx.x;
    const int nt = blockIdx.y;
    const int t  = blockIdx.z;
    const int tid = threadIdx.x;
    const int b_base = bt * 128;

    if (tid < 128) {
        sq[tid] = __ldg(q + (b_base + tid) * T_ + t);
        sf[tid] = __ldg(f + (b_base + tid) * T_ + t);
    }
    __syncthreads();

    for (int i = tid; i < 128 * 100; i += 256) {
        int m = i / 100, e = i - m * 100;
        As[e * K2_AP + m] = __ldg(eq + sq[m] * E_ + e) * __ldg(ef + sf[m] * E_ + e);
    }
    for (int i = tid; i < 100 * 120; i += 256) {
        int kk = i / 120, nn = i - kk * 120;
        Bs[kk * K2_BP + nn] = __ldg(Wi + (size_t)(t * E_ + kk) * G3_ + nt * 120 + nn);
    }
    __syncthreads();

    if (tid < 240) {
        const int tx = tid % 15;
        const int ty = tid / 15;

        ull acc[8][4];
        #pragma unroll
        for (int r = 0; r < 8; ++r)
            #pragma unroll
            for (int c = 0; c < 4; ++c) acc[r][c] = 0ULL;

        #pragma unroll 4
        for (int kk = 0; kk < 100; ++kk) {
            const float* ap = &As[kk * K2_AP + ty * 8];
            float4 a0 = *(const float4*)ap;
            float4 a1 = *(const float4*)(ap + 4);
            const ulonglong2* bp = (const ulonglong2*)&Bs[kk * K2_BP + tx * 8];
            ulonglong2 bA = bp[0], bB = bp[1];
            ull ad;
            ad = pack2(a0.x, a0.x); fma2(acc[0][0], ad, bA.x); fma2(acc[0][1], ad, bA.y); fma2(acc[0][2], ad, bB.x); fma2(acc[0][3], ad, bB.y);
            ad = pack2(a0.y, a0.y); fma2(acc[1][0], ad, bA.x); fma2(acc[1][1], ad, bA.y); fma2(acc[1][2], ad, bB.x); fma2(acc[1][3], ad, bB.y);
            ad = pack2(a0.z, a0.z); fma2(acc[2][0], ad, bA.x); fma2(acc[2][1], ad, bA.y); fma2(acc[2][2], ad, bB.x); fma2(acc[2][3], ad, bB.y);
            ad = pack2(a0.w, a0.w); fma2(acc[3][0], ad, bA.x); fma2(acc[3][1], ad, bA.y); fma2(acc[3][2], ad, bB.x); fma2(acc[3][3], ad, bB.y);
            ad = pack2(a1.x, a1.x); fma2(acc[4][0], ad, bA.x); fma2(acc[4][1], ad, bA.y); fma2(acc[4][2], ad, bB.x); fma2(acc[4][3], ad, bB.y);
            ad = pack2(a1.y, a1.y); fma2(acc[5][0], ad, bA.x); fma2(acc[5][1], ad, bA.y); fma2(acc[5][2], ad, bB.x); fma2(acc[5][3], ad, bB.y);
            ad = pack2(a1.z, a1.z); fma2(acc[6][0], ad, bA.x); fma2(acc[6][1], ad, bA.y); fma2(acc[6][2], ad, bB.x); fma2(acc[6][3], ad, bB.y);
            ad = pack2(a1.w, a1.w); fma2(acc[7][0], ad, bA.x); fma2(acc[7][1], ad, bA.y); fma2(acc[7][2], ad, bB.x); fma2(acc[7][3], ad, bB.y);
        }

        const int col = nt * 120 + tx * 8;
        float4 bi0 = *(const float4*)(bi + t * G3_ + col);
        float4 bi1 = *(const float4*)(bi + t * G3_ + col + 4);
        #pragma unroll
        for (int r = 0; r < 8; ++r) {
            int row = b_base + ty * 8 + r;
            float* dst = g_GI + ((size_t)t * B_ + row) * G3_ + col;
            float2 v0 = unpack2(acc[r][0]), v1 = unpack2(acc[r][1]);
            float2 v2 = unpack2(acc[r][2]), v3 = unpack2(acc[r][3]);
            *(float4*)dst       = make_float4(v0.x + bi0.x, v0.y + bi0.y, v1.x + bi0.z, v1.y + bi0.w);
            *(float4*)(dst + 4) = make_float4(v2.x + bi1.x, v2.y + bi1.y, v3.x + bi1.z, v3.y + bi1.w);
        }
    }
}

// ---------------------------------------------------------------------------
// Wh -> fragment layout conversion (once).
// A[m][k] = Wh[t][k][m]; frag a0..a3 per lane of m16n8k16; M pad 640, K pad 208.
// ---------------------------------------------------------------------------
__global__ void __launch_bounds__(128)
k_cvt_whf(const float* __restrict__ Wh) {
    __shared__ float sA[208][17];
    const int mt = blockIdx.x;   // 0..39
    const int t  = blockIdx.y;   // 0..199
    const int tid = threadIdx.x;
    const int m0 = mt * 16;

    for (int i = tid; i < 208 * 16; i += 128) {
        int k = i >> 4, mm = i & 15;
        int m = m0 + mm;
        float v = (k < H_ && m < G3_) ? __ldg(Wh + ((size_t)t * H_ + k) * G3_ + m) : 0.f;
        sA[k][mm] = v;
    }
    __syncthreads();

    const int wid = tid >> 5, lane = tid & 31;
    const int g = lane >> 2, c = lane & 3;
    for (int ks = wid; ks < 13; ks += 4) {
        int k0 = ks * 16 + 2 * c;
        uint4 uh, ul;
        pack_split2(sA[k0][g],       sA[k0 + 1][g],     uh.x, ul.x);
        pack_split2(sA[k0][g + 8],   sA[k0 + 1][g + 8], uh.y, ul.y);
        pack_split2(sA[k0 + 8][g],   sA[k0 + 9][g],     uh.z, ul.z);
        pack_split2(sA[k0 + 8][g+8], sA[k0 + 9][g + 8], uh.w, ul.w);
        size_t idx = (((size_t)t * 40 + mt) * 13 + ks) * 32 + lane;
        g_whf_hi[idx] = uh;
        g_whf_lo[idx] = ul;
    }
}

// ---------------------------------------------------------------------------
// K3: GRU scan v4 (tensor cores). 64 CTAs x 16 batch rows, 512 threads.
// Per step: gh^T[640][16] = Wh^T (fragged gmem bf16 hi/lo) @ h^T (smem bf16 hi/lo)
// 3-pass mma.sync m16n8k16; gi prefetched via cp.async; gates in fp32.
// ---------------------------------------------------------------------------
#define SOFF_GI   0                      // [16][600] f32    38400
#define SOFF_GH   38400                  // [640][18] f32    46080
#define SOFF_HF   84480                  // [16][200] f32    12800
#define SOFF_HHI  97280                  // [16][132] u32    8448
#define SOFF_HLO  105728                 //                   8448
#define SOFF_BHN  114176                 // [200] f32        800
#define SCAN_SMEM 114976

__global__ void __launch_bounds__(512, 1)
k_scan_mma(const float* __restrict__ bhn, const float* __restrict__ ic) {
    extern __shared__ char sm[];
    float*    sgi = (float*)(sm + SOFF_GI);
    float*    sgh = (float*)(sm + SOFF_GH);
    float*    shf = (float*)(sm + SOFF_HF);
    uint32_t* hh  = (uint32_t*)(sm + SOFF_HHI);
    uint32_t* hl  = (uint32_t*)(sm + SOFF_HLO);
    float*    sbh = (float*)(sm + SOFF_BHN);

    const int tid  = threadIdx.x;
    const int wid  = tid >> 5, lane = tid & 31;
    const int b0   = blockIdx.x * 16;
    const int g    = lane >> 2, cc = lane & 3;
    const uint32_t sgi_a = smem_u32(sgi);
    const uint32_t sbh_a = smem_u32(sbh);
    const int nmt = (wid < 8) ? 3 : 2;

    // init h (fp32 + bf16 hi/lo; k 200..207 zero)
    for (int i = tid; i < 16 * 132; i += 512) {
        int w = i % 132;
        uint32_t hi2 = 0, lo2 = 0;
        if (w < 100) {
            float v0 = __ldg(ic + 2 * w), v1 = __ldg(ic + 2 * w + 1);
            pack_split2(v0, v1, hi2, lo2);
        }
        hh[i] = hi2; hl[i] = lo2;
    }
    for (int i = tid; i < 3200; i += 512)
        shf[i] = __ldg(ic + (i % 200));
    __syncthreads();

    float acc[3][2][4];

    for (int t = 0; t < T_; ++t) {
        // --- prefetch gi[t] + bhn[t] via cp.async (consumed after GEMM) ---
        {
            const float* gib = g_GI + ((size_t)t * B_ + b0) * G3_;
            for (int i = tid; i < 2450; i += 512) {
                if (i < 2400) {
                    int b = i / 150, o = (i - b * 150) * 16;
                    uint32_t dst = sgi_a + b * 2400 + o;
                    const char* src = (const char*)(gib + b * G3_) + o;
                    asm volatile("cp.async.cg.shared.global [%0], [%1], 16;" :: "r"(dst), "l"(src) : "memory");
                } else {
                    int j = i - 2400;
                    uint32_t dst = sbh_a + j * 16;
                    const char* src = (const char*)(bhn + t * H_) + j * 16;
                    asm volatile("cp.async.cg.shared.global [%0], [%1], 16;" :: "r"(dst), "l"(src) : "memory");
                }
            }
            asm volatile("cp.async.commit_group;" ::: "memory");
        }

        // --- GEMM phase ---
        #pragma unroll
        for (int m = 0; m < 3; ++m)
            #pragma unroll
            for (int n = 0; n < 2; ++n)
                #pragma unroll
                for (int c = 0; c < 4; ++c) acc[m][n][c] = 0.f;

        size_t tb = (size_t)t * 40;
        const uint4* p0h = g_whf_hi + ((tb + wid)      * 13) * 32 + lane;
        const uint4* p1h = g_whf_hi + ((tb + 16 + wid) * 13) * 32 + lane;
        const uint4* p2h = g_whf_hi + ((tb + 32 + wid) * 13) * 32 + lane;
        const uint4* p0l = g_whf_lo + ((tb + wid)      * 13) * 32 + lane;
        const uint4* p1l = g_whf_lo + ((tb + 16 + wid) * 13) * 32 + lane;
        const uint4* p2l = g_whf_lo + ((tb + 32 + wid) * 13) * 32 + lane;

        uint4 ah0 = __ldg(p0h), al0 = __ldg(p0l);
        uint4 ah1 = __ldg(p1h), al1 = __ldg(p1l);
        uint4 ah2, al2;
        if (nmt == 3) { ah2 = __ldg(p2h); al2 = __ldg(p2l); }

        for (int ks = 0; ks < 13; ++ks) {
            uint4 nh0, nl0, nh1, nl1, nh2, nl2;
            if (ks < 12) {
                int off = (ks + 1) * 32;
                nh0 = __ldg(p0h + off); nl0 = __ldg(p0l + off);
                nh1 = __ldg(p1h + off); nl1 = __ldg(p1l + off);
                if (nmt == 3) { nh2 = __ldg(p2h + off); nl2 = __ldg(p2l + off); }
            }
            // B fragments from smem bf16 pairs
            int k2 = ks * 8;
            uint32_t bh0[2], bl0[2], bh1[2], bl1[2];
            {
                int r0 = g * 132 + k2 + cc;
                bh0[0] = hh[r0]; bh0[1] = hh[r0 + 4];
                bl0[0] = hl[r0]; bl0[1] = hl[r0 + 4];
                int r1 = (g + 8) * 132 + k2 + cc;
                bh1[0] = hh[r1]; bh1[1] = hh[r1 + 4];
                bl1[0] = hl[r1]; bl1[1] = hl[r1 + 4];
            }
            {
                uint32_t ah[4] = {ah0.x, ah0.y, ah0.z, ah0.w};
                uint32_t al[4] = {al0.x, al0.y, al0.z, al0.w};
                mma_bf16(acc[0][0], ah, bh0); mma_bf16(acc[0][0], ah, bl0); mma_bf16(acc[0][0], al, bh0);
                mma_bf16(acc[0][1], ah, bh1); mma_bf16(acc[0][1], ah, bl1); mma_bf16(acc[0][1], al, bh1);
            }
            {
                uint32_t ah[4] = {ah1.x, ah1.y, ah1.z, ah1.w};
                uint32_t al[4] = {al1.x, al1.y, al1.z, al1.w};
                mma_bf16(acc[1][0], ah, bh0); mma_bf16(acc[1][0], ah, bl0); mma_bf16(acc[1][0], al, bh0);
                mma_bf16(acc[1][1], ah, bh1); mma_bf16(acc[1][1], ah, bl1); mma_bf16(acc[1][1], al, bh1);
            }
            if (nmt == 3) {
                uint32_t ah[4] = {ah2.x, ah2.y, ah2.z, ah2.w};
                uint32_t al[4] = {al2.x, al2.y, al2.z, al2.w};
                mma_bf16(acc[2][0], ah, bh0); mma_bf16(acc[2][0], ah, bl0); mma_bf16(acc[2][0], al, bh0);
                mma_bf16(acc[2][1], ah, bh1); mma_bf16(acc[2][1], ah, bl1); mma_bf16(acc[2][1], al, bh1);
            }
            if (ks < 12) {
                ah0 = nh0; al0 = nl0;
                ah1 = nh1; al1 = nl1;
                if (nmt == 3) { ah2 = nh2; al2 = nl2; }
            }
        }

        // epilogue: c-frags -> sgh[col][b] (stride 18)
        #pragma unroll
        for (int m = 0; m < 3; ++m) {
            if (m < nmt) {
                int m0 = (m == 0 ? wid : (m == 1 ? 16 + wid : 32 + wid)) * 16;
                #pragma unroll
                for (int n = 0; n < 2; ++n) {
                    int colb = n * 8 + cc * 2;
                    *(float2*)&sgh[(m0 + g) * 18 + colb]     = make_float2(acc[m][n][0], acc[m][n][1]);
                    *(float2*)&sgh[(m0 + g + 8) * 18 + colb] = make_float2(acc[m][n][2], acc[m][n][3]);
                }
            }
        }

        asm volatile("cp.async.wait_group 0;" ::: "memory");
        __syncthreads();

        // --- gate phase: 1600 (b, j-pair) items ---
        for (int i = tid; i < 1600; i += 512) {
            int b = i / 100, jp = i - b * 100, j = jp * 2;
            const float* gib = sgi + b * G3_;
            float2 gr = *(const float2*)(gib + j);
            float2 gz = *(const float2*)(gib + 200 + j);
            float2 gn = *(const float2*)(gib + 400 + j);
            float ghr0 = sgh[j * 18 + b],         ghr1 = sgh[(j + 1) * 18 + b];
            float ghz0 = sgh[(200 + j) * 18 + b], ghz1 = sgh[(201 + j) * 18 + b];
            float ghn0 = sgh[(400 + j) * 18 + b], ghn1 = sgh[(401 + j) * 18 + b];
            float2 bv = *(const float2*)(sbh + j);
            float2 ho = *(const float2*)(shf + b * 200 + j);
            float r0 = fast_sigmoid(gr.x + ghr0), r1 = fast_sigmoid(gr.y + ghr1);
            float z0 = fast_sigmoid(gz.x + ghz0), z1 = fast_sigmoid(gz.y + ghz1);
            float n0 = fast_tanh(gn.x + r0 * (ghn0 + bv.x));
            float n1 = fast_tanh(gn.y + r1 * (ghn1 + bv.y));
            float h0 = (1.f - z0) * n0 + z0 * ho.x;
            float h1 = (1.f - z1) * n1 + z1 * ho.y;
            *(float2*)(shf + b * 200 + j) = make_float2(h0, h1);
            uint32_t hi2, lo2;
            pack_split2(h0, h1, hi2, lo2);
            hh[b * 132 + jp] = hi2;
            hl[b * 132 + jp] = lo2;
        }
        __syncthreads();
    }

    for (int i = tid; i < 3200; i += 512) {
        int b = i / 200, j = i - b * 200;
        g_hT[(b0 + b) * H_ + j] = shf[i];
    }
}

// ---------------------------------------------------------------------------
// Conversions to bf16 hi/lo for the output GEMM
// ---------------------------------------------------------------------------
__global__ void k_cvt_w(const float* __restrict__ Wout) {
    int nb = blockIdx.x * 256 + threadIdx.x;
    int k  = blockIdx.y;
    if (nb >= NPADW / 8) return;
    int n = nb * 8;

    union { unsigned short u[8]; uint4 v; } ph, pl;
    if (k < H_ && n + 7 < NITEMS) {
        const float4* src = (const float4*)(Wout + (size_t)k * NITEMS + n);
        float4 v0 = __ldg(src), v1 = __ldg(src + 1);
        float vv[8] = {v0.x, v0.y, v0.z, v0.w, v1.x, v1.y, v1.z, v1.w};
        #pragma unroll
        for (int j = 0; j < 8; ++j) bf_split(vv[j], ph.u[j], pl.u[j]);
    } else {
        #pragma unroll
        for (int j = 0; j < 8; ++j) {
            float v = (k < H_ && n + j < NITEMS) ? __ldg(Wout + (size_t)k * NITEMS + n + j) : 0.f;
            bf_split(v, ph.u[j], pl.u[j]);
        }
    }
    *(uint4*)(g_w_hi + (size_t)k * NPADW + n) = ph.v;
    *(uint4*)(g_w_lo + (size_t)k * NPADW + n) = pl.v;
}

__global__ void k_cvt_h() {
    int idx = blockIdx.x * 256 + threadIdx.x;
    if (idx >= B_ * 32) return;
    int m = idx >> 5, k0 = (idx & 31) * 8;

    union { unsigned short u[8]; uint4 v; } ph, pl;
    #pragma unroll
    for (int j = 0; j < 8; ++j) {
        int k = k0 + j;
        float v = (k < H_) ? g_hT[m * H_ + k] : 0.f;
        bf_split(v, ph.u[j], pl.u[j]);
    }
    *(uint4*)(g_h_hi + m * KPAD + k0) = ph.v;
    *(uint4*)(g_h_lo + m * KPAD + k0) = pl.v;
}

// ---------------------------------------------------------------------------
// K4 mma.sync: out = hT @ Wout + bout, bf16 hi/lo 3-pass
// ---------------------------------------------------------------------------
#define ASTR 72
#define BSTR 136
#define MMA_SMEM ((2*128*ASTR + 2*64*BSTR) * 2)

__global__ void __launch_bounds__(256, 1)
k_out_mma(const float* __restrict__ bout, float* __restrict__ out) {
    extern __shared__ __nv_bfloat16 smem_bf[];
    __nv_bfloat16* sAh = smem_bf;
    __nv_bfloat16* sAl = sAh + 128 * ASTR;
    __nv_bfloat16* sBh = sAl + 128 * ASTR;
    __nv_bfloat16* sBl = sBh + 64 * BSTR;

    const int tid  = threadIdx.x;
    const int wid  = tid >> 5, lane = tid & 31;
    const int mt   = blockIdx.x;
    const int nt   = blockIdx.y;
    const int wm   = wid & 1;
    const int wn   = wid >> 1;

    float acc[4][4][4];
    #pragma unroll
    for (int i = 0; i < 4; ++i)
        #pragma unroll
        for (int j = 0; j < 4; ++j)
            #pragma unroll
            for (int c = 0; c < 4; ++c) acc[i][j][c] = 0.f;

    const uint32_t sAh32 = smem_u32(sAh), sAl32 = smem_u32(sAl);
    const uint32_t sBh32 = smem_u32(sBh), sBl32 = smem_u32(sBl);

    for (int kc = 0; kc < 4; ++kc) {
        for (int i = tid; i < 1024; i += 256) {
            int m = i >> 3, kb = i & 7;
            size_t src = (size_t)(mt * 128 + m) * KPAD + kc * 64 + kb * 8;
            *(uint4*)(sAh + m * ASTR + kb * 8) = *(const uint4*)(g_h_hi + src);
            *(uint4*)(sAl + m * ASTR + kb * 8) = *(const uint4*)(g_h_lo + src);
        }
        for (int i = tid; i < 1024; i += 256) {
            int k = i >> 4, nb = i & 15;
            size_t src = (size_t)(kc * 64 + k) * NPADW + nt * 128 + nb * 8;
            *(uint4*)(sBh + k * BSTR + nb * 8) = *(const uint4*)(g_w_hi + src);
            *(uint4*)(sBl + k * BSTR + nb * 8) = *(const uint4*)(g_w_lo + src);
        }
        __syncthreads();

        #pragma unroll
        for (int ks = 0; ks < 4; ++ks) {
            uint32_t Ah[4][4], Al[4][4];
            #pragma unroll
            for (int fm = 0; fm < 4; ++fm) {
                uint32_t off = ((wm * 64 + fm * 16 + (lane & 15)) * ASTR
                                + ks * 16 + (lane >> 4) * 8) * 2;
                ldmA(Ah[fm], sAh32 + off);
                ldmA(Al[fm], sAl32 + off);
            }
            uint32_t Bh[4][2], Bl[4][2];
            #pragma unroll
            for (int fb = 0; fb < 2; ++fb) {
                uint32_t off = ((ks * 16 + (lane & 15)) * BSTR
                                + wn * 32 + fb * 16 + (lane >> 4) * 8) * 2;
                uint32_t r[4];
                ldmBT(r, sBh32 + off);
                Bh[fb*2][0] = r[0]; Bh[fb*2][1] = r[1];
                Bh[fb*2+1][0] = r[2]; Bh[fb*2+1][1] = r[3];
                ldmBT(r, sBl32 + off);
                Bl[fb*2][0] = r[0]; Bl[fb*2][1] = r[1];
                Bl[fb*2+1][0] = r[2]; Bl[fb*2+1][1] = r[3];
            }
            #pragma unroll
            for (int fm = 0; fm < 4; ++fm)
                #pragma unroll
                for (int fn = 0; fn < 4; ++fn) {
                    mma_bf16(acc[fm][fn], Ah[fm], Bh[fn]);
                    mma_bf16(acc[fm][fn], Ah[fm], Bl[fn]);
                    mma_bf16(acc[fm][fn], Al[fm], Bh[fn]);
                }
        }
        __syncthreads();
    }

    #pragma unroll
    for (int fm = 0; fm < 4; ++fm) {
        int gm = mt * 128 + wm * 64 + fm * 16 + (lane >> 2);
        #pragma unroll
        for (int fn = 0; fn < 4; ++fn) {
            int gn = nt * 128 + wn * 32 + fn * 8 + (lane & 3) * 2;
            if (gn < NITEMS) {
                float2 bv = __ldg((const float2*)(bout + gn));
                float2 o0 = make_float2(acc[fm][fn][0] + bv.x, acc[fm][fn][1] + bv.y);
                float2 o1 = make_float2(acc[fm][fn][2] + bv.x, acc[fm][fn][3] + bv.y);
                *(float2*)(out + (size_t)gm * NITEMS + gn) = o0;
                *(float2*)(out + (size_t)(gm + 8) * NITEMS + gn) = o1;
            }
        }
    }
}

// ---------------------------------------------------------------------------
extern "C" void kernel_launch(void* const* d_in, const int* in_sizes, int n_in,
                              void* d_out, int out_size) {
    const int*   q    = (const int*)  d_in[0];
    const int*   f    = (const int*)  d_in[1];
    const float* eq   = (const float*)d_in[2];
    const float* ef   = (const float*)d_in[3];
    const float* ic   = (const float*)d_in[4];
    const float* Wi   = (const float*)d_in[5];
    const float* bi   = (const float*)d_in[6];
    const float* Wh   = (const float*)d_in[7];
    const float* bhn  = (const float*)d_in[8];
    const float* Wout = (const float*)d_in[9];
    const float* bout = (const float*)d_in[10];
    float* out = (float*)d_out;

    static bool attr_done = false;
    if (!attr_done) {
        cudaFuncSetAttribute(k_gi,       cudaFuncAttributeMaxDynamicSharedMemorySize, K2_SMEM);
        cudaFuncSetAttribute(k_scan_mma, cudaFuncAttributeMaxDynamicSharedMemorySize, SCAN_SMEM);
        cudaFuncSetAttribute(k_out_mma,  cudaFuncAttributeMaxDynamicSharedMemorySize, MMA_SMEM);
        attr_done = true;
    }

    // Wout -> bf16 hi/lo (independent)
    {
        dim3 grid((NPADW / 8 + 255) / 256, KPAD);
        k_cvt_w<<<grid, 256>>>(Wout);
    }
    // Wh -> fragment bf16 hi/lo (needed by scan)
    {
        dim3 grid(40, 200);
        k_cvt_whf<<<grid, 128>>>(Wh);
    }
    // GI = (gathered state) @ Wi + bi
    {
        dim3 grid(8, 5, 200);
        k_gi<<<grid, 256, K2_SMEM>>>(q, f, eq, ef, Wi, bi);
    }
    // GRU scan (tensor cores)
    k_scan_mma<<<64, 512, SCAN_SMEM>>>(bhn, ic);
    // hT -> bf16 hi/lo
    k_cvt_h<<<(B_ * 32 + 255) / 256, 256>>>();
    // out = hT @ Wout + bout (tensor cores)
    {
        dim3 grid(8, NT2);
        k_out_mma<<<grid, 256, MMA_SMEM>>>(bout, out);
    }
}

// round 9
// speedup vs baseline: 1.8242x; 1.5010x over previous
#include <cuda_runtime.h>
#include <cuda_bf16.h>
#include <cstdint>

// Problem constants
#define B_   1024
#define T_   200
#define E_   100
#define H_   200
#define G3_  600      // 3*H
#define NITEMS 100000

#define KPAD 256             // K padded for output GEMM
#define NT2  782             // ceil(100000/128)
#define NPADW (NT2*128)      // 100096

// Scratch (device globals; allocation is forbidden)
__device__ float g_GI[(size_t)T_ * B_ * G3_]; // gi = x@Wi+bi  [t][b][600]
__device__ float g_hT[B_ * H_];               // final hidden state [b][200]

// bf16 hi/lo operands for the mma.sync output GEMM
__device__ __nv_bfloat16 g_w_hi[(size_t)KPAD * NPADW];  // [k][n]
__device__ __nv_bfloat16 g_w_lo[(size_t)KPAD * NPADW];
__device__ __nv_bfloat16 g_h_hi[B_ * KPAD];             // [m][k]
__device__ __nv_bfloat16 g_h_lo[B_ * KPAD];
// Wh pre-fragged for scan mma: [t][mt 40][ks 13][lane 32] uint4 (a0..a3 bf16 pairs)
__device__ uint4 g_whf_hi[(size_t)T_ * 40 * 13 * 32];
__device__ uint4 g_whf_lo[(size_t)T_ * 40 * 13 * 32];

typedef unsigned long long ull;

static __device__ __forceinline__ ull pack2(float x, float y) {
    ull r; asm("mov.b64 %0, {%1,%2};" : "=l"(r) : "f"(x), "f"(y)); return r;
}
static __device__ __forceinline__ float2 unpack2(ull v) {
    float2 r; asm("mov.b64 {%0,%1}, %2;" : "=f"(r.x), "=f"(r.y) : "l"(v)); return r;
}
static __device__ __forceinline__ void fma2(ull& d, ull a, ull b) {
    asm("fma.rn.f32x2 %0, %1, %2, %0;" : "+l"(d) : "l"(a), "l"(b));
}
static __device__ __forceinline__ float fast_sigmoid(float x) {
    return __fdividef(1.f, 1.f + __expf(-x));
}
static __device__ __forceinline__ float fast_tanh(float x) {
    x = fminf(fmaxf(x, -15.f), 15.f);
    float p = __expf(2.f * x);
    return __fdividef(p - 1.f, p + 1.f);
}
static __device__ __forceinline__ uint32_t smem_u32(const void* p) {
    uint32_t a;
    asm("{ .reg .u64 t; cvta.to.shared.u64 t, %1; cvt.u32.u64 %0, t; }" : "=r"(a) : "l"(p));
    return a;
}

// ---------------- mma.sync helpers (portable HMMA, sm_80+) ----------------
static __device__ __forceinline__ void ldmA(uint32_t* r, uint32_t addr) {
    asm volatile("ldmatrix.sync.aligned.m8n8.x4.shared.b16 {%0,%1,%2,%3}, [%4];"
        : "=r"(r[0]), "=r"(r[1]), "=r"(r[2]), "=r"(r[3]) : "r"(addr));
}
static __device__ __forceinline__ void ldmBT(uint32_t* r, uint32_t addr) {
    asm volatile("ldmatrix.sync.aligned.m8n8.x4.trans.shared.b16 {%0,%1,%2,%3}, [%4];"
        : "=r"(r[0]), "=r"(r[1]), "=r"(r[2]), "=r"(r[3]) : "r"(addr));
}
static __device__ __forceinline__ void mma_bf16(float* c, const uint32_t* a, const uint32_t* b) {
    asm volatile("mma.sync.aligned.m16n8k16.row.col.f32.bf16.bf16.f32 "
        "{%0,%1,%2,%3}, {%4,%5,%6,%7}, {%8,%9}, {%0,%1,%2,%3};"
        : "+f"(c[0]), "+f"(c[1]), "+f"(c[2]), "+f"(c[3])
        : "r"(a[0]), "r"(a[1]), "r"(a[2]), "r"(a[3]), "r"(b[0]), "r"(b[1]));
}
static __device__ __forceinline__ void bf_split(float v, unsigned short& h, unsigned short& l) {
    __nv_bfloat16 hh = __float2bfloat16(v);
    h = __bfloat16_as_ushort(hh);
    l = __bfloat16_as_ushort(__float2bfloat16(v - __bfloat162float(hh)));
}
// pack two floats -> bf16x2 hi and lo-residual bf16x2 (low half = v0)
static __device__ __forceinline__ void pack_split2(float v0, float v1, uint32_t& hi2, uint32_t& lo2) {
    asm("cvt.rn.bf16x2.f32 %0, %1, %2;" : "=r"(hi2) : "f"(v1), "f"(v0));
    float h0 = __uint_as_float(hi2 << 16);
    float h1 = __uint_as_float((hi2 >> 16) << 16);
    asm("cvt.rn.bf16x2.f32 %0, %1, %2;" : "=r"(lo2) : "f"(v1 - h1), "f"(v0 - h0));
}

// ---------------------------------------------------------------------------
// K2 SIMT (fused embed+GI)
// ---------------------------------------------------------------------------
#define K2_AP 136
#define K2_BP 124
#define K2_SMEM ((100*K2_AP + 100*K2_BP) * 4 + 128*2*4)

__global__ void __launch_bounds__(256, 2)
k_gi(const int* __restrict__ q, const int* __restrict__ f,
     const float* __restrict__ eq, const float* __restrict__ ef,
     const float* __restrict__ Wi, const float* __restrict__ bi) {
    extern __shared__ float smem[];
    float* As = smem;
    float* Bs = smem + 100 * K2_AP;
    int*   sq = (int*)(smem + 100 * K2_AP + 100 * K2_BP);
    int*   sf = sq + 128;

    const int bt = blockIdx.x;
    const int nt = blockIdx.y;
    const int t  = blockIdx.z;
    const int tid = threadIdx.x;
    const int b_base = bt * 128;

    if (tid < 128) {
        sq[tid] = __ldg(q + (b_base + tid) * T_ + t);
        sf[tid] = __ldg(f + (b_base + tid) * T_ + t);
    }
    __syncthreads();

    for (int i = tid; i < 128 * 100; i += 256) {
        int m = i / 100, e = i - m * 100;
        As[e * K2_AP + m] = __ldg(eq + sq[m] * E_ + e) * __ldg(ef + sf[m] * E_ + e);
    }
    for (int i = tid; i < 100 * 120; i += 256) {
        int kk = i / 120, nn = i - kk * 120;
        Bs[kk * K2_BP + nn] = __ldg(Wi + (size_t)(t * E_ + kk) * G3_ + nt * 120 + nn);
    }
    __syncthreads();

    if (tid < 240) {
        const int tx = tid % 15;
        const int ty = tid / 15;

        ull acc[8][4];
        #pragma unroll
        for (int r = 0; r < 8; ++r)
            #pragma unroll
            for (int c = 0; c < 4; ++c) acc[r][c] = 0ULL;

        #pragma unroll 4
        for (int kk = 0; kk < 100; ++kk) {
            const float* ap = &As[kk * K2_AP + ty * 8];
            float4 a0 = *(const float4*)ap;
            float4 a1 = *(const float4*)(ap + 4);
            const ulonglong2* bp = (const ulonglong2*)&Bs[kk * K2_BP + tx * 8];
            ulonglong2 bA = bp[0], bB = bp[1];
            ull ad;
            ad = pack2(a0.x, a0.x); fma2(acc[0][0], ad, bA.x); fma2(acc[0][1], ad, bA.y); fma2(acc[0][2], ad, bB.x); fma2(acc[0][3], ad, bB.y);
            ad = pack2(a0.y, a0.y); fma2(acc[1][0], ad, bA.x); fma2(acc[1][1], ad, bA.y); fma2(acc[1][2], ad, bB.x); fma2(acc[1][3], ad, bB.y);
            ad = pack2(a0.z, a0.z); fma2(acc[2][0], ad, bA.x); fma2(acc[2][1], ad, bA.y); fma2(acc[2][2], ad, bB.x); fma2(acc[2][3], ad, bB.y);
            ad = pack2(a0.w, a0.w); fma2(acc[3][0], ad, bA.x); fma2(acc[3][1], ad, bA.y); fma2(acc[3][2], ad, bB.x); fma2(acc[3][3], ad, bB.y);
            ad = pack2(a1.x, a1.x); fma2(acc[4][0], ad, bA.x); fma2(acc[4][1], ad, bA.y); fma2(acc[4][2], ad, bB.x); fma2(acc[4][3], ad, bB.y);
            ad = pack2(a1.y, a1.y); fma2(acc[5][0], ad, bA.x); fma2(acc[5][1], ad, bA.y); fma2(acc[5][2], ad, bB.x); fma2(acc[5][3], ad, bB.y);
            ad = pack2(a1.z, a1.z); fma2(acc[6][0], ad, bA.x); fma2(acc[6][1], ad, bA.y); fma2(acc[6][2], ad, bB.x); fma2(acc[6][3], ad, bB.y);
            ad = pack2(a1.w, a1.w); fma2(acc[7][0], ad, bA.x); fma2(acc[7][1], ad, bA.y); fma2(acc[7][2], ad, bB.x); fma2(acc[7][3], ad, bB.y);
        }

        const int col = nt * 120 + tx * 8;
        float4 bi0 = *(const float4*)(bi + t * G3_ + col);
        float4 bi1 = *(const float4*)(bi + t * G3_ + col + 4);
        #pragma unroll
        for (int r = 0; r < 8; ++r) {
            int row = b_base + ty * 8 + r;
            float* dst = g_GI + ((size_t)t * B_ + row) * G3_ + col;
            float2 v0 = unpack2(acc[r][0]), v1 = unpack2(acc[r][1]);
            float2 v2 = unpack2(acc[r][2]), v3 = unpack2(acc[r][3]);
            *(float4*)dst       = make_float4(v0.x + bi0.x, v0.y + bi0.y, v1.x + bi0.z, v1.y + bi0.w);
            *(float4*)(dst + 4) = make_float4(v2.x + bi1.x, v2.y + bi1.y, v3.x + bi1.z, v3.y + bi1.w);
        }
    }
}

// ---------------------------------------------------------------------------
// Wh -> fragment layout conversion (once).
// ---------------------------------------------------------------------------
__global__ void __launch_bounds__(128)
k_cvt_whf(const float* __restrict__ Wh) {
    __shared__ float sA[208][17];
    const int mt = blockIdx.x;   // 0..39
    const int t  = blockIdx.y;   // 0..199
    const int tid = threadIdx.x;
    const int m0 = mt * 16;

    for (int i = tid; i < 208 * 16; i += 128) {
        int k = i >> 4, mm = i & 15;
        int m = m0 + mm;
        float v = (k < H_ && m < G3_) ? __ldg(Wh + ((size_t)t * H_ + k) * G3_ + m) : 0.f;
        sA[k][mm] = v;
    }
    __syncthreads();

    const int wid = tid >> 5, lane = tid & 31;
    const int g = lane >> 2, c = lane & 3;
    for (int ks = wid; ks < 13; ks += 4) {
        int k0 = ks * 16 + 2 * c;
        uint4 uh, ul;
        pack_split2(sA[k0][g],       sA[k0 + 1][g],     uh.x, ul.x);
        pack_split2(sA[k0][g + 8],   sA[k0 + 1][g + 8], uh.y, ul.y);
        pack_split2(sA[k0 + 8][g],   sA[k0 + 9][g],     uh.z, ul.z);
        pack_split2(sA[k0 + 8][g+8], sA[k0 + 9][g + 8], uh.w, ul.w);
        size_t idx = (((size_t)t * 40 + mt) * 13 + ks) * 32 + lane;
        g_whf_hi[idx] = uh;
        g_whf_lo[idx] = ul;
    }
}

// ---------------------------------------------------------------------------
// K3: GRU scan v5 (tensor cores). 128 CTAs x 8 batch rows, 640 threads.
// 20 warps x 2 mtiles; n=8 (one B frag). Depth-2 A-frag prefetch.
// ---------------------------------------------------------------------------
#define SOFF_GI   0                      // [8][600] f32    19200
#define SOFF_GH   19200                  // [640][10] f32   25600
#define SOFF_HF   44800                  // [8][200] f32    6400
#define SOFF_HHI  51200                  // [8][132] u32    4224
#define SOFF_HLO  55424                  //                 4224
#define SOFF_BHN  59648                  // [200] f32       800
#define SCAN_SMEM 60448

__global__ void __launch_bounds__(640, 1)
k_scan_mma(const float* __restrict__ bhn, const float* __restrict__ ic) {
    extern __shared__ char sm[];
    float*    sgi = (float*)(sm + SOFF_GI);
    float*    sgh = (float*)(sm + SOFF_GH);
    float*    shf = (float*)(sm + SOFF_HF);
    uint32_t* hh  = (uint32_t*)(sm + SOFF_HHI);
    uint32_t* hl  = (uint32_t*)(sm + SOFF_HLO);
    float*    sbh = (float*)(sm + SOFF_BHN);

    const int tid  = threadIdx.x;
    const int wid  = tid >> 5, lane = tid & 31;
    const int b0   = blockIdx.x * 8;
    const int g    = lane >> 2, cc = lane & 3;
    const uint32_t sgi_a = smem_u32(sgi);
    const uint32_t sbh_a = smem_u32(sbh);

    // init h (fp32 + bf16 hi/lo; kpair >= 100 stays zero)
    for (int i = tid; i < 8 * 132; i += 640) {
        int w = i % 132;
        uint32_t hi2 = 0, lo2 = 0;
        if (w < 100) {
            float v0 = __ldg(ic + 2 * w), v1 = __ldg(ic + 2 * w + 1);
            pack_split2(v0, v1, hi2, lo2);
        }
        hh[i] = hi2; hl[i] = lo2;
    }
    for (int i = tid; i < 1600; i += 640)
        shf[i] = __ldg(ic + (i % 200));
    __syncthreads();

    float acc0[4], acc1[4];

    for (int t = 0; t < T_; ++t) {
        // --- prefetch gi[t] + bhn[t] via cp.async (consumed after GEMM) ---
        {
            const float* gib = g_GI + ((size_t)t * B_ + b0) * G3_;
            for (int i = tid; i < 1250; i += 640) {
                if (i < 1200) {
                    int b = i / 150, o = (i - b * 150) * 16;
                    uint32_t dst = sgi_a + b * 2400 + o;
                    const char* src = (const char*)(gib + b * G3_) + o;
                    asm volatile("cp.async.cg.shared.global [%0], [%1], 16;" :: "r"(dst), "l"(src) : "memory");
                } else {
                    int j = i - 1200;
                    uint32_t dst = sbh_a + j * 16;
                    const char* src = (const char*)(bhn + t * H_) + j * 16;
                    asm volatile("cp.async.cg.shared.global [%0], [%1], 16;" :: "r"(dst), "l"(src) : "memory");
                }
            }
            asm volatile("cp.async.commit_group;" ::: "memory");
        }

        // --- GEMM phase: warp wid covers mtiles {wid, wid+20} ---
        #pragma unroll
        for (int c = 0; c < 4; ++c) { acc0[c] = 0.f; acc1[c] = 0.f; }

        size_t tb = (size_t)t * 40;
        const uint4* p0h = g_whf_hi + ((tb + wid)      * 13) * 32 + lane;
        const uint4* p1h = g_whf_hi + ((tb + 20 + wid) * 13) * 32 + lane;
        const uint4* p0l = g_whf_lo + ((tb + wid)      * 13) * 32 + lane;
        const uint4* p1l = g_whf_lo + ((tb + 20 + wid) * 13) * 32 + lane;

        uint4 bh0[2], bl0[2], bh1[2], bl1[2];
        bh0[0] = __ldg(p0h);      bl0[0] = __ldg(p0l);
        bh1[0] = __ldg(p1h);      bl1[0] = __ldg(p1l);
        bh0[1] = __ldg(p0h + 32); bl0[1] = __ldg(p0l + 32);
        bh1[1] = __ldg(p1h + 32); bl1[1] = __ldg(p1l + 32);

        #pragma unroll
        for (int ks = 0; ks < 13; ++ks) {
            const int p = ks & 1;
            uint4 a0h = bh0[p], a0l = bl0[p], a1h = bh1[p], a1l = bl1[p];
            if (ks + 2 < 13) {
                int off = (ks + 2) * 32;
                bh0[p] = __ldg(p0h + off); bl0[p] = __ldg(p0l + off);
                bh1[p] = __ldg(p1h + off); bl1[p] = __ldg(p1l + off);
            }
            // B fragment (batch 8) from smem bf16 pairs
            int r0 = g * 132 + ks * 8 + cc;
            uint32_t Bh[2] = { hh[r0], hh[r0 + 4] };
            uint32_t Bl[2] = { hl[r0], hl[r0 + 4] };
            {
                uint32_t Ah[4] = {a0h.x, a0h.y, a0h.z, a0h.w};
                uint32_t Al[4] = {a0l.x, a0l.y, a0l.z, a0l.w};
                mma_bf16(acc0, Ah, Bh); mma_bf16(acc0, Ah, Bl); mma_bf16(acc0, Al, Bh);
            }
            {
                uint32_t Ah[4] = {a1h.x, a1h.y, a1h.z, a1h.w};
                uint32_t Al[4] = {a1l.x, a1l.y, a1l.z, a1l.w};
                mma_bf16(acc1, Ah, Bh); mma_bf16(acc1, Ah, Bl); mma_bf16(acc1, Al, Bh);
            }
        }

        // epilogue: c-frags -> sgh[col][b] (stride 10)
        {
            int m0 = wid * 16;
            *(float2*)&sgh[(m0 + g) * 10 + cc * 2]     = make_float2(acc0[0], acc0[1]);
            *(float2*)&sgh[(m0 + g + 8) * 10 + cc * 2] = make_float2(acc0[2], acc0[3]);
            int m1 = (wid + 20) * 16;
            *(float2*)&sgh[(m1 + g) * 10 + cc * 2]     = make_float2(acc1[0], acc1[1]);
            *(float2*)&sgh[(m1 + g + 8) * 10 + cc * 2] = make_float2(acc1[2], acc1[3]);
        }

        asm volatile("cp.async.wait_group 0;" ::: "memory");
        __syncthreads();

        // --- gate phase: 800 (b, j-pair) items ---
        for (int i = tid; i < 800; i += 640) {
            int b = i / 100, jp = i - b * 100, j = jp * 2;
            const float* gib = sgi + b * G3_;
            float2 gr = *(const float2*)(gib + j);
            float2 gz = *(const float2*)(gib + 200 + j);
            float2 gn = *(const float2*)(gib + 400 + j);
            float ghr0 = sgh[j * 10 + b],         ghr1 = sgh[(j + 1) * 10 + b];
            float ghz0 = sgh[(200 + j) * 10 + b], ghz1 = sgh[(201 + j) * 10 + b];
            float ghn0 = sgh[(400 + j) * 10 + b], ghn1 = sgh[(401 + j) * 10 + b];
            float2 bv = *(const float2*)(sbh + j);
            float2 ho = *(const float2*)(shf + b * 200 + j);
            float r0 = fast_sigmoid(gr.x + ghr0), r1 = fast_sigmoid(gr.y + ghr1);
            float z0 = fast_sigmoid(gz.x + ghz0), z1 = fast_sigmoid(gz.y + ghz1);
            float n0 = fast_tanh(gn.x + r0 * (ghn0 + bv.x));
            float n1 = fast_tanh(gn.y + r1 * (ghn1 + bv.y));
            float h0 = (1.f - z0) * n0 + z0 * ho.x;
            float h1 = (1.f - z1) * n1 + z1 * ho.y;
            *(float2*)(shf + b * 200 + j) = make_float2(h0, h1);
            uint32_t hi2, lo2;
            pack_split2(h0, h1, hi2, lo2);
            hh[b * 132 + jp] = hi2;
            hl[b * 132 + jp] = lo2;
        }
        __syncthreads();
    }

    for (int i = tid; i < 1600; i += 640) {
        int b = i / 200, j = i - b * 200;
        g_hT[(b0 + b) * H_ + j] = shf[i];
    }
}

// ---------------------------------------------------------------------------
// Conversions to bf16 hi/lo for the output GEMM
// ---------------------------------------------------------------------------
__global__ void k_cvt_w(const float* __restrict__ Wout) {
    int nb = blockIdx.x * 256 + threadIdx.x;
    int k  = blockIdx.y;
    if (nb >= NPADW / 8) return;
    int n = nb * 8;

    union { unsigned short u[8]; uint4 v; } ph, pl;
    if (k < H_ && n + 7 < NITEMS) {
        const float4* src = (const float4*)(Wout + (size_t)k * NITEMS + n);
        float4 v0 = __ldg(src), v1 = __ldg(src + 1);
        float vv[8] = {v0.x, v0.y, v0.z, v0.w, v1.x, v1.y, v1.z, v1.w};
        #pragma unroll
        for (int j = 0; j < 8; ++j) bf_split(vv[j], ph.u[j], pl.u[j]);
    } else {
        #pragma unroll
        for (int j = 0; j < 8; ++j) {
            float v = (k < H_ && n + j < NITEMS) ? __ldg(Wout + (size_t)k * NITEMS + n + j) : 0.f;
            bf_split(v, ph.u[j], pl.u[j]);
        }
    }
    *(uint4*)(g_w_hi + (size_t)k * NPADW + n) = ph.v;
    *(uint4*)(g_w_lo + (size_t)k * NPADW + n) = pl.v;
}

__global__ void k_cvt_h() {
    int idx = blockIdx.x * 256 + threadIdx.x;
    if (idx >= B_ * 32) return;
    int m = idx >> 5, k0 = (idx & 31) * 8;

    union { unsigned short u[8]; uint4 v; } ph, pl;
    #pragma unroll
    for (int j = 0; j < 8; ++j) {
        int k = k0 + j;
        float v = (k < H_) ? g_hT[m * H_ + k] : 0.f;
        bf_split(v, ph.u[j], pl.u[j]);
    }
    *(uint4*)(g_h_hi + m * KPAD + k0) = ph.v;
    *(uint4*)(g_h_lo + m * KPAD + k0) = pl.v;
}

// ---------------------------------------------------------------------------
// K4 mma.sync: out = hT @ Wout + bout, bf16 hi/lo 3-pass
// ---------------------------------------------------------------------------
#define ASTR 72
#define BSTR 136
#define MMA_SMEM ((2*128*ASTR + 2*64*BSTR) * 2)

__global__ void __launch_bounds__(256, 1)
k_out_mma(const float* __restrict__ bout, float* __restrict__ out) {
    extern __shared__ __nv_bfloat16 smem_bf[];
    __nv_bfloat16* sAh = smem_bf;
    __nv_bfloat16* sAl = sAh + 128 * ASTR;
    __nv_bfloat16* sBh = sAl + 128 * ASTR;
    __nv_bfloat16* sBl = sBh + 64 * BSTR;

    const int tid  = threadIdx.x;
    const int wid  = tid >> 5, lane = tid & 31;
    const int mt   = blockIdx.x;
    const int nt   = blockIdx.y;
    const int wm   = wid & 1;
    const int wn   = wid >> 1;

    float acc[4][4][4];
    #pragma unroll
    for (int i = 0; i < 4; ++i)
        #pragma unroll
        for (int j = 0; j < 4; ++j)
            #pragma unroll
            for (int c = 0; c < 4; ++c) acc[i][j][c] = 0.f;

    const uint32_t sAh32 = smem_u32(sAh), sAl32 = smem_u32(sAl);
    const uint32_t sBh32 = smem_u32(sBh), sBl32 = smem_u32(sBl);

    for (int kc = 0; kc < 4; ++kc) {
        for (int i = tid; i < 1024; i += 256) {
            int m = i >> 3, kb = i & 7;
            size_t src = (size_t)(mt * 128 + m) * KPAD + kc * 64 + kb * 8;
            *(uint4*)(sAh + m * ASTR + kb * 8) = *(const uint4*)(g_h_hi + src);
            *(uint4*)(sAl + m * ASTR + kb * 8) = *(const uint4*)(g_h_lo + src);
        }
        for (int i = tid; i < 1024; i += 256) {
            int k = i >> 4, nb = i & 15;
            size_t src = (size_t)(kc * 64 + k) * NPADW + nt * 128 + nb * 8;
            *(uint4*)(sBh + k * BSTR + nb * 8) = *(const uint4*)(g_w_hi + src);
            *(uint4*)(sBl + k * BSTR + nb * 8) = *(const uint4*)(g_w_lo + src);
        }
        __syncthreads();

        #pragma unroll
        for (int ks = 0; ks < 4; ++ks) {
            uint32_t Ah[4][4], Al[4][4];
            #pragma unroll
            for (int fm = 0; fm < 4; ++fm) {
                uint32_t off = ((wm * 64 + fm * 16 + (lane & 15)) * ASTR
                                + ks * 16 + (lane >> 4) * 8) * 2;
                ldmA(Ah[fm], sAh32 + off);
                ldmA(Al[fm], sAl32 + off);
            }
            uint32_t Bh[4][2], Bl[4][2];
            #pragma unroll
            for (int fb = 0; fb < 2; ++fb) {
                uint32_t off = ((ks * 16 + (lane & 15)) * BSTR
                                + wn * 32 + fb * 16 + (lane >> 4) * 8) * 2;
                uint32_t r[4];
                ldmBT(r, sBh32 + off);
                Bh[fb*2][0] = r[0]; Bh[fb*2][1] = r[1];
                Bh[fb*2+1][0] = r[2]; Bh[fb*2+1][1] = r[3];
                ldmBT(r, sBl32 + off);
                Bl[fb*2][0] = r[0]; Bl[fb*2][1] = r[1];
                Bl[fb*2+1][0] = r[2]; Bl[fb*2+1][1] = r[3];
            }
            #pragma unroll
            for (int fm = 0; fm < 4; ++fm)
                #pragma unroll
                for (int fn = 0; fn < 4; ++fn) {
                    mma_bf16(acc[fm][fn], Ah[fm], Bh[fn]);
                    mma_bf16(acc[fm][fn], Ah[fm], Bl[fn]);
                    mma_bf16(acc[fm][fn], Al[fm], Bh[fn]);
                }
        }
        __syncthreads();
    }

    #pragma unroll
    for (int fm = 0; fm < 4; ++fm) {
        int gm = mt * 128 + wm * 64 + fm * 16 + (lane >> 2);
        #pragma unroll
        for (int fn = 0; fn < 4; ++fn) {
            int gn = nt * 128 + wn * 32 + fn * 8 + (lane & 3) * 2;
            if (gn < NITEMS) {
                float2 bv = __ldg((const float2*)(bout + gn));
                float2 o0 = make_float2(acc[fm][fn][0] + bv.x, acc[fm][fn][1] + bv.y);
                float2 o1 = make_float2(acc[fm][fn][2] + bv.x, acc[fm][fn][3] + bv.y);
                *(float2*)(out + (size_t)gm * NITEMS + gn) = o0;
                *(float2*)(out + (size_t)(gm + 8) * NITEMS + gn) = o1;
            }
        }
    }
}

// ---------------------------------------------------------------------------
extern "C" void kernel_launch(void* const* d_in, const int* in_sizes, int n_in,
                              void* d_out, int out_size) {
    const int*   q    = (const int*)  d_in[0];
    const int*   f    = (const int*)  d_in[1];
    const float* eq   = (const float*)d_in[2];
    const float* ef   = (const float*)d_in[3];
    const float* ic   = (const float*)d_in[4];
    const float* Wi   = (const float*)d_in[5];
    const float* bi   = (const float*)d_in[6];
    const float* Wh   = (const float*)d_in[7];
    const float* bhn  = (const float*)d_in[8];
    const float* Wout = (const float*)d_in[9];
    const float* bout = (const float*)d_in[10];
    float* out = (float*)d_out;

    static bool attr_done = false;
    if (!attr_done) {
        cudaFuncSetAttribute(k_gi,       cudaFuncAttributeMaxDynamicSharedMemorySize, K2_SMEM);
        cudaFuncSetAttribute(k_scan_mma, cudaFuncAttributeMaxDynamicSharedMemorySize, SCAN_SMEM);
        cudaFuncSetAttribute(k_out_mma,  cudaFuncAttributeMaxDynamicSharedMemorySize, MMA_SMEM);
        attr_done = true;
    }

    // Wout -> bf16 hi/lo (independent)
    {
        dim3 grid((NPADW / 8 + 255) / 256, KPAD);
        k_cvt_w<<<grid, 256>>>(Wout);
    }
    // Wh -> fragment bf16 hi/lo (needed by scan)
    {
        dim3 grid(40, 200);
        k_cvt_whf<<<grid, 128>>>(Wh);
    }
    // GI = (gathered state) @ Wi + bi
    {
        dim3 grid(8, 5, 200);
        k_gi<<<grid, 256, K2_SMEM>>>(q, f, eq, ef, Wi, bi);
    }
    // GRU scan (tensor cores, 128 CTAs x 8 rows)
    k_scan_mma<<<128, 640, SCAN_SMEM>>>(bhn, ic);
    // hT -> bf16 hi/lo
    k_cvt_h<<<(B_ * 32 + 255) / 256, 256>>>();
    // out = hT @ Wout + bout (tensor cores)
    {
        dim3 grid(8, NT2);
        k_out_mma<<<grid, 256, MMA_SMEM>>>(bout, out);
    }
}

// round 10
// speedup vs baseline: 2.4688x; 1.3533x over previous
#include <cuda_runtime.h>
#include <cuda_bf16.h>
#include <cstdint>

// Problem constants
#define B_   1024
#define T_   200
#define E_   100
#define H_   200
#define G3_  600      // 3*H
#define NITEMS 100000

#define KPAD 256             // K padded for output GEMM
#define NT2  782             // ceil(100000/128)
#define NPADW (NT2*128)      // 100096

#define GI_KP 112            // K pad for GI GEMM
#define GI_NP 640            // N pad for GI GEMM

// Scratch (device globals; allocation is forbidden)
__device__ float g_GI[(size_t)T_ * B_ * G3_]; // gi = x@Wi+bi  [t][b][600]
__device__ float g_hT[B_ * H_];               // final hidden state [b][200]

// bf16 hi/lo operands for the mma.sync output GEMM
__device__ __nv_bfloat16 g_w_hi[(size_t)KPAD * NPADW];  // [k][n]
__device__ __nv_bfloat16 g_w_lo[(size_t)KPAD * NPADW];
__device__ __nv_bfloat16 g_h_hi[B_ * KPAD];             // [m][k]
__device__ __nv_bfloat16 g_h_lo[B_ * KPAD];
// Wh pre-fragged for scan mma: [t][mt 40][ks 13][lane 32] uint4
__device__ uint4 g_whf_hi[(size_t)T_ * 40 * 13 * 32];
__device__ uint4 g_whf_lo[(size_t)T_ * 40 * 13 * 32];
// Wi linear bf16 hi/lo for GI GEMM: [t][112][640]
__device__ __nv_bfloat16 g_wi_hi[(size_t)T_ * GI_KP * GI_NP];
__device__ __nv_bfloat16 g_wi_lo[(size_t)T_ * GI_KP * GI_NP];

static __device__ __forceinline__ float fast_sigmoid(float x) {
    return __fdividef(1.f, 1.f + __expf(-x));
}
static __device__ __forceinline__ float fast_tanh(float x) {
    x = fminf(fmaxf(x, -15.f), 15.f);
    float p = __expf(2.f * x);
    return __fdividef(p - 1.f, p + 1.f);
}
static __device__ __forceinline__ uint32_t smem_u32(const void* p) {
    uint32_t a;
    asm("{ .reg .u64 t; cvta.to.shared.u64 t, %1; cvt.u32.u64 %0, t; }" : "=r"(a) : "l"(p));
    return a;
}

// ---------------- mma.sync helpers ----------------
static __device__ __forceinline__ void ldmA(uint32_t* r, uint32_t addr) {
    asm volatile("ldmatrix.sync.aligned.m8n8.x4.shared.b16 {%0,%1,%2,%3}, [%4];"
        : "=r"(r[0]), "=r"(r[1]), "=r"(r[2]), "=r"(r[3]) : "r"(addr));
}
static __device__ __forceinline__ void ldmBT(uint32_t* r, uint32_t addr) {
    asm volatile("ldmatrix.sync.aligned.m8n8.x4.trans.shared.b16 {%0,%1,%2,%3}, [%4];"
        : "=r"(r[0]), "=r"(r[1]), "=r"(r[2]), "=r"(r[3]) : "r"(addr));
}
static __device__ __forceinline__ void mma_bf16(float* c, const uint32_t* a, const uint32_t* b) {
    asm volatile("mma.sync.aligned.m16n8k16.row.col.f32.bf16.bf16.f32 "
        "{%0,%1,%2,%3}, {%4,%5,%6,%7}, {%8,%9}, {%0,%1,%2,%3};"
        : "+f"(c[0]), "+f"(c[1]), "+f"(c[2]), "+f"(c[3])
        : "r"(a[0]), "r"(a[1]), "r"(a[2]), "r"(a[3]), "r"(b[0]), "r"(b[1]));
}
static __device__ __forceinline__ void bf_split(float v, unsigned short& h, unsigned short& l) {
    __nv_bfloat16 hh = __float2bfloat16(v);
    h = __bfloat16_as_ushort(hh);
    l = __bfloat16_as_ushort(__float2bfloat16(v - __bfloat162float(hh)));
}
static __device__ __forceinline__ void pack_split2(float v0, float v1, uint32_t& hi2, uint32_t& lo2) {
    asm("cvt.rn.bf16x2.f32 %0, %1, %2;" : "=r"(hi2) : "f"(v1), "f"(v0));
    float h0 = __uint_as_float(hi2 << 16);
    float h1 = __uint_as_float((hi2 >> 16) << 16);
    asm("cvt.rn.bf16x2.f32 %0, %1, %2;" : "=r"(lo2) : "f"(v1 - h1), "f"(v0 - h0));
}
static __device__ __forceinline__ void cp16(uint32_t dst, const void* src) {
    asm volatile("cp.async.cg.shared.global [%0], [%1], 16;" :: "r"(dst), "l"(src) : "memory");
}

// ---------------------------------------------------------------------------
// Wi conversion: [200][100][600] fp32 -> linear [200][112][640] bf16 hi/lo
// ---------------------------------------------------------------------------
__global__ void k_cvt_wi(const float* __restrict__ Wi) {
    int idx = blockIdx.x * 256 + threadIdx.x;   // 200*112*80
    if (idx >= T_ * GI_KP * 80) return;
    int n8 = idx % 80;
    int k  = (idx / 80) % GI_KP;
    int t  = idx / (80 * GI_KP);
    int n  = n8 * 8;

    union { unsigned short u[8]; uint4 v; } ph, pl;
    #pragma unroll
    for (int j = 0; j < 8; ++j) {
        float v = (k < E_ && n + j < G3_) ? __ldg(Wi + ((size_t)t * E_ + k) * G3_ + n + j) : 0.f;
        bf_split(v, ph.u[j], pl.u[j]);
    }
    size_t dst = ((size_t)t * GI_KP + k) * GI_NP + n;
    *(uint4*)(g_wi_hi + dst) = ph.v;
    *(uint4*)(g_wi_lo + dst) = pl.v;
}

// ---------------------------------------------------------------------------
// K2 mma v2: GI[t][b][n] = sum_e (eq[q]*ef[f]) * Wi[t][e][n] + bi[t][n]
// grid (bt 8, t 200); per CTA: M=128 x N=640 x K=112; A gathered once,
// B in N=64 chunks, cp.async double-buffered. 256 threads (2m x 4n warps).
// ---------------------------------------------------------------------------
#define GIA_STR 120
#define GIB_STR 72
#define GI2_A_BYTES (128 * GIA_STR * 2)                 // 30720 per split
#define GI2_B_SPLIT (GI_KP * GIB_STR * 2)               // 16128
#define GI2_B_BUF   (2 * GI2_B_SPLIT)                   // 32256 per buffer
#define GI2_SMEM    (2 * GI2_A_BYTES + 2 * GI2_B_BUF)   // 125952

__global__ void __launch_bounds__(256, 1)
k_gi_mma(const int* __restrict__ q, const int* __restrict__ f,
         const float* __restrict__ eq, const float* __restrict__ ef,
         const float* __restrict__ bi) {
    extern __shared__ char sm[];
    __nv_bfloat16* sAh = (__nv_bfloat16*)sm;                      // [128][120]
    __nv_bfloat16* sAl = (__nv_bfloat16*)(sm + GI2_A_BYTES);
    char* sB = sm + 2 * GI2_A_BYTES;                              // [2][2][112][72]
    __shared__ int sq[128], sf[128];

    const int tid  = threadIdx.x;
    const int wid  = tid >> 5, lane = tid & 31;
    const int bt   = blockIdx.x;       // 0..7
    const int t    = blockIdx.y;       // 0..199
    const int wm   = wid & 1;          // m half (64) -> 4 m-frags? no: 2m x 4n
    const int wn   = wid >> 1;         // n quarter of 64-chunk? chunk is 64 wide
    const int b_base = bt * 128;

    // warp layout inside a 64-wide chunk: wm in {0,1} covers m 64; wn in {0..3} covers 16 cols
    // => per warp: 4 m-frags x 2 n-frags
    if (tid < 128) {
        sq[tid] = __ldg(q + (b_base + tid) * T_ + t);
        sf[tid] = __ldg(f + (b_base + tid) * T_ + t);
    }
    __syncthreads();

    // A fill: gather+product -> bf16 hi/lo, [m][k] stride 120
    for (int i = tid; i < 128 * 25; i += 256) {
        int m = i / 25, c4 = i - m * 25;
        int k0 = c4 * 4;
        float4 a = __ldg((const float4*)(eq + sq[m] * E_ + k0));
        float4 b = __ldg((const float4*)(ef + sf[m] * E_ + k0));
        float vv[4] = {a.x * b.x, a.y * b.y, a.z * b.z, a.w * b.w};
        union { unsigned short u[4]; uint2 v; } ph, pl;
        #pragma unroll
        for (int j = 0; j < 4; ++j) bf_split(vv[j], ph.u[j], pl.u[j]);
        *(uint2*)(sAh + m * GIA_STR + k0) = ph.v;
        *(uint2*)(sAl + m * GIA_STR + k0) = pl.v;
    }
    // zero pad k 100..111
    for (int i = tid; i < 128 * 6; i += 256) {
        int m = i / 6, kk = 100 + 2 * (i - m * 6);
        *(uint32_t*)(sAh + m * GIA_STR + kk) = 0;
        *(uint32_t*)(sAl + m * GIA_STR + kk) = 0;
    }

    const uint32_t sB32 = smem_u32(sB);
    // B chunk fill via cp.async: chunk c -> buffer p
    auto fillB = [&](int c, int p) {
        size_t srcbase = (size_t)t * GI_KP * GI_NP + c * 64;
        uint32_t dstbase = sB32 + p * GI2_B_BUF;
        for (int i = tid; i < 1792; i += 256) {
            int split = i >> 10;             // 0: hi (i<896? no) -- fix below
            int r = i & 1023;
            // 1792 = 2*896; use split = i/896
            split = i / 896;
            r = i - split * 896;
            int k = r >> 3, j = r & 7;
            const __nv_bfloat16* src = (split ? g_wi_lo : g_wi_hi) + srcbase + (size_t)k * GI_NP + j * 8;
            uint32_t dst = dstbase + split * GI2_B_SPLIT + (k * GIB_STR + j * 8) * 2;
            cp16(dst, src);
        }
        asm volatile("cp.async.commit_group;" ::: "memory");
    };

    fillB(0, 0);

    const uint32_t sAh32 = smem_u32(sAh), sAl32 = smem_u32(sAl);

    for (int c = 0; c < 10; ++c) {
        if (c + 1 < 10) {
            fillB(c + 1, (c + 1) & 1);
            asm volatile("cp.async.wait_group 1;" ::: "memory");
        } else {
            asm volatile("cp.async.wait_group 0;" ::: "memory");
        }
        __syncthreads();

        const uint32_t bh32 = sB32 + (c & 1) * GI2_B_BUF;
        const uint32_t bl32 = bh32 + GI2_B_SPLIT;

        float acc[4][2][4];
        #pragma unroll
        for (int i = 0; i < 4; ++i)
            #pragma unroll
            for (int j = 0; j < 2; ++j)
                #pragma unroll
                for (int k = 0; k < 4; ++k) acc[i][j][k] = 0.f;

        #pragma unroll
        for (int ks = 0; ks < 7; ++ks) {
            uint32_t Ah[4][4], Al[4][4];
            #pragma unroll
            for (int fm = 0; fm < 4; ++fm) {
                uint32_t off = ((wm * 64 + fm * 16 + (lane & 15)) * GIA_STR
                                + ks * 16 + (lane >> 4) * 8) * 2;
                ldmA(Ah[fm], sAh32 + off);
                ldmA(Al[fm], sAl32 + off);
            }
            uint32_t Bh[2][2], Bl[2][2];
            {
                uint32_t off = ((ks * 16 + (lane & 15)) * GIB_STR
                                + wn * 16 + (lane >> 4) * 8) * 2;
                uint32_t r[4];
                ldmBT(r, bh32 + off);
                Bh[0][0] = r[0]; Bh[0][1] = r[1];
                Bh[1][0] = r[2]; Bh[1][1] = r[3];
                ldmBT(r, bl32 + off);
                Bl[0][0] = r[0]; Bl[0][1] = r[1];
                Bl[1][0] = r[2]; Bl[1][1] = r[3];
            }
            #pragma unroll
            for (int fm = 0; fm < 4; ++fm)
                #pragma unroll
                for (int fn = 0; fn < 2; ++fn) {
                    mma_bf16(acc[fm][fn], Ah[fm], Bh[fn]);
                    mma_bf16(acc[fm][fn], Ah[fm], Bl[fn]);
                    mma_bf16(acc[fm][fn], Al[fm], Bh[fn]);
                }
        }

        // epilogue for this chunk
        #pragma unroll
        for (int fm = 0; fm < 4; ++fm) {
            int gm = b_base + wm * 64 + fm * 16 + (lane >> 2);
            #pragma unroll
            for (int fn = 0; fn < 2; ++fn) {
                int gn = c * 64 + wn * 16 + fn * 8 + (lane & 3) * 2;
                if (gn < G3_) {
                    float2 bv = __ldg((const float2*)(bi + t * G3_ + gn));
                    float2 o0 = make_float2(acc[fm][fn][0] + bv.x, acc[fm][fn][1] + bv.y);
                    float2 o1 = make_float2(acc[fm][fn][2] + bv.x, acc[fm][fn][3] + bv.y);
                    *(float2*)(g_GI + ((size_t)t * B_ + gm) * G3_ + gn) = o0;
                    *(float2*)(g_GI + ((size_t)t * B_ + gm + 8) * G3_ + gn) = o1;
                }
            }
        }
        __syncthreads();
    }
}

// ---------------------------------------------------------------------------
// Wh -> fragment layout conversion (once).
// ---------------------------------------------------------------------------
__global__ void __launch_bounds__(128)
k_cvt_whf(const float* __restrict__ Wh) {
    __shared__ float sA[208][17];
    const int mt = blockIdx.x;   // 0..39
    const int t  = blockIdx.y;   // 0..199
    const int tid = threadIdx.x;
    const int m0 = mt * 16;

    for (int i = tid; i < 208 * 16; i += 128) {
        int k = i >> 4, mm = i & 15;
        int m = m0 + mm;
        float v = (k < H_ && m < G3_) ? __ldg(Wh + ((size_t)t * H_ + k) * G3_ + m) : 0.f;
        sA[k][mm] = v;
    }
    __syncthreads();

    const int wid = tid >> 5, lane = tid & 31;
    const int g = lane >> 2, c = lane & 3;
    for (int ks = wid; ks < 13; ks += 4) {
        int k0 = ks * 16 + 2 * c;
        uint4 uh, ul;
        pack_split2(sA[k0][g],       sA[k0 + 1][g],     uh.x, ul.x);
        pack_split2(sA[k0][g + 8],   sA[k0 + 1][g + 8], uh.y, ul.y);
        pack_split2(sA[k0 + 8][g],   sA[k0 + 9][g],     uh.z, ul.z);
        pack_split2(sA[k0 + 8][g+8], sA[k0 + 9][g + 8], uh.w, ul.w);
        size_t idx = (((size_t)t * 40 + mt) * 13 + ks) * 32 + lane;
        g_whf_hi[idx] = uh;
        g_whf_lo[idx] = ul;
    }
}

// ---------------------------------------------------------------------------
// K3: GRU scan v5 (tensor cores). 128 CTAs x 8 batch rows, 640 threads.
// ---------------------------------------------------------------------------
#define SOFF_GI   0                      // [8][600] f32    19200
#define SOFF_GH   19200                  // [640][10] f32   25600
#define SOFF_HF   44800                  // [8][200] f32    6400
#define SOFF_HHI  51200                  // [8][132] u32    4224
#define SOFF_HLO  55424                  //                 4224
#define SOFF_BHN  59648                  // [200] f32       800
#define SCAN_SMEM 60448

__global__ void __launch_bounds__(640, 1)
k_scan_mma(const float* __restrict__ bhn, const float* __restrict__ ic) {
    extern __shared__ char sm[];
    float*    sgi = (float*)(sm + SOFF_GI);
    float*    sgh = (float*)(sm + SOFF_GH);
    float*    shf = (float*)(sm + SOFF_HF);
    uint32_t* hh  = (uint32_t*)(sm + SOFF_HHI);
    uint32_t* hl  = (uint32_t*)(sm + SOFF_HLO);
    float*    sbh = (float*)(sm + SOFF_BHN);

    const int tid  = threadIdx.x;
    const int wid  = tid >> 5, lane = tid & 31;
    const int b0   = blockIdx.x * 8;
    const int g    = lane >> 2, cc = lane & 3;
    const uint32_t sgi_a = smem_u32(sgi);
    const uint32_t sbh_a = smem_u32(sbh);

    for (int i = tid; i < 8 * 132; i += 640) {
        int w = i % 132;
        uint32_t hi2 = 0, lo2 = 0;
        if (w < 100) {
            float v0 = __ldg(ic + 2 * w), v1 = __ldg(ic + 2 * w + 1);
            pack_split2(v0, v1, hi2, lo2);
        }
        hh[i] = hi2; hl[i] = lo2;
    }
    for (int i = tid; i < 1600; i += 640)
        shf[i] = __ldg(ic + (i % 200));
    __syncthreads();

    float acc0[4], acc1[4];

    for (int t = 0; t < T_; ++t) {
        {
            const float* gib = g_GI + ((size_t)t * B_ + b0) * G3_;
            for (int i = tid; i < 1250; i += 640) {
                if (i < 1200) {
                    int b = i / 150, o = (i - b * 150) * 16;
                    cp16(sgi_a + b * 2400 + o, (const char*)(gib + b * G3_) + o);
                } else {
                    int j = i - 1200;
                    cp16(sbh_a + j * 16, (const char*)(bhn + t * H_) + j * 16);
                }
            }
            asm volatile("cp.async.commit_group;" ::: "memory");
        }

        #pragma unroll
        for (int c = 0; c < 4; ++c) { acc0[c] = 0.f; acc1[c] = 0.f; }

        size_t tb = (size_t)t * 40;
        const uint4* p0h = g_whf_hi + ((tb + wid)      * 13) * 32 + lane;
        const uint4* p1h = g_whf_hi + ((tb + 20 + wid) * 13) * 32 + lane;
        const uint4* p0l = g_whf_lo + ((tb + wid)      * 13) * 32 + lane;
        const uint4* p1l = g_whf_lo + ((tb + 20 + wid) * 13) * 32 + lane;

        uint4 bh0[2], bl0[2], bh1[2], bl1[2];
        bh0[0] = __ldg(p0h);      bl0[0] = __ldg(p0l);
        bh1[0] = __ldg(p1h);      bl1[0] = __ldg(p1l);
        bh0[1] = __ldg(p0h + 32); bl0[1] = __ldg(p0l + 32);
        bh1[1] = __ldg(p1h + 32); bl1[1] = __ldg(p1l + 32);

        #pragma unroll
        for (int ks = 0; ks < 13; ++ks) {
            const int p = ks & 1;
            uint4 a0h = bh0[p], a0l = bl0[p], a1h = bh1[p], a1l = bl1[p];
            if (ks + 2 < 13) {
                int off = (ks + 2) * 32;
                bh0[p] = __ldg(p0h + off); bl0[p] = __ldg(p0l + off);
                bh1[p] = __ldg(p1h + off); bl1[p] = __ldg(p1l + off);
            }
            int r0 = g * 132 + ks * 8 + cc;
            uint32_t Bh[2] = { hh[r0], hh[r0 + 4] };
            uint32_t Bl[2] = { hl[r0], hl[r0 + 4] };
            {
                uint32_t Ah[4] = {a0h.x, a0h.y, a0h.z, a0h.w};
                uint32_t Al[4] = {a0l.x, a0l.y, a0l.z, a0l.w};
                mma_bf16(acc0, Ah, Bh); mma_bf16(acc0, Ah, Bl); mma_bf16(acc0, Al, Bh);
            }
            {
                uint32_t Ah[4] = {a1h.x, a1h.y, a1h.z, a1h.w};
                uint32_t Al[4] = {a1l.x, a1l.y, a1l.z, a1l.w};
                mma_bf16(acc1, Ah, Bh); mma_bf16(acc1, Ah, Bl); mma_bf16(acc1, Al, Bh);
            }
        }

        {
            int m0 = wid * 16;
            *(float2*)&sgh[(m0 + g) * 10 + cc * 2]     = make_float2(acc0[0], acc0[1]);
            *(float2*)&sgh[(m0 + g + 8) * 10 + cc * 2] = make_float2(acc0[2], acc0[3]);
            int m1 = (wid + 20) * 16;
            *(float2*)&sgh[(m1 + g) * 10 + cc * 2]     = make_float2(acc1[0], acc1[1]);
            *(float2*)&sgh[(m1 + g + 8) * 10 + cc * 2] = make_float2(acc1[2], acc1[3]);
        }

        asm volatile("cp.async.wait_group 0;" ::: "memory");
        __syncthreads();

        for (int i = tid; i < 800; i += 640) {
            int b = i / 100, jp = i - b * 100, j = jp * 2;
            const float* gib = sgi + b * G3_;
            float2 gr = *(const float2*)(gib + j);
            float2 gz = *(const float2*)(gib + 200 + j);
            float2 gn = *(const float2*)(gib + 400 + j);
            float ghr0 = sgh[j * 10 + b],         ghr1 = sgh[(j + 1) * 10 + b];
            float ghz0 = sgh[(200 + j) * 10 + b], ghz1 = sgh[(201 + j) * 10 + b];
            float ghn0 = sgh[(400 + j) * 10 + b], ghn1 = sgh[(401 + j) * 10 + b];
            float2 bv = *(const float2*)(sbh + j);
            float2 ho = *(const float2*)(shf + b * 200 + j);
            float r0 = fast_sigmoid(gr.x + ghr0), r1 = fast_sigmoid(gr.y + ghr1);
            float z0 = fast_sigmoid(gz.x + ghz0), z1 = fast_sigmoid(gz.y + ghz1);
            float n0 = fast_tanh(gn.x + r0 * (ghn0 + bv.x));
            float n1 = fast_tanh(gn.y + r1 * (ghn1 + bv.y));
            float h0 = (1.f - z0) * n0 + z0 * ho.x;
            float h1 = (1.f - z1) * n1 + z1 * ho.y;
            *(float2*)(shf + b * 200 + j) = make_float2(h0, h1);
            uint32_t hi2, lo2;
            pack_split2(h0, h1, hi2, lo2);
            hh[b * 132 + jp] = hi2;
            hl[b * 132 + jp] = lo2;
        }
        __syncthreads();
    }

    for (int i = tid; i < 1600; i += 640) {
        int b = i / 200, j = i - b * 200;
        g_hT[(b0 + b) * H_ + j] = shf[i];
    }
}

// ---------------------------------------------------------------------------
// Conversions to bf16 hi/lo for the output GEMM
// ---------------------------------------------------------------------------
__global__ void k_cvt_w(const float* __restrict__ Wout) {
    int nb = blockIdx.x * 256 + threadIdx.x;
    int k  = blockIdx.y;
    if (nb >= NPADW / 8) return;
    int n = nb * 8;

    union { unsigned short u[8]; uint4 v; } ph, pl;
    if (k < H_ && n + 7 < NITEMS) {
        const float4* src = (const float4*)(Wout + (size_t)k * NITEMS + n);
        float4 v0 = __ldg(src), v1 = __ldg(src + 1);
        float vv[8] = {v0.x, v0.y, v0.z, v0.w, v1.x, v1.y, v1.z, v1.w};
        #pragma unroll
        for (int j = 0; j < 8; ++j) bf_split(vv[j], ph.u[j], pl.u[j]);
    } else {
        #pragma unroll
        for (int j = 0; j < 8; ++j) {
            float v = (k < H_ && n + j < NITEMS) ? __ldg(Wout + (size_t)k * NITEMS + n + j) : 0.f;
            bf_split(v, ph.u[j], pl.u[j]);
        }
    }
    *(uint4*)(g_w_hi + (size_t)k * NPADW + n) = ph.v;
    *(uint4*)(g_w_lo + (size_t)k * NPADW + n) = pl.v;
}

__global__ void k_cvt_h() {
    int idx = blockIdx.x * 256 + threadIdx.x;
    if (idx >= B_ * 32) return;
    int m = idx >> 5, k0 = (idx & 31) * 8;

    union { unsigned short u[8]; uint4 v; } ph, pl;
    #pragma unroll
    for (int j = 0; j < 8; ++j) {
        int k = k0 + j;
        float v = (k < H_) ? g_hT[m * H_ + k] : 0.f;
        bf_split(v, ph.u[j], pl.u[j]);
    }
    *(uint4*)(g_h_hi + m * KPAD + k0) = ph.v;
    *(uint4*)(g_h_lo + m * KPAD + k0) = pl.v;
}

// ---------------------------------------------------------------------------
// K4 mma.sync: out = hT @ Wout + bout, bf16 hi/lo 3-pass
// ---------------------------------------------------------------------------
#define ASTR 72
#define BSTR 136
#define MMA_SMEM ((2*128*ASTR + 2*64*BSTR) * 2)

__global__ void __launch_bounds__(256, 1)
k_out_mma(const float* __restrict__ bout, float* __restrict__ out) {
    extern __shared__ __nv_bfloat16 smem_bf[];
    __nv_bfloat16* sAh = smem_bf;
    __nv_bfloat16* sAl = sAh + 128 * ASTR;
    __nv_bfloat16* sBh = sAl + 128 * ASTR;
    __nv_bfloat16* sBl = sBh + 64 * BSTR;

    const int tid  = threadIdx.x;
    const int wid  = tid >> 5, lane = tid & 31;
    const int mt   = blockIdx.x;
    const int nt   = blockIdx.y;
    const int wm   = wid & 1;
    const int wn   = wid >> 1;

    float acc[4][4][4];
    #pragma unroll
    for (int i = 0; i < 4; ++i)
        #pragma unroll
        for (int j = 0; j < 4; ++j)
            #pragma unroll
            for (int c = 0; c < 4; ++c) acc[i][j][c] = 0.f;

    const uint32_t sAh32 = smem_u32(sAh), sAl32 = smem_u32(sAl);
    const uint32_t sBh32 = smem_u32(sBh), sBl32 = smem_u32(sBl);

    for (int kc = 0; kc < 4; ++kc) {
        for (int i = tid; i < 1024; i += 256) {
            int m = i >> 3, kb = i & 7;
            size_t src = (size_t)(mt * 128 + m) * KPAD + kc * 64 + kb * 8;
            *(uint4*)(sAh + m * ASTR + kb * 8) = *(const uint4*)(g_h_hi + src);
            *(uint4*)(sAl + m * ASTR + kb * 8) = *(const uint4*)(g_h_lo + src);
        }
        for (int i = tid; i < 1024; i += 256) {
            int k = i >> 4, nb = i & 15;
            size_t src = (size_t)(kc * 64 + k) * NPADW + nt * 128 + nb * 8;
            *(uint4*)(sBh + k * BSTR + nb * 8) = *(const uint4*)(g_w_hi + src);
            *(uint4*)(sBl + k * BSTR + nb * 8) = *(const uint4*)(g_w_lo + src);
        }
        __syncthreads();

        #pragma unroll
        for (int ks = 0; ks < 4; ++ks) {
            uint32_t Ah[4][4], Al[4][4];
            #pragma unroll
            for (int fm = 0; fm < 4; ++fm) {
                uint32_t off = ((wm * 64 + fm * 16 + (lane & 15)) * ASTR
                                + ks * 16 + (lane >> 4) * 8) * 2;
                ldmA(Ah[fm], sAh32 + off);
                ldmA(Al[fm], sAl32 + off);
            }
            uint32_t Bh[4][2], Bl[4][2];
            #pragma unroll
            for (int fb = 0; fb < 2; ++fb) {
                uint32_t off = ((ks * 16 + (lane & 15)) * BSTR
                                + wn * 32 + fb * 16 + (lane >> 4) * 8) * 2;
                uint32_t r[4];
                ldmBT(r, sBh32 + off);
                Bh[fb*2][0] = r[0]; Bh[fb*2][1] = r[1];
                Bh[fb*2+1][0] = r[2]; Bh[fb*2+1][1] = r[3];
                ldmBT(r, sBl32 + off);
                Bl[fb*2][0] = r[0]; Bl[fb*2][1] = r[1];
                Bl[fb*2+1][0] = r[2]; Bl[fb*2+1][1] = r[3];
            }
            #pragma unroll
            for (int fm = 0; fm < 4; ++fm)
                #pragma unroll
                for (int fn = 0; fn < 4; ++fn) {
                    mma_bf16(acc[fm][fn], Ah[fm], Bh[fn]);
                    mma_bf16(acc[fm][fn], Ah[fm], Bl[fn]);
                    mma_bf16(acc[fm][fn], Al[fm], Bh[fn]);
                }
        }
        __syncthreads();
    }

    #pragma unroll
    for (int fm = 0; fm < 4; ++fm) {
        int gm = mt * 128 + wm * 64 + fm * 16 + (lane >> 2);
        #pragma unroll
        for (int fn = 0; fn < 4; ++fn) {
            int gn = nt * 128 + wn * 32 + fn * 8 + (lane & 3) * 2;
            if (gn < NITEMS) {
                float2 bv = __ldg((const float2*)(bout + gn));
                float2 o0 = make_float2(acc[fm][fn][0] + bv.x, acc[fm][fn][1] + bv.y);
                float2 o1 = make_float2(acc[fm][fn][2] + bv.x, acc[fm][fn][3] + bv.y);
                *(float2*)(out + (size_t)gm * NITEMS + gn) = o0;
                *(float2*)(out + (size_t)(gm + 8) * NITEMS + gn) = o1;
            }
        }
    }
}

// ---------------------------------------------------------------------------
extern "C" void kernel_launch(void* const* d_in, const int* in_sizes, int n_in,
                              void* d_out, int out_size) {
    const int*   q    = (const int*)  d_in[0];
    const int*   f    = (const int*)  d_in[1];
    const float* eq   = (const float*)d_in[2];
    const float* ef   = (const float*)d_in[3];
    const float* ic   = (const float*)d_in[4];
    const float* Wi   = (const float*)d_in[5];
    const float* bi   = (const float*)d_in[6];
    const float* Wh   = (const float*)d_in[7];
    const float* bhn  = (const float*)d_in[8];
    const float* Wout = (const float*)d_in[9];
    const float* bout = (const float*)d_in[10];
    float* out = (float*)d_out;

    static bool attr_done = false;
    if (!attr_done) {
        cudaFuncSetAttribute(k_gi_mma,   cudaFuncAttributeMaxDynamicSharedMemorySize, GI2_SMEM);
        cudaFuncSetAttribute(k_scan_mma, cudaFuncAttributeMaxDynamicSharedMemorySize, SCAN_SMEM);
        cudaFuncSetAttribute(k_out_mma,  cudaFuncAttributeMaxDynamicSharedMemorySize, MMA_SMEM);
        attr_done = true;
    }

    // Wout -> bf16 hi/lo (independent)
    {
        dim3 grid((NPADW / 8 + 255) / 256, KPAD);
        k_cvt_w<<<grid, 256>>>(Wout);
    }
    // Wi -> linear bf16 hi/lo
    k_cvt_wi<<<(T_ * GI_KP * 80 + 255) / 256, 256>>>(Wi);
    // Wh -> fragment bf16 hi/lo
    {
        dim3 grid(40, 200);
        k_cvt_whf<<<grid, 128>>>(Wh);
    }
    // GI = (gathered state) @ Wi + bi (tensor cores, A-reuse + cp.async B)
    {
        dim3 grid(8, 200);
        k_gi_mma<<<grid, 256, GI2_SMEM>>>(q, f, eq, ef, bi);
    }
    // GRU scan (tensor cores)
    k_scan_mma<<<128, 640, SCAN_SMEM>>>(bhn, ic);
    // hT -> bf16 hi/lo
    k_cvt_h<<<(B_ * 32 + 255) / 256, 256>>>();
    // out = hT @ Wout + bout (tensor cores)
    {
        dim3 grid(8, NT2);
        k_out_mma<<<grid, 256, MMA_SMEM>>>(bout, out);
    }
}

// round 11
// speedup vs baseline: 2.6308x; 1.0656x over previous
#include <cuda_runtime.h>
#include <cuda_bf16.h>
#include <cstdint>

// Problem constants
#define B_   1024
#define T_   200
#define E_   100
#define H_   200
#define G3_  600      // 3*H
#define NITEMS 100000

#define KPAD 256             // K padded for output GEMM
#define NT2  782             // ceil(100000/128)
#define NPADW (NT2*128)      // 100096

#define GI_KP 112            // K pad for GI GEMM
#define GI_NP 640            // N pad for GI GEMM

// Scratch (device globals; allocation is forbidden)
__device__ float g_GI[(size_t)T_ * B_ * G3_]; // gi = x@Wi+bi  [t][b][600]
__device__ float g_hT[B_ * H_];               // final hidden state [b][200]

// bf16 hi/lo operands for the mma.sync output GEMM
__device__ __nv_bfloat16 g_w_hi[(size_t)KPAD * NPADW];  // [k][n]
__device__ __nv_bfloat16 g_w_lo[(size_t)KPAD * NPADW];
__device__ __nv_bfloat16 g_h_hi[B_ * KPAD];             // [m][k]
__device__ __nv_bfloat16 g_h_lo[B_ * KPAD];
// Wh pre-fragged for scan mma: [t][mt 40][ks 13][lane 32] uint4
__device__ uint4 g_whf_hi[(size_t)T_ * 40 * 13 * 32];
__device__ uint4 g_whf_lo[(size_t)T_ * 40 * 13 * 32];
// Wi linear bf16 hi/lo for GI GEMM: [t][112][640]
__device__ __nv_bfloat16 g_wi_hi[(size_t)T_ * GI_KP * GI_NP];
__device__ __nv_bfloat16 g_wi_lo[(size_t)T_ * GI_KP * GI_NP];

static __device__ __forceinline__ float fast_sigmoid(float x) {
    return __fdividef(1.f, 1.f + __expf(-x));
}
static __device__ __forceinline__ float fast_tanh(float x) {
    x = fminf(fmaxf(x, -15.f), 15.f);
    float p = __expf(2.f * x);
    return __fdividef(p - 1.f, p + 1.f);
}
static __device__ __forceinline__ uint32_t smem_u32(const void* p) {
    uint32_t a;
    asm("{ .reg .u64 t; cvta.to.shared.u64 t, %1; cvt.u32.u64 %0, t; }" : "=r"(a) : "l"(p));
    return a;
}

// ---------------- mma.sync helpers ----------------
static __device__ __forceinline__ void ldmA(uint32_t* r, uint32_t addr) {
    asm volatile("ldmatrix.sync.aligned.m8n8.x4.shared.b16 {%0,%1,%2,%3}, [%4];"
        : "=r"(r[0]), "=r"(r[1]), "=r"(r[2]), "=r"(r[3]) : "r"(addr));
}
static __device__ __forceinline__ void ldmBT(uint32_t* r, uint32_t addr) {
    asm volatile("ldmatrix.sync.aligned.m8n8.x4.trans.shared.b16 {%0,%1,%2,%3}, [%4];"
        : "=r"(r[0]), "=r"(r[1]), "=r"(r[2]), "=r"(r[3]) : "r"(addr));
}
static __device__ __forceinline__ void mma_bf16(float* c, const uint32_t* a, const uint32_t* b) {
    asm volatile("mma.sync.aligned.m16n8k16.row.col.f32.bf16.bf16.f32 "
        "{%0,%1,%2,%3}, {%4,%5,%6,%7}, {%8,%9}, {%0,%1,%2,%3};"
        : "+f"(c[0]), "+f"(c[1]), "+f"(c[2]), "+f"(c[3])
        : "r"(a[0]), "r"(a[1]), "r"(a[2]), "r"(a[3]), "r"(b[0]), "r"(b[1]));
}
static __device__ __forceinline__ void bf_split(float v, unsigned short& h, unsigned short& l) {
    __nv_bfloat16 hh = __float2bfloat16(v);
    h = __bfloat16_as_ushort(hh);
    l = __bfloat16_as_ushort(__float2bfloat16(v - __bfloat162float(hh)));
}
static __device__ __forceinline__ void pack_split2(float v0, float v1, uint32_t& hi2, uint32_t& lo2) {
    asm("cvt.rn.bf16x2.f32 %0, %1, %2;" : "=r"(hi2) : "f"(v1), "f"(v0));
    float h0 = __uint_as_float(hi2 << 16);
    float h1 = __uint_as_float((hi2 >> 16) << 16);
    asm("cvt.rn.bf16x2.f32 %0, %1, %2;" : "=r"(lo2) : "f"(v1 - h1), "f"(v0 - h0));
}
static __device__ __forceinline__ void cp16(uint32_t dst, const void* src) {
    asm volatile("cp.async.cg.shared.global [%0], [%1], 16;" :: "r"(dst), "l"(src) : "memory");
}

// ---------------------------------------------------------------------------
// Wi conversion: [200][100][600] fp32 -> linear [200][112][640] bf16 hi/lo
// ---------------------------------------------------------------------------
__global__ void k_cvt_wi(const float* __restrict__ Wi) {
    int idx = blockIdx.x * 256 + threadIdx.x;   // 200*112*80
    if (idx >= T_ * GI_KP * 80) return;
    int n8 = idx % 80;
    int k  = (idx / 80) % GI_KP;
    int t  = idx / (80 * GI_KP);
    int n  = n8 * 8;

    union { unsigned short u[8]; uint4 v; } ph, pl;
    #pragma unroll
    for (int j = 0; j < 8; ++j) {
        float v = (k < E_ && n + j < G3_) ? __ldg(Wi + ((size_t)t * E_ + k) * G3_ + n + j) : 0.f;
        bf_split(v, ph.u[j], pl.u[j]);
    }
    size_t dst = ((size_t)t * GI_KP + k) * GI_NP + n;
    *(uint4*)(g_wi_hi + dst) = ph.v;
    *(uint4*)(g_wi_lo + dst) = pl.v;
}

// ---------------------------------------------------------------------------
// K2 mma v3: grid (bt 8, t 200); per CTA M=128 x N=640 x K=112.
// 512 threads (16 warps: 2m x 8n), B chunks of 128 cols (5 chunks),
// cp.async double-buffered.
// ---------------------------------------------------------------------------
#define GIA_STR 120
#define GIB_STR 136
#define GI3_A_BYTES (128 * GIA_STR * 2)                 // 30720 per split
#define GI3_B_SPLIT (GI_KP * GIB_STR * 2)               // 30464
#define GI3_B_BUF   (2 * GI3_B_SPLIT)                   // 60928
#define GI3_SMEM    (2 * GI3_A_BYTES + 2 * GI3_B_BUF)   // 183296

__global__ void __launch_bounds__(512, 1)
k_gi_mma(const int* __restrict__ q, const int* __restrict__ f,
         const float* __restrict__ eq, const float* __restrict__ ef,
         const float* __restrict__ bi) {
    extern __shared__ char sm[];
    __nv_bfloat16* sAh = (__nv_bfloat16*)sm;                      // [128][120]
    __nv_bfloat16* sAl = (__nv_bfloat16*)(sm + GI3_A_BYTES);
    char* sB = sm + 2 * GI3_A_BYTES;                              // [2][2][112][136]
    __shared__ int sq[128], sf[128];

    const int tid  = threadIdx.x;
    const int wid  = tid >> 5, lane = tid & 31;
    const int bt   = blockIdx.x;       // 0..7
    const int t    = blockIdx.y;       // 0..199
    const int wm   = wid & 1;          // m half
    const int wn   = wid >> 1;         // 0..7 : 16-col group within 128 chunk
    const int b_base = bt * 128;

    if (tid < 128) {
        sq[tid] = __ldg(q + (b_base + tid) * T_ + t);
        sf[tid] = __ldg(f + (b_base + tid) * T_ + t);
    }
    __syncthreads();

    // A fill: gather+product -> bf16 hi/lo, [m][k] stride 120
    for (int i = tid; i < 128 * 25; i += 512) {
        int m = i / 25, c4 = i - m * 25;
        int k0 = c4 * 4;
        float4 a = __ldg((const float4*)(eq + sq[m] * E_ + k0));
        float4 b = __ldg((const float4*)(ef + sf[m] * E_ + k0));
        float vv[4] = {a.x * b.x, a.y * b.y, a.z * b.z, a.w * b.w};
        union { unsigned short u[4]; uint2 v; } ph, pl;
        #pragma unroll
        for (int j = 0; j < 4; ++j) bf_split(vv[j], ph.u[j], pl.u[j]);
        *(uint2*)(sAh + m * GIA_STR + k0) = ph.v;
        *(uint2*)(sAl + m * GIA_STR + k0) = pl.v;
    }
    for (int i = tid; i < 128 * 6; i += 512) {
        int m = i / 6, kk = 100 + 2 * (i - m * 6);
        *(uint32_t*)(sAh + m * GIA_STR + kk) = 0;
        *(uint32_t*)(sAl + m * GIA_STR + kk) = 0;
    }

    const uint32_t sB32 = smem_u32(sB);
    // B chunk fill via cp.async: chunk c (128 cols) -> buffer p
    auto fillB = [&](int c, int p) {
        size_t srcbase = (size_t)t * GI_KP * GI_NP + c * 128;
        uint32_t dstbase = sB32 + p * GI3_B_BUF;
        // 2 splits x 112 k x 16 j = 3584 cp16
        for (int i = tid; i < 3584; i += 512) {
            int split = i / 1792;
            int r = i - split * 1792;
            int k = r >> 4, j = r & 15;
            const __nv_bfloat16* src = (split ? g_wi_lo : g_wi_hi) + srcbase + (size_t)k * GI_NP + j * 8;
            uint32_t dst = dstbase + split * GI3_B_SPLIT + (k * GIB_STR + j * 8) * 2;
            cp16(dst, src);
        }
        asm volatile("cp.async.commit_group;" ::: "memory");
    };

    fillB(0, 0);

    const uint32_t sAh32 = smem_u32(sAh), sAl32 = smem_u32(sAl);

    for (int c = 0; c < 5; ++c) {
        if (c + 1 < 5) {
            fillB(c + 1, (c + 1) & 1);
            asm volatile("cp.async.wait_group 1;" ::: "memory");
        } else {
            asm volatile("cp.async.wait_group 0;" ::: "memory");
        }
        __syncthreads();

        const uint32_t bh32 = sB32 + (c & 1) * GI3_B_BUF;
        const uint32_t bl32 = bh32 + GI3_B_SPLIT;

        float acc[4][2][4];
        #pragma unroll
        for (int i = 0; i < 4; ++i)
            #pragma unroll
            for (int j = 0; j < 2; ++j)
                #pragma unroll
                for (int k = 0; k < 4; ++k) acc[i][j][k] = 0.f;

        #pragma unroll
        for (int ks = 0; ks < 7; ++ks) {
            uint32_t Ah[4][4], Al[4][4];
            #pragma unroll
            for (int fm = 0; fm < 4; ++fm) {
                uint32_t off = ((wm * 64 + fm * 16 + (lane & 15)) * GIA_STR
                                + ks * 16 + (lane >> 4) * 8) * 2;
                ldmA(Ah[fm], sAh32 + off);
                ldmA(Al[fm], sAl32 + off);
            }
            uint32_t Bh[2][2], Bl[2][2];
            {
                uint32_t off = ((ks * 16 + (lane & 15)) * GIB_STR
                                + wn * 16 + (lane >> 4) * 8) * 2;
                uint32_t r[4];
                ldmBT(r, bh32 + off);
                Bh[0][0] = r[0]; Bh[0][1] = r[1];
                Bh[1][0] = r[2]; Bh[1][1] = r[3];
                ldmBT(r, bl32 + off);
                Bl[0][0] = r[0]; Bl[0][1] = r[1];
                Bl[1][0] = r[2]; Bl[1][1] = r[3];
            }
            #pragma unroll
            for (int fm = 0; fm < 4; ++fm)
                #pragma unroll
                for (int fn = 0; fn < 2; ++fn) {
                    mma_bf16(acc[fm][fn], Ah[fm], Bh[fn]);
                    mma_bf16(acc[fm][fn], Ah[fm], Bl[fn]);
                    mma_bf16(acc[fm][fn], Al[fm], Bh[fn]);
                }
        }

        #pragma unroll
        for (int fm = 0; fm < 4; ++fm) {
            int gm = b_base + wm * 64 + fm * 16 + (lane >> 2);
            #pragma unroll
            for (int fn = 0; fn < 2; ++fn) {
                int gn = c * 128 + wn * 16 + fn * 8 + (lane & 3) * 2;
                if (gn < G3_) {
                    float2 bv = __ldg((const float2*)(bi + t * G3_ + gn));
                    float2 o0 = make_float2(acc[fm][fn][0] + bv.x, acc[fm][fn][1] + bv.y);
                    float2 o1 = make_float2(acc[fm][fn][2] + bv.x, acc[fm][fn][3] + bv.y);
                    *(float2*)(g_GI + ((size_t)t * B_ + gm) * G3_ + gn) = o0;
                    *(float2*)(g_GI + ((size_t)t * B_ + gm + 8) * G3_ + gn) = o1;
                }
            }
        }
        __syncthreads();
    }
}

// ---------------------------------------------------------------------------
// Wh -> fragment layout conversion (once).
// ---------------------------------------------------------------------------
__global__ void __launch_bounds__(128)
k_cvt_whf(const float* __restrict__ Wh) {
    __shared__ float sA[208][17];
    const int mt = blockIdx.x;   // 0..39
    const int t  = blockIdx.y;   // 0..199
    const int tid = threadIdx.x;
    const int m0 = mt * 16;

    for (int i = tid; i < 208 * 16; i += 128) {
        int k = i >> 4, mm = i & 15;
        int m = m0 + mm;
        float v = (k < H_ && m < G3_) ? __ldg(Wh + ((size_t)t * H_ + k) * G3_ + m) : 0.f;
        sA[k][mm] = v;
    }
    __syncthreads();

    const int wid = tid >> 5, lane = tid & 31;
    const int g = lane >> 2, c = lane & 3;
    for (int ks = wid; ks < 13; ks += 4) {
        int k0 = ks * 16 + 2 * c;
        uint4 uh, ul;
        pack_split2(sA[k0][g],       sA[k0 + 1][g],     uh.x, ul.x);
        pack_split2(sA[k0][g + 8],   sA[k0 + 1][g + 8], uh.y, ul.y);
        pack_split2(sA[k0 + 8][g],   sA[k0 + 9][g],     uh.z, ul.z);
        pack_split2(sA[k0 + 8][g+8], sA[k0 + 9][g + 8], uh.w, ul.w);
        size_t idx = (((size_t)t * 40 + mt) * 13 + ks) * 32 + lane;
        g_whf_hi[idx] = uh;
        g_whf_lo[idx] = ul;
    }
}

// ---------------------------------------------------------------------------
// K3: GRU scan v6. 128 CTAs x 8 rows, 640 threads. Cross-step weight prefetch;
// final epilogue writes g_hT AND g_h_hi/lo (cvt_h fused).
// ---------------------------------------------------------------------------
#define SOFF_GI   0                      // [8][600] f32    19200
#define SOFF_GH   19200                  // [640][10] f32   25600
#define SOFF_HF   44800                  // [8][200] f32    6400
#define SOFF_HHI  51200                  // [8][132] u32    4224
#define SOFF_HLO  55424                  //                 4224
#define SOFF_BHN  59648                  // [200] f32       800
#define SCAN_SMEM 60448

__global__ void __launch_bounds__(640, 1)
k_scan_mma(const float* __restrict__ bhn, const float* __restrict__ ic) {
    extern __shared__ char sm[];
    float*    sgi = (float*)(sm + SOFF_GI);
    float*    sgh = (float*)(sm + SOFF_GH);
    float*    shf = (float*)(sm + SOFF_HF);
    uint32_t* hh  = (uint32_t*)(sm + SOFF_HHI);
    uint32_t* hl  = (uint32_t*)(sm + SOFF_HLO);
    float*    sbh = (float*)(sm + SOFF_BHN);

    const int tid  = threadIdx.x;
    const int wid  = tid >> 5, lane = tid & 31;
    const int b0   = blockIdx.x * 8;
    const int g    = lane >> 2, cc = lane & 3;
    const uint32_t sgi_a = smem_u32(sgi);
    const uint32_t sbh_a = smem_u32(sbh);

    for (int i = tid; i < 8 * 132; i += 640) {
        int w = i % 132;
        uint32_t hi2 = 0, lo2 = 0;
        if (w < 100) {
            float v0 = __ldg(ic + 2 * w), v1 = __ldg(ic + 2 * w + 1);
            pack_split2(v0, v1, hi2, lo2);
        }
        hh[i] = hi2; hl[i] = lo2;
    }
    for (int i = tid; i < 1600; i += 640)
        shf[i] = __ldg(ic + (i % 200));
    __syncthreads();

    float acc0[4], acc1[4];
    uint4 bh0[2], bl0[2], bh1[2], bl1[2];

    // preload (t=0, ks=0,1)
    {
        const uint4* p0h = g_whf_hi + ((size_t)wid * 13) * 32 + lane;
        const uint4* p1h = g_whf_hi + ((size_t)(20 + wid) * 13) * 32 + lane;
        const uint4* p0l = g_whf_lo + ((size_t)wid * 13) * 32 + lane;
        const uint4* p1l = g_whf_lo + ((size_t)(20 + wid) * 13) * 32 + lane;
        bh0[0] = __ldg(p0h);      bl0[0] = __ldg(p0l);
        bh1[0] = __ldg(p1h);      bl1[0] = __ldg(p1l);
        bh0[1] = __ldg(p0h + 32); bl0[1] = __ldg(p0l + 32);
        bh1[1] = __ldg(p1h + 32); bl1[1] = __ldg(p1l + 32);
    }

    for (int t = 0; t < T_; ++t) {
        // prefetch gi[t] + bhn[t]
        {
            const float* gib = g_GI + ((size_t)t * B_ + b0) * G3_;
            for (int i = tid; i < 1250; i += 640) {
                if (i < 1200) {
                    int b = i / 150, o = (i - b * 150) * 16;
                    cp16(sgi_a + b * 2400 + o, (const char*)(gib + b * G3_) + o);
                } else {
                    int j = i - 1200;
                    cp16(sbh_a + j * 16, (const char*)(bhn + t * H_) + j * 16);
                }
            }
            asm volatile("cp.async.commit_group;" ::: "memory");
        }

        #pragma unroll
        for (int c = 0; c < 4; ++c) { acc0[c] = 0.f; acc1[c] = 0.f; }

        size_t tb = (size_t)t * 40;
        const uint4* p0h = g_whf_hi + ((tb + wid)      * 13) * 32 + lane;
        const uint4* p1h = g_whf_hi + ((tb + 20 + wid) * 13) * 32 + lane;
        const uint4* p0l = g_whf_lo + ((tb + wid)      * 13) * 32 + lane;
        const uint4* p1l = g_whf_lo + ((tb + 20 + wid) * 13) * 32 + lane;

        #pragma unroll
        for (int ks = 0; ks < 13; ++ks) {
            const int p = ks & 1;
            uint4 a0h = bh0[p], a0l = bl0[p], a1h = bh1[p], a1l = bl1[p];
            if (ks + 2 < 13) {
                int off = (ks + 2) * 32;
                bh0[p] = __ldg(p0h + off); bl0[p] = __ldg(p0l + off);
                bh1[p] = __ldg(p1h + off); bl1[p] = __ldg(p1l + off);
            }
            int r0 = g * 132 + ks * 8 + cc;
            uint32_t Bh[2] = { hh[r0], hh[r0 + 4] };
            uint32_t Bl[2] = { hl[r0], hl[r0 + 4] };
            {
                uint32_t Ah[4] = {a0h.x, a0h.y, a0h.z, a0h.w};
                uint32_t Al[4] = {a0l.x, a0l.y, a0l.z, a0l.w};
                mma_bf16(acc0, Ah, Bh); mma_bf16(acc0, Ah, Bl); mma_bf16(acc0, Al, Bh);
            }
            {
                uint32_t Ah[4] = {a1h.x, a1h.y, a1h.z, a1h.w};
                uint32_t Al[4] = {a1l.x, a1l.y, a1l.z, a1l.w};
                mma_bf16(acc1, Ah, Bh); mma_bf16(acc1, Ah, Bl); mma_bf16(acc1, Al, Bh);
            }
        }

        // epilogue: c-frags -> sgh[col][b] (stride 10)
        {
            int m0 = wid * 16;
            *(float2*)&sgh[(m0 + g) * 10 + cc * 2]     = make_float2(acc0[0], acc0[1]);
            *(float2*)&sgh[(m0 + g + 8) * 10 + cc * 2] = make_float2(acc0[2], acc0[3]);
            int m1 = (wid + 20) * 16;
            *(float2*)&sgh[(m1 + g) * 10 + cc * 2]     = make_float2(acc1[0], acc1[1]);
            *(float2*)&sgh[(m1 + g + 8) * 10 + cc * 2] = make_float2(acc1[2], acc1[3]);
        }

        // prefetch next step's first weight frags (overlaps gate phase)
        if (t + 1 < T_) {
            size_t nb = (size_t)(t + 1) * 40;
            const uint4* n0h = g_whf_hi + ((nb + wid)      * 13) * 32 + lane;
            const uint4* n1h = g_whf_hi + ((nb + 20 + wid) * 13) * 32 + lane;
            const uint4* n0l = g_whf_lo + ((nb + wid)      * 13) * 32 + lane;
            const uint4* n1l = g_whf_lo + ((nb + 20 + wid) * 13) * 32 + lane;
            bh0[0] = __ldg(n0h);      bl0[0] = __ldg(n0l);
            bh1[0] = __ldg(n1h);      bl1[0] = __ldg(n1l);
            bh0[1] = __ldg(n0h + 32); bl0[1] = __ldg(n0l + 32);
            bh1[1] = __ldg(n1h + 32); bl1[1] = __ldg(n1l + 32);
        }

        asm volatile("cp.async.wait_group 0;" ::: "memory");
        __syncthreads();

        // gate phase: 800 (b, j-pair) items
        for (int i = tid; i < 800; i += 640) {
            int b = i / 100, jp = i - b * 100, j = jp * 2;
            const float* gib = sgi + b * G3_;
            float2 gr = *(const float2*)(gib + j);
            float2 gz = *(const float2*)(gib + 200 + j);
            float2 gn = *(const float2*)(gib + 400 + j);
            float ghr0 = sgh[j * 10 + b],         ghr1 = sgh[(j + 1) * 10 + b];
            float ghz0 = sgh[(200 + j) * 10 + b], ghz1 = sgh[(201 + j) * 10 + b];
            float ghn0 = sgh[(400 + j) * 10 + b], ghn1 = sgh[(401 + j) * 10 + b];
            float2 bv = *(const float2*)(sbh + j);
            float2 ho = *(const float2*)(shf + b * 200 + j);
            float r0 = fast_sigmoid(gr.x + ghr0), r1 = fast_sigmoid(gr.y + ghr1);
            float z0 = fast_sigmoid(gz.x + ghz0), z1 = fast_sigmoid(gz.y + ghz1);
            float n0 = fast_tanh(gn.x + r0 * (ghn0 + bv.x));
            float n1 = fast_tanh(gn.y + r1 * (ghn1 + bv.y));
            float h0 = (1.f - z0) * n0 + z0 * ho.x;
            float h1 = (1.f - z1) * n1 + z1 * ho.y;
            *(float2*)(shf + b * 200 + j) = make_float2(h0, h1);
            uint32_t hi2, lo2;
            pack_split2(h0, h1, hi2, lo2);
            hh[b * 132 + jp] = hi2;
            hl[b * 132 + jp] = lo2;
        }
        __syncthreads();
    }

    // final: write fp32 hT and fused bf16 hi/lo conversion
    for (int i = tid; i < 1600; i += 640) {
        int b = i / 200, j = i - b * 200;
        g_hT[(b0 + b) * H_ + j] = shf[i];
    }
    for (int i = tid; i < 8 * 128; i += 640) {
        int b = i / 128, kp = i - b * 128;
        int k0 = kp * 2;
        float v0 = (k0 < H_) ? shf[b * 200 + k0] : 0.f;
        float v1 = (k0 + 1 < H_) ? shf[b * 200 + k0 + 1] : 0.f;
        uint32_t hi2, lo2;
        pack_split2(v0, v1, hi2, lo2);
        *(uint32_t*)(g_h_hi + (size_t)(b0 + b) * KPAD + k0) = hi2;
        *(uint32_t*)(g_h_lo + (size_t)(b0 + b) * KPAD + k0) = lo2;
    }
}

// ---------------------------------------------------------------------------
// Wout conversion
// ---------------------------------------------------------------------------
__global__ void k_cvt_w(const float* __restrict__ Wout) {
    int nb = blockIdx.x * 256 + threadIdx.x;
    int k  = blockIdx.y;
    if (nb >= NPADW / 8) return;
    int n = nb * 8;

    union { unsigned short u[8]; uint4 v; } ph, pl;
    if (k < H_ && n + 7 < NITEMS) {
        const float4* src = (const float4*)(Wout + (size_t)k * NITEMS + n);
        float4 v0 = __ldg(src), v1 = __ldg(src + 1);
        float vv[8] = {v0.x, v0.y, v0.z, v0.w, v1.x, v1.y, v1.z, v1.w};
        #pragma unroll
        for (int j = 0; j < 8; ++j) bf_split(vv[j], ph.u[j], pl.u[j]);
    } else {
        #pragma unroll
        for (int j = 0; j < 8; ++j) {
            float v = (k < H_ && n + j < NITEMS) ? __ldg(Wout + (size_t)k * NITEMS + n + j) : 0.f;
            bf_split(v, ph.u[j], pl.u[j]);
        }
    }
    *(uint4*)(g_w_hi + (size_t)k * NPADW + n) = ph.v;
    *(uint4*)(g_w_lo + (size_t)k * NPADW + n) = pl.v;
}

// ---------------------------------------------------------------------------
// K4 mma.sync: out = hT @ Wout + bout, bf16 hi/lo 3-pass, 2 CTAs/SM
// ---------------------------------------------------------------------------
#define ASTR 72
#define BSTR 136
#define MMA_SMEM ((2*128*ASTR + 2*64*BSTR) * 2)

__global__ void __launch_bounds__(256, 2)
k_out_mma(const float* __restrict__ bout, float* __restrict__ out) {
    extern __shared__ __nv_bfloat16 smem_bf[];
    __nv_bfloat16* sAh = smem_bf;
    __nv_bfloat16* sAl = sAh + 128 * ASTR;
    __nv_bfloat16* sBh = sAl + 128 * ASTR;
    __nv_bfloat16* sBl = sBh + 64 * BSTR;

    const int tid  = threadIdx.x;
    const int wid  = tid >> 5, lane = tid & 31;
    const int mt   = blockIdx.x;
    const int nt   = blockIdx.y;
    const int wm   = wid & 1;
    const int wn   = wid >> 1;

    float acc[4][4][4];
    #pragma unroll
    for (int i = 0; i < 4; ++i)
        #pragma unroll
        for (int j = 0; j < 4; ++j)
            #pragma unroll
            for (int c = 0; c < 4; ++c) acc[i][j][c] = 0.f;

    const uint32_t sAh32 = smem_u32(sAh), sAl32 = smem_u32(sAl);
    const uint32_t sBh32 = smem_u32(sBh), sBl32 = smem_u32(sBl);

    for (int kc = 0; kc < 4; ++kc) {
        for (int i = tid; i < 1024; i += 256) {
            int m = i >> 3, kb = i & 7;
            size_t src = (size_t)(mt * 128 + m) * KPAD + kc * 64 + kb * 8;
            *(uint4*)(sAh + m * ASTR + kb * 8) = *(const uint4*)(g_h_hi + src);
            *(uint4*)(sAl + m * ASTR + kb * 8) = *(const uint4*)(g_h_lo + src);
        }
        for (int i = tid; i < 1024; i += 256) {
            int k = i >> 4, nb = i & 15;
            size_t src = (size_t)(kc * 64 + k) * NPADW + nt * 128 + nb * 8;
            *(uint4*)(sBh + k * BSTR + nb * 8) = *(const uint4*)(g_w_hi + src);
            *(uint4*)(sBl + k * BSTR + nb * 8) = *(const uint4*)(g_w_lo + src);
        }
        __syncthreads();

        #pragma unroll
        for (int ks = 0; ks < 4; ++ks) {
            uint32_t Ah[4][4], Al[4][4];
            #pragma unroll
            for (int fm = 0; fm < 4; ++fm) {
                uint32_t off = ((wm * 64 + fm * 16 + (lane & 15)) * ASTR
                                + ks * 16 + (lane >> 4) * 8) * 2;
                ldmA(Ah[fm], sAh32 + off);
                ldmA(Al[fm], sAl32 + off);
            }
            uint32_t Bh[4][2], Bl[4][2];
            #pragma unroll
            for (int fb = 0; fb < 2; ++fb) {
                uint32_t off = ((ks * 16 + (lane & 15)) * BSTR
                                + wn * 32 + fb * 16 + (lane >> 4) * 8) * 2;
                uint32_t r[4];
                ldmBT(r, sBh32 + off);
                Bh[fb*2][0] = r[0]; Bh[fb*2][1] = r[1];
                Bh[fb*2+1][0] = r[2]; Bh[fb*2+1][1] = r[3];
                ldmBT(r, sBl32 + off);
                Bl[fb*2][0] = r[0]; Bl[fb*2][1] = r[1];
                Bl[fb*2+1][0] = r[2]; Bl[fb*2+1][1] = r[3];
            }
            #pragma unroll
            for (int fm = 0; fm < 4; ++fm)
                #pragma unroll
                for (int fn = 0; fn < 4; ++fn) {
                    mma_bf16(acc[fm][fn], Ah[fm], Bh[fn]);
                    mma_bf16(acc[fm][fn], Ah[fm], Bl[fn]);
                    mma_bf16(acc[fm][fn], Al[fm], Bh[fn]);
                }
        }
        __syncthreads();
    }

    #pragma unroll
    for (int fm = 0; fm < 4; ++fm) {
        int gm = mt * 128 + wm * 64 + fm * 16 + (lane >> 2);
        #pragma unroll
        for (int fn = 0; fn < 4; ++fn) {
            int gn = nt * 128 + wn * 32 + fn * 8 + (lane & 3) * 2;
            if (gn < NITEMS) {
                float2 bv = __ldg((const float2*)(bout + gn));
                float2 o0 = make_float2(acc[fm][fn][0] + bv.x, acc[fm][fn][1] + bv.y);
                float2 o1 = make_float2(acc[fm][fn][2] + bv.x, acc[fm][fn][3] + bv.y);
                *(float2*)(out + (size_t)gm * NITEMS + gn) = o0;
                *(float2*)(out + (size_t)(gm + 8) * NITEMS + gn) = o1;
            }
        }
    }
}

// ---------------------------------------------------------------------------
extern "C" void kernel_launch(void* const* d_in, const int* in_sizes, int n_in,
                              void* d_out, int out_size) {
    const int*   q    = (const int*)  d_in[0];
    const int*   f    = (const int*)  d_in[1];
    const float* eq   = (const float*)d_in[2];
    const float* ef   = (const float*)d_in[3];
    const float* ic   = (const float*)d_in[4];
    const float* Wi   = (const float*)d_in[5];
    const float* bi   = (const float*)d_in[6];
    const float* Wh   = (const float*)d_in[7];
    const float* bhn  = (const float*)d_in[8];
    const float* Wout = (const float*)d_in[9];
    const float* bout = (const float*)d_in[10];
    float* out = (float*)d_out;

    static bool attr_done = false;
    if (!attr_done) {
        cudaFuncSetAttribute(k_gi_mma,   cudaFuncAttributeMaxDynamicSharedMemorySize, GI3_SMEM);
        cudaFuncSetAttribute(k_scan_mma, cudaFuncAttributeMaxDynamicSharedMemorySize, SCAN_SMEM);
        cudaFuncSetAttribute(k_out_mma,  cudaFuncAttributeMaxDynamicSharedMemorySize, MMA_SMEM);
        attr_done = true;
    }

    // Wout -> bf16 hi/lo (independent)
    {
        dim3 grid((NPADW / 8 + 255) / 256, KPAD);
        k_cvt_w<<<grid, 256>>>(Wout);
    }
    // Wi -> linear bf16 hi/lo
    k_cvt_wi<<<(T_ * GI_KP * 80 + 255) / 256, 256>>>(Wi);
    // Wh -> fragment bf16 hi/lo
    {
        dim3 grid(40, 200);
        k_cvt_whf<<<grid, 128>>>(Wh);
    }
    // GI = (gathered state) @ Wi + bi (tensor cores, 512 threads, 128-wide chunks)
    {
        dim3 grid(8, 200);
        k_gi_mma<<<grid, 512, GI3_SMEM>>>(q, f, eq, ef, bi);
    }
    // GRU scan (tensor cores, cross-step prefetch, fused hT conversion)
    k_scan_mma<<<128, 640, SCAN_SMEM>>>(bhn, ic);
    // out = hT @ Wout + bout (tensor cores, 2 CTAs/SM)
    {
        dim3 grid(8, NT2);
        k_out_mma<<<grid, 256, MMA_SMEM>>>(bout, out);
    }
}

// round 12
// speedup vs baseline: 2.6569x; 1.0099x over previous
#include <cuda_runtime.h>
#include <cuda_bf16.h>
#include <cstdint>

// Problem constants
#define B_   1024
#define T_   200
#define E_   100
#define H_   200
#define G3_  600      // 3*H
#define NITEMS 100000

#define KPAD 256             // K padded for output GEMM
#define NT2  782             // ceil(100000/128)
#define NPADW (NT2*128)      // 100096

#define GI_KP 112            // K pad for GI GEMM
#define GI_NP 640            // N pad for GI GEMM

// Scratch (device globals; allocation is forbidden)
__device__ float g_GI[(size_t)T_ * B_ * G3_]; // gi = x@Wi+bi  [t][b][600]

// bf16 hi/lo operands for the mma.sync output GEMM
__device__ __nv_bfloat16 g_w_hi[(size_t)KPAD * NPADW];  // [k][n]
__device__ __nv_bfloat16 g_w_lo[(size_t)KPAD * NPADW];
__device__ __nv_bfloat16 g_h_hi[B_ * KPAD];             // [m][k]
__device__ __nv_bfloat16 g_h_lo[B_ * KPAD];
// Wh pre-fragged for scan mma: [t][mt 40][ks 13][lane 32] uint4
__device__ uint4 g_whf_hi[(size_t)T_ * 40 * 13 * 32];
__device__ uint4 g_whf_lo[(size_t)T_ * 40 * 13 * 32];
// Wi linear bf16 hi/lo for GI GEMM: [t][112][640]
__device__ __nv_bfloat16 g_wi_hi[(size_t)T_ * GI_KP * GI_NP];
__device__ __nv_bfloat16 g_wi_lo[(size_t)T_ * GI_KP * GI_NP];

static __device__ __forceinline__ float fast_sigmoid(float x) {
    return __fdividef(1.f, 1.f + __expf(-x));
}
static __device__ __forceinline__ float fast_tanh(float x) {
    x = fminf(fmaxf(x, -15.f), 15.f);
    float p = __expf(2.f * x);
    return __fdividef(p - 1.f, p + 1.f);
}
static __device__ __forceinline__ uint32_t smem_u32(const void* p) {
    uint32_t a;
    asm("{ .reg .u64 t; cvta.to.shared.u64 t, %1; cvt.u32.u64 %0, t; }" : "=r"(a) : "l"(p));
    return a;
}

// ---------------- mma.sync helpers ----------------
static __device__ __forceinline__ void ldmA(uint32_t* r, uint32_t addr) {
    asm volatile("ldmatrix.sync.aligned.m8n8.x4.shared.b16 {%0,%1,%2,%3}, [%4];"
        : "=r"(r[0]), "=r"(r[1]), "=r"(r[2]), "=r"(r[3]) : "r"(addr));
}
static __device__ __forceinline__ void ldmBT(uint32_t* r, uint32_t addr) {
    asm volatile("ldmatrix.sync.aligned.m8n8.x4.trans.shared.b16 {%0,%1,%2,%3}, [%4];"
        : "=r"(r[0]), "=r"(r[1]), "=r"(r[2]), "=r"(r[3]) : "r"(addr));
}
static __device__ __forceinline__ void mma_bf16(float* c, const uint32_t* a, const uint32_t* b) {
    asm volatile("mma.sync.aligned.m16n8k16.row.col.f32.bf16.bf16.f32 "
        "{%0,%1,%2,%3}, {%4,%5,%6,%7}, {%8,%9}, {%0,%1,%2,%3};"
        : "+f"(c[0]), "+f"(c[1]), "+f"(c[2]), "+f"(c[3])
        : "r"(a[0]), "r"(a[1]), "r"(a[2]), "r"(a[3]), "r"(b[0]), "r"(b[1]));
}
static __device__ __forceinline__ void bf_split(float v, unsigned short& h, unsigned short& l) {
    __nv_bfloat16 hh = __float2bfloat16(v);
    h = __bfloat16_as_ushort(hh);
    l = __bfloat16_as_ushort(__float2bfloat16(v - __bfloat162float(hh)));
}
static __device__ __forceinline__ void pack_split2(float v0, float v1, uint32_t& hi2, uint32_t& lo2) {
    asm("cvt.rn.bf16x2.f32 %0, %1, %2;" : "=r"(hi2) : "f"(v1), "f"(v0));
    float h0 = __uint_as_float(hi2 << 16);
    float h1 = __uint_as_float((hi2 >> 16) << 16);
    asm("cvt.rn.bf16x2.f32 %0, %1, %2;" : "=r"(lo2) : "f"(v1 - h1), "f"(v0 - h0));
}
static __device__ __forceinline__ void cp16(uint32_t dst, const void* src) {
    asm volatile("cp.async.cg.shared.global [%0], [%1], 16;" :: "r"(dst), "l"(src) : "memory");
}

// ---------------------------------------------------------------------------
// Wi conversion: [200][100][600] fp32 -> linear [200][112][640] bf16 hi/lo
// ---------------------------------------------------------------------------
__global__ void k_cvt_wi(const float* __restrict__ Wi) {
    int idx = blockIdx.x * 256 + threadIdx.x;   // 200*112*80
    if (idx >= T_ * GI_KP * 80) return;
    int n8 = idx % 80;
    int k  = (idx / 80) % GI_KP;
    int t  = idx / (80 * GI_KP);
    int n  = n8 * 8;

    union { unsigned short u[8]; uint4 v; } ph, pl;
    #pragma unroll
    for (int j = 0; j < 8; ++j) {
        float v = (k < E_ && n + j < G3_) ? __ldg(Wi + ((size_t)t * E_ + k) * G3_ + n + j) : 0.f;
        bf_split(v, ph.u[j], pl.u[j]);
    }
    size_t dst = ((size_t)t * GI_KP + k) * GI_NP + n;
    *(uint4*)(g_wi_hi + dst) = ph.v;
    *(uint4*)(g_wi_lo + dst) = pl.v;
}

// ---------------------------------------------------------------------------
// K2 mma v3: grid (bt 8, t 200); per CTA M=128 x N=640 x K=112.
// 512 threads (16 warps: 2m x 8n), B chunks of 128 cols (5 chunks),
// cp.async double-buffered; bi staged in smem.
// ---------------------------------------------------------------------------
#define GIA_STR 120
#define GIB_STR 136
#define GI3_A_BYTES (128 * GIA_STR * 2)                 // 30720 per split
#define GI3_B_SPLIT (GI_KP * GIB_STR * 2)               // 30464
#define GI3_B_BUF   (2 * GI3_B_SPLIT)                   // 60928
#define GI3_SMEM    (2 * GI3_A_BYTES + 2 * GI3_B_BUF)   // 183296

__global__ void __launch_bounds__(512, 1)
k_gi_mma(const int* __restrict__ q, const int* __restrict__ f,
         const float* __restrict__ eq, const float* __restrict__ ef,
         const float* __restrict__ bi) {
    extern __shared__ char sm[];
    __nv_bfloat16* sAh = (__nv_bfloat16*)sm;                      // [128][120]
    __nv_bfloat16* sAl = (__nv_bfloat16*)(sm + GI3_A_BYTES);
    char* sB = sm + 2 * GI3_A_BYTES;                              // [2][2][112][136]
    __shared__ int sq[128], sf[128];
    __shared__ float sbi[608];

    const int tid  = threadIdx.x;
    const int wid  = tid >> 5, lane = tid & 31;
    const int bt   = blockIdx.x;       // 0..7
    const int t    = blockIdx.y;       // 0..199
    const int wm   = wid & 1;          // m half
    const int wn   = wid >> 1;         // 0..7 : 16-col group within 128 chunk
    const int b_base = bt * 128;

    const uint32_t sB32 = smem_u32(sB);
    // B chunk fill via cp.async: chunk c (128 cols) -> buffer p
    auto fillB = [&](int c, int p) {
        size_t srcbase = (size_t)t * GI_KP * GI_NP + c * 128;
        uint32_t dstbase = sB32 + p * GI3_B_BUF;
        for (int i = tid; i < 3584; i += 512) {
            int split = i / 1792;
            int r = i - split * 1792;
            int k = r >> 4, j = r & 15;
            const __nv_bfloat16* src = (split ? g_wi_lo : g_wi_hi) + srcbase + (size_t)k * GI_NP + j * 8;
            uint32_t dst = dstbase + split * GI3_B_SPLIT + (k * GIB_STR + j * 8) * 2;
            cp16(dst, src);
        }
        asm volatile("cp.async.commit_group;" ::: "memory");
    };

    // issue first B chunk immediately (overlaps A gather)
    fillB(0, 0);

    if (tid < 128) {
        sq[tid] = __ldg(q + (b_base + tid) * T_ + t);
        sf[tid] = __ldg(f + (b_base + tid) * T_ + t);
    }
    for (int i = tid; i < G3_; i += 512)
        sbi[i] = __ldg(bi + t * G3_ + i);
    __syncthreads();

    // A fill: gather+product -> bf16 hi/lo, [m][k] stride 120
    for (int i = tid; i < 128 * 25; i += 512) {
        int m = i / 25, c4 = i - m * 25;
        int k0 = c4 * 4;
        float4 a = __ldg((const float4*)(eq + sq[m] * E_ + k0));
        float4 b = __ldg((const float4*)(ef + sf[m] * E_ + k0));
        float vv[4] = {a.x * b.x, a.y * b.y, a.z * b.z, a.w * b.w};
        union { unsigned short u[4]; uint2 v; } ph, pl;
        #pragma unroll
        for (int j = 0; j < 4; ++j) bf_split(vv[j], ph.u[j], pl.u[j]);
        *(uint2*)(sAh + m * GIA_STR + k0) = ph.v;
        *(uint2*)(sAl + m * GIA_STR + k0) = pl.v;
    }
    for (int i = tid; i < 128 * 6; i += 512) {
        int m = i / 6, kk = 100 + 2 * (i - m * 6);
        *(uint32_t*)(sAh + m * GIA_STR + kk) = 0;
        *(uint32_t*)(sAl + m * GIA_STR + kk) = 0;
    }

    const uint32_t sAh32 = smem_u32(sAh), sAl32 = smem_u32(sAl);

    for (int c = 0; c < 5; ++c) {
        if (c + 1 < 5) {
            fillB(c + 1, (c + 1) & 1);
            asm volatile("cp.async.wait_group 1;" ::: "memory");
        } else {
            asm volatile("cp.async.wait_group 0;" ::: "memory");
        }
        __syncthreads();

        const uint32_t bh32 = sB32 + (c & 1) * GI3_B_BUF;
        const uint32_t bl32 = bh32 + GI3_B_SPLIT;

        float acc[4][2][4];
        #pragma unroll
        for (int i = 0; i < 4; ++i)
            #pragma unroll
            for (int j = 0; j < 2; ++j)
                #pragma unroll
                for (int k = 0; k < 4; ++k) acc[i][j][k] = 0.f;

        #pragma unroll
        for (int ks = 0; ks < 7; ++ks) {
            uint32_t Ah[4][4], Al[4][4];
            #pragma unroll
            for (int fm = 0; fm < 4; ++fm) {
                uint32_t off = ((wm * 64 + fm * 16 + (lane & 15)) * GIA_STR
                                + ks * 16 + (lane >> 4) * 8) * 2;
                ldmA(Ah[fm], sAh32 + off);
                ldmA(Al[fm], sAl32 + off);
            }
            uint32_t Bh[2][2], Bl[2][2];
            {
                uint32_t off = ((ks * 16 + (lane & 15)) * GIB_STR
                                + wn * 16 + (lane >> 4) * 8) * 2;
                uint32_t r[4];
                ldmBT(r, bh32 + off);
                Bh[0][0] = r[0]; Bh[0][1] = r[1];
                Bh[1][0] = r[2]; Bh[1][1] = r[3];
                ldmBT(r, bl32 + off);
                Bl[0][0] = r[0]; Bl[0][1] = r[1];
                Bl[1][0] = r[2]; Bl[1][1] = r[3];
            }
            #pragma unroll
            for (int fm = 0; fm < 4; ++fm)
                #pragma unroll
                for (int fn = 0; fn < 2; ++fn) {
                    mma_bf16(acc[fm][fn], Ah[fm], Bh[fn]);
                    mma_bf16(acc[fm][fn], Ah[fm], Bl[fn]);
                    mma_bf16(acc[fm][fn], Al[fm], Bh[fn]);
                }
        }

        #pragma unroll
        for (int fm = 0; fm < 4; ++fm) {
            int gm = b_base + wm * 64 + fm * 16 + (lane >> 2);
            #pragma unroll
            for (int fn = 0; fn < 2; ++fn) {
                int gn = c * 128 + wn * 16 + fn * 8 + (lane & 3) * 2;
                if (gn < G3_) {
                    float2 bv = *(float2*)&sbi[gn];
                    float2 o0 = make_float2(acc[fm][fn][0] + bv.x, acc[fm][fn][1] + bv.y);
                    float2 o1 = make_float2(acc[fm][fn][2] + bv.x, acc[fm][fn][3] + bv.y);
                    *(float2*)(g_GI + ((size_t)t * B_ + gm) * G3_ + gn) = o0;
                    *(float2*)(g_GI + ((size_t)t * B_ + gm + 8) * G3_ + gn) = o1;
                }
            }
        }
        __syncthreads();
    }
}

// ---------------------------------------------------------------------------
// Wh -> fragment layout conversion (once). 38 mtiles used by the scan.
// ---------------------------------------------------------------------------
__global__ void __launch_bounds__(128)
k_cvt_whf(const float* __restrict__ Wh) {
    __shared__ float sA[208][17];
    const int mt = blockIdx.x;   // 0..37
    const int t  = blockIdx.y;   // 0..199
    const int tid = threadIdx.x;
    const int m0 = mt * 16;

    for (int i = tid; i < 208 * 16; i += 128) {
        int k = i >> 4, mm = i & 15;
        int m = m0 + mm;
        float v = (k < H_ && m < G3_) ? __ldg(Wh + ((size_t)t * H_ + k) * G3_ + m) : 0.f;
        sA[k][mm] = v;
    }
    __syncthreads();

    const int wid = tid >> 5, lane = tid & 31;
    const int g = lane >> 2, c = lane & 3;
    for (int ks = wid; ks < 13; ks += 4) {
        int k0 = ks * 16 + 2 * c;
        uint4 uh, ul;
        pack_split2(sA[k0][g],       sA[k0 + 1][g],     uh.x, ul.x);
        pack_split2(sA[k0][g + 8],   sA[k0 + 1][g + 8], uh.y, ul.y);
        pack_split2(sA[k0 + 8][g],   sA[k0 + 9][g],     uh.z, ul.z);
        pack_split2(sA[k0 + 8][g+8], sA[k0 + 9][g + 8], uh.w, ul.w);
        size_t idx = (((size_t)t * 40 + mt) * 13 + ks) * 32 + lane;
        g_whf_hi[idx] = uh;
        g_whf_lo[idx] = ul;
    }
}

// ---------------------------------------------------------------------------
// K3: GRU scan v7. 128 CTAs x 8 rows, 608 threads (19 warps x 2 mtiles = 38).
// 2-bank accumulators (shorter HMMA dep chains); cross-step weight prefetch;
// fused hT bf16 conversion.
// ---------------------------------------------------------------------------
#define SOFF_GI   0                      // [8][600] f32    19200
#define SOFF_GH   19200                  // [608][10] f32   24320
#define SOFF_HF   43520                  // [8][200] f32    6400
#define SOFF_HHI  49920                  // [8][132] u32    4224
#define SOFF_HLO  54144                  //                 4224
#define SOFF_BHN  58368                  // [200] f32       800
#define SCAN_SMEM 59168

#define WHF_S1    (19 * 13 * 32)         // stream-1 offset (uint4)
#define WHF_TSTEP (40 * 13 * 32)         // per-t offset (uint4)

__global__ void __launch_bounds__(608, 1)
k_scan_mma(const float* __restrict__ bhn, const float* __restrict__ ic) {
    extern __shared__ char sm[];
    float*    sgi = (float*)(sm + SOFF_GI);
    float*    sgh = (float*)(sm + SOFF_GH);
    float*    shf = (float*)(sm + SOFF_HF);
    uint32_t* hh  = (uint32_t*)(sm + SOFF_HHI);
    uint32_t* hl  = (uint32_t*)(sm + SOFF_HLO);
    float*    sbh = (float*)(sm + SOFF_BHN);

    const int tid  = threadIdx.x;
    const int wid  = tid >> 5, lane = tid & 31;   // wid 0..18
    const int b0   = blockIdx.x * 8;
    const int g    = lane >> 2, cc = lane & 3;
    const uint32_t sgi_a = smem_u32(sgi);
    const uint32_t sbh_a = smem_u32(sbh);

    for (int i = tid; i < 8 * 132; i += 608) {
        int w = i % 132;
        uint32_t hi2 = 0, lo2 = 0;
        if (w < 100) {
            float v0 = __ldg(ic + 2 * w), v1 = __ldg(ic + 2 * w + 1);
            pack_split2(v0, v1, hi2, lo2);
        }
        hh[i] = hi2; hl[i] = lo2;
    }
    for (int i = tid; i < 1600; i += 608)
        shf[i] = __ldg(ic + (i % 200));
    __syncthreads();

    float acc0a[4], acc0b[4], acc1a[4], acc1b[4];
    uint4 bh0[2], bl0[2], bh1[2], bl1[2];

    const uint4* ph = g_whf_hi + ((size_t)wid * 13) * 32 + lane;
    const uint4* pl = g_whf_lo + ((size_t)wid * 13) * 32 + lane;

    // preload (t=0, ks=0,1)
    bh0[0] = __ldg(ph);               bl0[0] = __ldg(pl);
    bh1[0] = __ldg(ph + WHF_S1);      bl1[0] = __ldg(pl + WHF_S1);
    bh0[1] = __ldg(ph + 32);          bl0[1] = __ldg(pl + 32);
    bh1[1] = __ldg(ph + WHF_S1 + 32); bl1[1] = __ldg(pl + WHF_S1 + 32);

    for (int t = 0; t < T_; ++t) {
        // prefetch gi[t] + bhn[t]
        {
            const float* gib = g_GI + ((size_t)t * B_ + b0) * G3_;
            for (int i = tid; i < 1250; i += 608) {
                if (i < 1200) {
                    int b = i / 150, o = (i - b * 150) * 16;
                    cp16(sgi_a + b * 2400 + o, (const char*)(gib + b * G3_) + o);
                } else {
                    int j = i - 1200;
                    cp16(sbh_a + j * 16, (const char*)(bhn + t * H_) + j * 16);
                }
            }
            asm volatile("cp.async.commit_group;" ::: "memory");
        }

        #pragma unroll
        for (int c = 0; c < 4; ++c) { acc0a[c] = 0.f; acc0b[c] = 0.f; acc1a[c] = 0.f; acc1b[c] = 0.f; }

        #pragma unroll
        for (int ks = 0; ks < 13; ++ks) {
            const int p = ks & 1;
            uint4 a0h = bh0[p], a0l = bl0[p], a1h = bh1[p], a1l = bl1[p];
            if (ks + 2 < 13) {
                int off = (ks + 2) * 32;
                bh0[p] = __ldg(ph + off);          bl0[p] = __ldg(pl + off);
                bh1[p] = __ldg(ph + WHF_S1 + off); bl1[p] = __ldg(pl + WHF_S1 + off);
            }
            int r0 = g * 132 + ks * 8 + cc;
            uint32_t Bh[2] = { hh[r0], hh[r0 + 4] };
            uint32_t Bl[2] = { hl[r0], hl[r0 + 4] };
            uint32_t Ah0[4] = {a0h.x, a0h.y, a0h.z, a0h.w};
            uint32_t Al0[4] = {a0l.x, a0l.y, a0l.z, a0l.w};
            uint32_t Ah1[4] = {a1h.x, a1h.y, a1h.z, a1h.w};
            uint32_t Al1[4] = {a1l.x, a1l.y, a1l.z, a1l.w};
            mma_bf16(acc0a, Ah0, Bh);
            mma_bf16(acc1a, Ah1, Bh);
            mma_bf16(acc0b, Ah0, Bl);
            mma_bf16(acc1b, Ah1, Bl);
            mma_bf16(acc0b, Al0, Bh);
            mma_bf16(acc1b, Al1, Bh);
        }

        // epilogue: c-frags -> sgh[col][b] (stride 10)
        {
            int m0 = wid * 16;
            *(float2*)&sgh[(m0 + g) * 10 + cc * 2]     = make_float2(acc0a[0] + acc0b[0], acc0a[1] + acc0b[1]);
            *(float2*)&sgh[(m0 + g + 8) * 10 + cc * 2] = make_float2(acc0a[2] + acc0b[2], acc0a[3] + acc0b[3]);
            int m1 = (wid + 19) * 16;
            *(float2*)&sgh[(m1 + g) * 10 + cc * 2]     = make_float2(acc1a[0] + acc1b[0], acc1a[1] + acc1b[1]);
            *(float2*)&sgh[(m1 + g + 8) * 10 + cc * 2] = make_float2(acc1a[2] + acc1b[2], acc1a[3] + acc1b[3]);
        }

        // prefetch next step's first weight frags (overlaps gate phase)
        if (t + 1 < T_) {
            ph += WHF_TSTEP;
            pl += WHF_TSTEP;
            bh0[0] = __ldg(ph);               bl0[0] = __ldg(pl);
            bh1[0] = __ldg(ph + WHF_S1);      bl1[0] = __ldg(pl + WHF_S1);
            bh0[1] = __ldg(ph + 32);          bl0[1] = __ldg(pl + 32);
            bh1[1] = __ldg(ph + WHF_S1 + 32); bl1[1] = __ldg(pl + WHF_S1 + 32);
        }

        asm volatile("cp.async.wait_group 0;" ::: "memory");
        __syncthreads();

        // gate phase: 800 (b, j-pair) items
        for (int i = tid; i < 800; i += 608) {
            int b = i / 100, jp = i - b * 100, j = jp * 2;
            const float* gib = sgi + b * G3_;
            float2 gr = *(const float2*)(gib + j);
            float2 gz = *(const float2*)(gib + 200 + j);
            float2 gn = *(const float2*)(gib + 400 + j);
            float ghr0 = sgh[j * 10 + b],         ghr1 = sgh[(j + 1) * 10 + b];
            float ghz0 = sgh[(200 + j) * 10 + b], ghz1 = sgh[(201 + j) * 10 + b];
            float ghn0 = sgh[(400 + j) * 10 + b], ghn1 = sgh[(401 + j) * 10 + b];
            float2 bv = *(const float2*)(sbh + j);
            float2 ho = *(const float2*)(shf + b * 200 + j);
            float r0 = fast_sigmoid(gr.x + ghr0), r1 = fast_sigmoid(gr.y + ghr1);
            float z0 = fast_sigmoid(gz.x + ghz0), z1 = fast_sigmoid(gz.y + ghz1);
            float n0 = fast_tanh(gn.x + r0 * (ghn0 + bv.x));
            float n1 = fast_tanh(gn.y + r1 * (ghn1 + bv.y));
            float h0 = (1.f - z0) * n0 + z0 * ho.x;
            float h1 = (1.f - z1) * n1 + z1 * ho.y;
            *(float2*)(shf + b * 200 + j) = make_float2(h0, h1);
            uint32_t hi2, lo2;
            pack_split2(h0, h1, hi2, lo2);
            hh[b * 132 + jp] = hi2;
            hl[b * 132 + jp] = lo2;
        }
        __syncthreads();
    }

    // final: fused bf16 hi/lo conversion of hT for the output GEMM
    for (int i = tid; i < 8 * 128; i += 608) {
        int b = i / 128, kp = i - b * 128;
        int k0 = kp * 2;
        float v0 = (k0 < H_) ? shf[b * 200 + k0] : 0.f;
        float v1 = (k0 + 1 < H_) ? shf[b * 200 + k0 + 1] : 0.f;
        uint32_t hi2, lo2;
        pack_split2(v0, v1, hi2, lo2);
        *(uint32_t*)(g_h_hi + (size_t)(b0 + b) * KPAD + k0) = hi2;
        *(uint32_t*)(g_h_lo + (size_t)(b0 + b) * KPAD + k0) = lo2;
    }
}

// ---------------------------------------------------------------------------
// Wout conversion
// ---------------------------------------------------------------------------
__global__ void k_cvt_w(const float* __restrict__ Wout) {
    int nb = blockIdx.x * 256 + threadIdx.x;
    int k  = blockIdx.y;
    if (nb >= NPADW / 8) return;
    int n = nb * 8;

    union { unsigned short u[8]; uint4 v; } ph, pl;
    if (k < H_ && n + 7 < NITEMS) {
        const float4* src = (const float4*)(Wout + (size_t)k * NITEMS + n);
        float4 v0 = __ldg(src), v1 = __ldg(src + 1);
        float vv[8] = {v0.x, v0.y, v0.z, v0.w, v1.x, v1.y, v1.z, v1.w};
        #pragma unroll
        for (int j = 0; j < 8; ++j) bf_split(vv[j], ph.u[j], pl.u[j]);
    } else {
        #pragma unroll
        for (int j = 0; j < 8; ++j) {
            float v = (k < H_ && n + j < NITEMS) ? __ldg(Wout + (size_t)k * NITEMS + n + j) : 0.f;
            bf_split(v, ph.u[j], pl.u[j]);
        }
    }
    *(uint4*)(g_w_hi + (size_t)k * NPADW + n) = ph.v;
    *(uint4*)(g_w_lo + (size_t)k * NPADW + n) = pl.v;
}

// ---------------------------------------------------------------------------
// K4 mma.sync v2: out = hT @ Wout + bout, bf16 hi/lo 3-pass,
// cp.async double-buffered kc pipeline.
// ---------------------------------------------------------------------------
#define ASTR 72
#define BSTR 136
#define OUT_AB (128 * ASTR * 2)           // 18432 per A split
#define OUT_BB (64 * BSTR * 2)            // 17408 per B split
#define OUT_BUF (2 * OUT_AB + 2 * OUT_BB) // 71680
#define MMA_SMEM (2 * OUT_BUF)            // 143360

__global__ void __launch_bounds__(256)
k_out_mma(const float* __restrict__ bout, float* __restrict__ out) {
    extern __shared__ char smc[];
    const int tid  = threadIdx.x;
    const int wid  = tid >> 5, lane = tid & 31;
    const int mt   = blockIdx.x;
    const int nt   = blockIdx.y;
    const int wm   = wid & 1;
    const int wn   = wid >> 1;
    const uint32_t sbase = smem_u32(smc);

    auto fill = [&](int kc, int p) {
        uint32_t buf = sbase + p * OUT_BUF;
        for (int i = tid; i < 2048; i += 256) {
            int split = i >> 10, r = i & 1023;
            int m = r >> 3, kb = r & 7;
            const __nv_bfloat16* src = (split ? g_h_lo : g_h_hi)
                + (size_t)(mt * 128 + m) * KPAD + kc * 64 + kb * 8;
            cp16(buf + split * OUT_AB + (m * ASTR + kb * 8) * 2, src);
        }
        for (int i = tid; i < 2048; i += 256) {
            int split = i >> 10, r = i & 1023;
            int k = r >> 4, nb = r & 15;
            const __nv_bfloat16* src = (split ? g_w_lo : g_w_hi)
                + (size_t)(kc * 64 + k) * NPADW + nt * 128 + nb * 8;
            cp16(buf + 2 * OUT_AB + split * OUT_BB + (k * BSTR + nb * 8) * 2, src);
        }
        asm volatile("cp.async.commit_group;" ::: "memory");
    };

    fill(0, 0);

    float acc[4][4][4];
    #pragma unroll
    for (int i = 0; i < 4; ++i)
        #pragma unroll
        for (int j = 0; j < 4; ++j)
            #pragma unroll
            for (int c = 0; c < 4; ++c) acc[i][j][c] = 0.f;

    for (int kc = 0; kc < 4; ++kc) {
        if (kc + 1 < 4) {
            fill(kc + 1, (kc + 1) & 1);
            asm volatile("cp.async.wait_group 1;" ::: "memory");
        } else {
            asm volatile("cp.async.wait_group 0;" ::: "memory");
        }
        __syncthreads();

        uint32_t buf = sbase + (kc & 1) * OUT_BUF;
        const uint32_t sAh32 = buf, sAl32 = buf + OUT_AB;
        const uint32_t sBh32 = buf + 2 * OUT_AB, sBl32 = sBh32 + OUT_BB;

        #pragma unroll
        for (int ks = 0; ks < 4; ++ks) {
            uint32_t Ah[4][4], Al[4][4];
            #pragma unroll
            for (int fm = 0; fm < 4; ++fm) {
                uint32_t off = ((wm * 64 + fm * 16 + (lane & 15)) * ASTR
                                + ks * 16 + (lane >> 4) * 8) * 2;
                ldmA(Ah[fm], sAh32 + off);
                ldmA(Al[fm], sAl32 + off);
            }
            uint32_t Bh[4][2], Bl[4][2];
            #pragma unroll
            for (int fb = 0; fb < 2; ++fb) {
                uint32_t off = ((ks * 16 + (lane & 15)) * BSTR
                                + wn * 32 + fb * 16 + (lane >> 4) * 8) * 2;
                uint32_t r[4];
                ldmBT(r, sBh32 + off);
                Bh[fb*2][0] = r[0]; Bh[fb*2][1] = r[1];
                Bh[fb*2+1][0] = r[2]; Bh[fb*2+1][1] = r[3];
                ldmBT(r, sBl32 + off);
                Bl[fb*2][0] = r[0]; Bl[fb*2][1] = r[1];
                Bl[fb*2+1][0] = r[2]; Bl[fb*2+1][1] = r[3];
            }
            #pragma unroll
            for (int fm = 0; fm < 4; ++fm)
                #pragma unroll
                for (int fn = 0; fn < 4; ++fn) {
                    mma_bf16(acc[fm][fn], Ah[fm], Bh[fn]);
                    mma_bf16(acc[fm][fn], Ah[fm], Bl[fn]);
                    mma_bf16(acc[fm][fn], Al[fm], Bh[fn]);
                }
        }
        __syncthreads();
    }

    #pragma unroll
    for (int fm = 0; fm < 4; ++fm) {
        int gm = mt * 128 + wm * 64 + fm * 16 + (lane >> 2);
        #pragma unroll
        for (int fn = 0; fn < 4; ++fn) {
            int gn = nt * 128 + wn * 32 + fn * 8 + (lane & 3) * 2;
            if (gn < NITEMS) {
                float2 bv = __ldg((const float2*)(bout + gn));
                float2 o0 = make_float2(acc[fm][fn][0] + bv.x, acc[fm][fn][1] + bv.y);
                float2 o1 = make_float2(acc[fm][fn][2] + bv.x, acc[fm][fn][3] + bv.y);
                *(float2*)(out + (size_t)gm * NITEMS + gn) = o0;
                *(float2*)(out + (size_t)(gm + 8) * NITEMS + gn) = o1;
            }
        }
    }
}

// ---------------------------------------------------------------------------
extern "C" void kernel_launch(void* const* d_in, const int* in_sizes, int n_in,
                              void* d_out, int out_size) {
    const int*   q    = (const int*)  d_in[0];
    const int*   f    = (const int*)  d_in[1];
    const float* eq   = (const float*)d_in[2];
    const float* ef   = (const float*)d_in[3];
    const float* ic   = (const float*)d_in[4];
    const float* Wi   = (const float*)d_in[5];
    const float* bi   = (const float*)d_in[6];
    const float* Wh   = (const float*)d_in[7];
    const float* bhn  = (const float*)d_in[8];
    const float* Wout = (const float*)d_in[9];
    const float* bout = (const float*)d_in[10];
    float* out = (float*)d_out;

    static bool attr_done = false;
    if (!attr_done) {
        cudaFuncSetAttribute(k_gi_mma,   cudaFuncAttributeMaxDynamicSharedMemorySize, GI3_SMEM);
        cudaFuncSetAttribute(k_scan_mma, cudaFuncAttributeMaxDynamicSharedMemorySize, SCAN_SMEM);
        cudaFuncSetAttribute(k_out_mma,  cudaFuncAttributeMaxDynamicSharedMemorySize, MMA_SMEM);
        attr_done = true;
    }

    // Wout -> bf16 hi/lo (independent)
    {
        dim3 grid((NPADW / 8 + 255) / 256, KPAD);
        k_cvt_w<<<grid, 256>>>(Wout);
    }
    // Wi -> linear bf16 hi/lo
    k_cvt_wi<<<(T_ * GI_KP * 80 + 255) / 256, 256>>>(Wi);
    // Wh -> fragment bf16 hi/lo (38 mtiles used)
    {
        dim3 grid(38, 200);
        k_cvt_whf<<<grid, 128>>>(Wh);
    }
    // GI = (gathered state) @ Wi + bi
    {
        dim3 grid(8, 200);
        k_gi_mma<<<grid, 512, GI3_SMEM>>>(q, f, eq, ef, bi);
    }
    // GRU scan (tensor cores, 608 threads, 2-bank accumulators)
    k_scan_mma<<<128, 608, SCAN_SMEM>>>(bhn, ic);
    // out = hT @ Wout + bout (tensor cores, cp.async pipelined)
    {
        dim3 grid(8, NT2);
        k_out_mma<<<grid, 256, MMA_SMEM>>>(bout, out);
    }
}

// round 13
// speedup vs baseline: 2.8150x; 1.0595x over previous
#include <cuda_runtime.h>
#include <cuda_bf16.h>
#include <cstdint>

// Problem constants
#define B_   1024
#define T_   200
#define E_   100
#define H_   200
#define G3_  600      // 3*H
#define NITEMS 100000

#define KPAD 256             // K padded storage for output GEMM operands
#define NT3  391             // ceil(100000/256)
#define NPADW (NT3*256)      // 100096

#define GI_KP 112            // K pad for GI GEMM
#define GI_NP 640            // N pad for GI GEMM

// Scratch (device globals; allocation is forbidden)
__device__ float g_GI[(size_t)T_ * B_ * G3_]; // gi = x@Wi+bi  [t][b][600]

// bf16 hi/lo operands for the mma.sync output GEMM
__device__ __nv_bfloat16 g_w_hi[(size_t)KPAD * NPADW];  // [k][n]
__device__ __nv_bfloat16 g_w_lo[(size_t)KPAD * NPADW];
__device__ __nv_bfloat16 g_h_hi[B_ * KPAD];             // [m][k]
__device__ __nv_bfloat16 g_h_lo[B_ * KPAD];
// Wh pre-fragged for scan mma: [t][mt 40][ks 13][lane 32] uint4
__device__ uint4 g_whf_hi[(size_t)T_ * 40 * 13 * 32];
__device__ uint4 g_whf_lo[(size_t)T_ * 40 * 13 * 32];
// Wi linear bf16 hi/lo for GI GEMM: [t][112][640]
__device__ __nv_bfloat16 g_wi_hi[(size_t)T_ * GI_KP * GI_NP];
__device__ __nv_bfloat16 g_wi_lo[(size_t)T_ * GI_KP * GI_NP];

static __device__ __forceinline__ float fast_sigmoid(float x) {
    return __fdividef(1.f, 1.f + __expf(-x));
}
static __device__ __forceinline__ float fast_tanh(float x) {
    x = fminf(fmaxf(x, -15.f), 15.f);
    float p = __expf(2.f * x);
    return __fdividef(p - 1.f, p + 1.f);
}
static __device__ __forceinline__ uint32_t smem_u32(const void* p) {
    uint32_t a;
    asm("{ .reg .u64 t; cvta.to.shared.u64 t, %1; cvt.u32.u64 %0, t; }" : "=r"(a) : "l"(p));
    return a;
}

// ---------------- mma.sync helpers ----------------
static __device__ __forceinline__ void ldmA(uint32_t* r, uint32_t addr) {
    asm volatile("ldmatrix.sync.aligned.m8n8.x4.shared.b16 {%0,%1,%2,%3}, [%4];"
        : "=r"(r[0]), "=r"(r[1]), "=r"(r[2]), "=r"(r[3]) : "r"(addr));
}
static __device__ __forceinline__ void ldmBT(uint32_t* r, uint32_t addr) {
    asm volatile("ldmatrix.sync.aligned.m8n8.x4.trans.shared.b16 {%0,%1,%2,%3}, [%4];"
        : "=r"(r[0]), "=r"(r[1]), "=r"(r[2]), "=r"(r[3]) : "r"(addr));
}
static __device__ __forceinline__ void mma_bf16(float* c, const uint32_t* a, const uint32_t* b) {
    asm volatile("mma.sync.aligned.m16n8k16.row.col.f32.bf16.bf16.f32 "
        "{%0,%1,%2,%3}, {%4,%5,%6,%7}, {%8,%9}, {%0,%1,%2,%3};"
        : "+f"(c[0]), "+f"(c[1]), "+f"(c[2]), "+f"(c[3])
        : "r"(a[0]), "r"(a[1]), "r"(a[2]), "r"(a[3]), "r"(b[0]), "r"(b[1]));
}
static __device__ __forceinline__ void bf_split(float v, unsigned short& h, unsigned short& l) {
    __nv_bfloat16 hh = __float2bfloat16(v);
    h = __bfloat16_as_ushort(hh);
    l = __bfloat16_as_ushort(__float2bfloat16(v - __bfloat162float(hh)));
}
static __device__ __forceinline__ void pack_split2(float v0, float v1, uint32_t& hi2, uint32_t& lo2) {
    asm("cvt.rn.bf16x2.f32 %0, %1, %2;" : "=r"(hi2) : "f"(v1), "f"(v0));
    float h0 = __uint_as_float(hi2 << 16);
    float h1 = __uint_as_float((hi2 >> 16) << 16);
    asm("cvt.rn.bf16x2.f32 %0, %1, %2;" : "=r"(lo2) : "f"(v1 - h1), "f"(v0 - h0));
}
static __device__ __forceinline__ void cp16(uint32_t dst, const void* src) {
    asm volatile("cp.async.cg.shared.global [%0], [%1], 16;" :: "r"(dst), "l"(src) : "memory");
}

// ---------------------------------------------------------------------------
// Wi conversion: [200][100][600] fp32 -> linear [200][112][640] bf16 hi/lo
// ---------------------------------------------------------------------------
__global__ void k_cvt_wi(const float* __restrict__ Wi) {
    int idx = blockIdx.x * 256 + threadIdx.x;   // 200*112*80
    if (idx >= T_ * GI_KP * 80) return;
    int n8 = idx % 80;
    int k  = (idx / 80) % GI_KP;
    int t  = idx / (80 * GI_KP);
    int n  = n8 * 8;

    union { unsigned short u[8]; uint4 v; } ph, pl;
    #pragma unroll
    for (int j = 0; j < 8; ++j) {
        float v = (k < E_ && n + j < G3_) ? __ldg(Wi + ((size_t)t * E_ + k) * G3_ + n + j) : 0.f;
        bf_split(v, ph.u[j], pl.u[j]);
    }
    size_t dst = ((size_t)t * GI_KP + k) * GI_NP + n;
    *(uint4*)(g_wi_hi + dst) = ph.v;
    *(uint4*)(g_wi_lo + dst) = pl.v;
}

// ---------------------------------------------------------------------------
// K2 mma v3: grid (bt 8, t 200); per CTA M=128 x N=640 x K=112.
// 512 threads (16 warps: 2m x 8n), B chunks of 128 cols (5 chunks),
// cp.async double-buffered; bi staged in smem.
// ---------------------------------------------------------------------------
#define GIA_STR 120
#define GIB_STR 136
#define GI3_A_BYTES (128 * GIA_STR * 2)                 // 30720 per split
#define GI3_B_SPLIT (GI_KP * GIB_STR * 2)               // 30464
#define GI3_B_BUF   (2 * GI3_B_SPLIT)                   // 60928
#define GI3_SMEM    (2 * GI3_A_BYTES + 2 * GI3_B_BUF)   // 183296

__global__ void __launch_bounds__(512, 1)
k_gi_mma(const int* __restrict__ q, const int* __restrict__ f,
         const float* __restrict__ eq, const float* __restrict__ ef,
         const float* __restrict__ bi) {
    extern __shared__ char sm[];
    __nv_bfloat16* sAh = (__nv_bfloat16*)sm;                      // [128][120]
    __nv_bfloat16* sAl = (__nv_bfloat16*)(sm + GI3_A_BYTES);
    char* sB = sm + 2 * GI3_A_BYTES;                              // [2][2][112][136]
    __shared__ int sq[128], sf[128];
    __shared__ float sbi[608];

    const int tid  = threadIdx.x;
    const int wid  = tid >> 5, lane = tid & 31;
    const int bt   = blockIdx.x;       // 0..7
    const int t    = blockIdx.y;       // 0..199
    const int wm   = wid & 1;          // m half
    const int wn   = wid >> 1;         // 0..7 : 16-col group within 128 chunk
    const int b_base = bt * 128;

    const uint32_t sB32 = smem_u32(sB);
    auto fillB = [&](int c, int p) {
        size_t srcbase = (size_t)t * GI_KP * GI_NP + c * 128;
        uint32_t dstbase = sB32 + p * GI3_B_BUF;
        for (int i = tid; i < 3584; i += 512) {
            int split = i / 1792;
            int r = i - split * 1792;
            int k = r >> 4, j = r & 15;
            const __nv_bfloat16* src = (split ? g_wi_lo : g_wi_hi) + srcbase + (size_t)k * GI_NP + j * 8;
            uint32_t dst = dstbase + split * GI3_B_SPLIT + (k * GIB_STR + j * 8) * 2;
            cp16(dst, src);
        }
        asm volatile("cp.async.commit_group;" ::: "memory");
    };

    fillB(0, 0);

    if (tid < 128) {
        sq[tid] = __ldg(q + (b_base + tid) * T_ + t);
        sf[tid] = __ldg(f + (b_base + tid) * T_ + t);
    }
    for (int i = tid; i < G3_; i += 512)
        sbi[i] = __ldg(bi + t * G3_ + i);
    __syncthreads();

    for (int i = tid; i < 128 * 25; i += 512) {
        int m = i / 25, c4 = i - m * 25;
        int k0 = c4 * 4;
        float4 a = __ldg((const float4*)(eq + sq[m] * E_ + k0));
        float4 b = __ldg((const float4*)(ef + sf[m] * E_ + k0));
        float vv[4] = {a.x * b.x, a.y * b.y, a.z * b.z, a.w * b.w};
        union { unsigned short u[4]; uint2 v; } ph, pl;
        #pragma unroll
        for (int j = 0; j < 4; ++j) bf_split(vv[j], ph.u[j], pl.u[j]);
        *(uint2*)(sAh + m * GIA_STR + k0) = ph.v;
        *(uint2*)(sAl + m * GIA_STR + k0) = pl.v;
    }
    for (int i = tid; i < 128 * 6; i += 512) {
        int m = i / 6, kk = 100 + 2 * (i - m * 6);
        *(uint32_t*)(sAh + m * GIA_STR + kk) = 0;
        *(uint32_t*)(sAl + m * GIA_STR + kk) = 0;
    }

    const uint32_t sAh32 = smem_u32(sAh), sAl32 = smem_u32(sAl);

    for (int c = 0; c < 5; ++c) {
        if (c + 1 < 5) {
            fillB(c + 1, (c + 1) & 1);
            asm volatile("cp.async.wait_group 1;" ::: "memory");
        } else {
            asm volatile("cp.async.wait_group 0;" ::: "memory");
        }
        __syncthreads();

        const uint32_t bh32 = sB32 + (c & 1) * GI3_B_BUF;
        const uint32_t bl32 = bh32 + GI3_B_SPLIT;

        float acc[4][2][4];
        #pragma unroll
        for (int i = 0; i < 4; ++i)
            #pragma unroll
            for (int j = 0; j < 2; ++j)
                #pragma unroll
                for (int k = 0; k < 4; ++k) acc[i][j][k] = 0.f;

        #pragma unroll
        for (int ks = 0; ks < 7; ++ks) {
            uint32_t Ah[4][4], Al[4][4];
            #pragma unroll
            for (int fm = 0; fm < 4; ++fm) {
                uint32_t off = ((wm * 64 + fm * 16 + (lane & 15)) * GIA_STR
                                + ks * 16 + (lane >> 4) * 8) * 2;
                ldmA(Ah[fm], sAh32 + off);
                ldmA(Al[fm], sAl32 + off);
            }
            uint32_t Bh[2][2], Bl[2][2];
            {
                uint32_t off = ((ks * 16 + (lane & 15)) * GIB_STR
                                + wn * 16 + (lane >> 4) * 8) * 2;
                uint32_t r[4];
                ldmBT(r, bh32 + off);
                Bh[0][0] = r[0]; Bh[0][1] = r[1];
                Bh[1][0] = r[2]; Bh[1][1] = r[3];
                ldmBT(r, bl32 + off);
                Bl[0][0] = r[0]; Bl[0][1] = r[1];
                Bl[1][0] = r[2]; Bl[1][1] = r[3];
            }
            #pragma unroll
            for (int fm = 0; fm < 4; ++fm)
                #pragma unroll
                for (int fn = 0; fn < 2; ++fn) {
                    mma_bf16(acc[fm][fn], Ah[fm], Bh[fn]);
                    mma_bf16(acc[fm][fn], Ah[fm], Bl[fn]);
                    mma_bf16(acc[fm][fn], Al[fm], Bh[fn]);
                }
        }

        #pragma unroll
        for (int fm = 0; fm < 4; ++fm) {
            int gm = b_base + wm * 64 + fm * 16 + (lane >> 2);
            #pragma unroll
            for (int fn = 0; fn < 2; ++fn) {
                int gn = c * 128 + wn * 16 + fn * 8 + (lane & 3) * 2;
                if (gn < G3_) {
                    float2 bv = *(float2*)&sbi[gn];
                    float2 o0 = make_float2(acc[fm][fn][0] + bv.x, acc[fm][fn][1] + bv.y);
                    float2 o1 = make_float2(acc[fm][fn][2] + bv.x, acc[fm][fn][3] + bv.y);
                    *(float2*)(g_GI + ((size_t)t * B_ + gm) * G3_ + gn) = o0;
                    *(float2*)(g_GI + ((size_t)t * B_ + gm + 8) * G3_ + gn) = o1;
                }
            }
        }
        __syncthreads();
    }
}

// ---------------------------------------------------------------------------
// Wh -> fragment layout conversion (once). 38 mtiles used by the scan.
// ---------------------------------------------------------------------------
__global__ void __launch_bounds__(128)
k_cvt_whf(const float* __restrict__ Wh) {
    __shared__ float sA[208][17];
    const int mt = blockIdx.x;   // 0..37
    const int t  = blockIdx.y;   // 0..199
    const int tid = threadIdx.x;
    const int m0 = mt * 16;

    for (int i = tid; i < 208 * 16; i += 128) {
        int k = i >> 4, mm = i & 15;
        int m = m0 + mm;
        float v = (k < H_ && m < G3_) ? __ldg(Wh + ((size_t)t * H_ + k) * G3_ + m) : 0.f;
        sA[k][mm] = v;
    }
    __syncthreads();

    const int wid = tid >> 5, lane = tid & 31;
    const int g = lane >> 2, c = lane & 3;
    for (int ks = wid; ks < 13; ks += 4) {
        int k0 = ks * 16 + 2 * c;
        uint4 uh, ul;
        pack_split2(sA[k0][g],       sA[k0 + 1][g],     uh.x, ul.x);
        pack_split2(sA[k0][g + 8],   sA[k0 + 1][g + 8], uh.y, ul.y);
        pack_split2(sA[k0 + 8][g],   sA[k0 + 9][g],     uh.z, ul.z);
        pack_split2(sA[k0 + 8][g+8], sA[k0 + 9][g + 8], uh.w, ul.w);
        size_t idx = (((size_t)t * 40 + mt) * 13 + ks) * 32 + lane;
        g_whf_hi[idx] = uh;
        g_whf_lo[idx] = ul;
    }
}

// ---------------------------------------------------------------------------
// K3: GRU scan v7. 128 CTAs x 8 rows, 608 threads (19 warps x 2 mtiles = 38).
// ---------------------------------------------------------------------------
#define SOFF_GI   0                      // [8][600] f32    19200
#define SOFF_GH   19200                  // [608][10] f32   24320
#define SOFF_HF   43520                  // [8][200] f32    6400
#define SOFF_HHI  49920                  // [8][132] u32    4224
#define SOFF_HLO  54144                  //                 4224
#define SOFF_BHN  58368                  // [200] f32       800
#define SCAN_SMEM 59168

#define WHF_S1    (19 * 13 * 32)         // stream-1 offset (uint4)
#define WHF_TSTEP (40 * 13 * 32)         // per-t offset (uint4)

__global__ void __launch_bounds__(608, 1)
k_scan_mma(const float* __restrict__ bhn, const float* __restrict__ ic) {
    extern __shared__ char sm[];
    float*    sgi = (float*)(sm + SOFF_GI);
    float*    sgh = (float*)(sm + SOFF_GH);
    float*    shf = (float*)(sm + SOFF_HF);
    uint32_t* hh  = (uint32_t*)(sm + SOFF_HHI);
    uint32_t* hl  = (uint32_t*)(sm + SOFF_HLO);
    float*    sbh = (float*)(sm + SOFF_BHN);

    const int tid  = threadIdx.x;
    const int wid  = tid >> 5, lane = tid & 31;   // wid 0..18
    const int b0   = blockIdx.x * 8;
    const int g    = lane >> 2, cc = lane & 3;
    const uint32_t sgi_a = smem_u32(sgi);
    const uint32_t sbh_a = smem_u32(sbh);

    for (int i = tid; i < 8 * 132; i += 608) {
        int w = i % 132;
        uint32_t hi2 = 0, lo2 = 0;
        if (w < 100) {
            float v0 = __ldg(ic + 2 * w), v1 = __ldg(ic + 2 * w + 1);
            pack_split2(v0, v1, hi2, lo2);
        }
        hh[i] = hi2; hl[i] = lo2;
    }
    for (int i = tid; i < 1600; i += 608)
        shf[i] = __ldg(ic + (i % 200));
    __syncthreads();

    float acc0a[4], acc0b[4], acc1a[4], acc1b[4];
    uint4 bh0[2], bl0[2], bh1[2], bl1[2];

    const uint4* ph = g_whf_hi + ((size_t)wid * 13) * 32 + lane;
    const uint4* pl = g_whf_lo + ((size_t)wid * 13) * 32 + lane;

    bh0[0] = __ldg(ph);               bl0[0] = __ldg(pl);
    bh1[0] = __ldg(ph + WHF_S1);      bl1[0] = __ldg(pl + WHF_S1);
    bh0[1] = __ldg(ph + 32);          bl0[1] = __ldg(pl + 32);
    bh1[1] = __ldg(ph + WHF_S1 + 32); bl1[1] = __ldg(pl + WHF_S1 + 32);

    for (int t = 0; t < T_; ++t) {
        {
            const float* gib = g_GI + ((size_t)t * B_ + b0) * G3_;
            for (int i = tid; i < 1250; i += 608) {
                if (i < 1200) {
                    int b = i / 150, o = (i - b * 150) * 16;
                    cp16(sgi_a + b * 2400 + o, (const char*)(gib + b * G3_) + o);
                } else {
                    int j = i - 1200;
                    cp16(sbh_a + j * 16, (const char*)(bhn + t * H_) + j * 16);
                }
            }
            asm volatile("cp.async.commit_group;" ::: "memory");
        }

        #pragma unroll
        for (int c = 0; c < 4; ++c) { acc0a[c] = 0.f; acc0b[c] = 0.f; acc1a[c] = 0.f; acc1b[c] = 0.f; }

        #pragma unroll
        for (int ks = 0; ks < 13; ++ks) {
            const int p = ks & 1;
            uint4 a0h = bh0[p], a0l = bl0[p], a1h = bh1[p], a1l = bl1[p];
            if (ks + 2 < 13) {
                int off = (ks + 2) * 32;
                bh0[p] = __ldg(ph + off);          bl0[p] = __ldg(pl + off);
                bh1[p] = __ldg(ph + WHF_S1 + off); bl1[p] = __ldg(pl + WHF_S1 + off);
            }
            int r0 = g * 132 + ks * 8 + cc;
            uint32_t Bh[2] = { hh[r0], hh[r0 + 4] };
            uint32_t Bl[2] = { hl[r0], hl[r0 + 4] };
            uint32_t Ah0[4] = {a0h.x, a0h.y, a0h.z, a0h.w};
            uint32_t Al0[4] = {a0l.x, a0l.y, a0l.z, a0l.w};
            uint32_t Ah1[4] = {a1h.x, a1h.y, a1h.z, a1h.w};
            uint32_t Al1[4] = {a1l.x, a1l.y, a1l.z, a1l.w};
            mma_bf16(acc0a, Ah0, Bh);
            mma_bf16(acc1a, Ah1, Bh);
            mma_bf16(acc0b, Ah0, Bl);
            mma_bf16(acc1b, Ah1, Bl);
            mma_bf16(acc0b, Al0, Bh);
            mma_bf16(acc1b, Al1, Bh);
        }

        {
            int m0 = wid * 16;
            *(float2*)&sgh[(m0 + g) * 10 + cc * 2]     = make_float2(acc0a[0] + acc0b[0], acc0a[1] + acc0b[1]);
            *(float2*)&sgh[(m0 + g + 8) * 10 + cc * 2] = make_float2(acc0a[2] + acc0b[2], acc0a[3] + acc0b[3]);
            int m1 = (wid + 19) * 16;
            *(float2*)&sgh[(m1 + g) * 10 + cc * 2]     = make_float2(acc1a[0] + acc1b[0], acc1a[1] + acc1b[1]);
            *(float2*)&sgh[(m1 + g + 8) * 10 + cc * 2] = make_float2(acc1a[2] + acc1b[2], acc1a[3] + acc1b[3]);
        }

        if (t + 1 < T_) {
            ph += WHF_TSTEP;
            pl += WHF_TSTEP;
            bh0[0] = __ldg(ph);               bl0[0] = __ldg(pl);
            bh1[0] = __ldg(ph + WHF_S1);      bl1[0] = __ldg(pl + WHF_S1);
            bh0[1] = __ldg(ph + 32);          bl0[1] = __ldg(pl + 32);
            bh1[1] = __ldg(ph + WHF_S1 + 32); bl1[1] = __ldg(pl + WHF_S1 + 32);
        }

        asm volatile("cp.async.wait_group 0;" ::: "memory");
        __syncthreads();

        for (int i = tid; i < 800; i += 608) {
            int b = i / 100, jp = i - b * 100, j = jp * 2;
            const float* gib = sgi + b * G3_;
            float2 gr = *(const float2*)(gib + j);
            float2 gz = *(const float2*)(gib + 200 + j);
            float2 gn = *(const float2*)(gib + 400 + j);
            float ghr0 = sgh[j * 10 + b],         ghr1 = sgh[(j + 1) * 10 + b];
            float ghz0 = sgh[(200 + j) * 10 + b], ghz1 = sgh[(201 + j) * 10 + b];
            float ghn0 = sgh[(400 + j) * 10 + b], ghn1 = sgh[(401 + j) * 10 + b];
            float2 bv = *(const float2*)(sbh + j);
            float2 ho = *(const float2*)(shf + b * 200 + j);
            float r0 = fast_sigmoid(gr.x + ghr0), r1 = fast_sigmoid(gr.y + ghr1);
            float z0 = fast_sigmoid(gz.x + ghz0), z1 = fast_sigmoid(gz.y + ghz1);
            float n0 = fast_tanh(gn.x + r0 * (ghn0 + bv.x));
            float n1 = fast_tanh(gn.y + r1 * (ghn1 + bv.y));
            float h0 = (1.f - z0) * n0 + z0 * ho.x;
            float h1 = (1.f - z1) * n1 + z1 * ho.y;
            *(float2*)(shf + b * 200 + j) = make_float2(h0, h1);
            uint32_t hi2, lo2;
            pack_split2(h0, h1, hi2, lo2);
            hh[b * 132 + jp] = hi2;
            hl[b * 132 + jp] = lo2;
        }
        __syncthreads();
    }

    // final: fused bf16 hi/lo conversion of hT for the output GEMM
    for (int i = tid; i < 8 * 128; i += 608) {
        int b = i / 128, kp = i - b * 128;
        int k0 = kp * 2;
        float v0 = (k0 < H_) ? shf[b * 200 + k0] : 0.f;
        float v1 = (k0 + 1 < H_) ? shf[b * 200 + k0 + 1] : 0.f;
        uint32_t hi2, lo2;
        pack_split2(v0, v1, hi2, lo2);
        *(uint32_t*)(g_h_hi + (size_t)(b0 + b) * KPAD + k0) = hi2;
        *(uint32_t*)(g_h_lo + (size_t)(b0 + b) * KPAD + k0) = lo2;
    }
}

// ---------------------------------------------------------------------------
// Wout conversion
// ---------------------------------------------------------------------------
__global__ void k_cvt_w(const float* __restrict__ Wout) {
    int nb = blockIdx.x * 256 + threadIdx.x;
    int k  = blockIdx.y;
    if (nb >= NPADW / 8) return;
    int n = nb * 8;

    union { unsigned short u[8]; uint4 v; } ph, pl;
    if (k < H_ && n + 7 < NITEMS) {
        const float4* src = (const float4*)(Wout + (size_t)k * NITEMS + n);
        float4 v0 = __ldg(src), v1 = __ldg(src + 1);
        float vv[8] = {v0.x, v0.y, v0.z, v0.w, v1.x, v1.y, v1.z, v1.w};
        #pragma unroll
        for (int j = 0; j < 8; ++j) bf_split(vv[j], ph.u[j], pl.u[j]);
    } else {
        #pragma unroll
        for (int j = 0; j < 8; ++j) {
            float v = (k < H_ && n + j < NITEMS) ? __ldg(Wout + (size_t)k * NITEMS + n + j) : 0.f;
            bf_split(v, ph.u[j], pl.u[j]);
        }
    }
    *(uint4*)(g_w_hi + (size_t)k * NPADW + n) = ph.v;
    *(uint4*)(g_w_lo + (size_t)k * NPADW + n) = pl.v;
}

// ---------------------------------------------------------------------------
// K4 mma.sync v3: out = hT @ Wout + bout, bf16 hi/lo 3-pass.
// 512 threads (16 warps: 2m x 8n), BN=256, K trimmed to 208 (chunks 64/64/64/16),
// cp.async double-buffered. grid (8, 391).
// ---------------------------------------------------------------------------
#define OASTR 72
#define OBSTR 264
#define OUT_AB (128 * OASTR * 2)            // 18432 per A split
#define OUT_BB (64 * OBSTR * 2)             // 33792 per B split
#define OUT_BUF (2 * OUT_AB + 2 * OUT_BB)   // 104448
#define MMA_SMEM (2 * OUT_BUF)              // 208896

__global__ void __launch_bounds__(512, 1)
k_out_mma(const float* __restrict__ bout, float* __restrict__ out) {
    extern __shared__ char smc[];
    const int tid  = threadIdx.x;
    const int wid  = tid >> 5, lane = tid & 31;
    const int mt   = blockIdx.x;        // 0..7
    const int nt   = blockIdx.y;        // 0..390
    const int wm   = wid & 1;           // m half (64)
    const int wn   = wid >> 1;          // 0..7 : 32-col group of 256
    const uint32_t sbase = smem_u32(smc);

    auto fill = [&](int kc, int p) {
        const int nk = (kc < 3) ? 4 : 1;          // ks per chunk
        const int k0 = kc * 64;
        uint32_t buf = sbase + p * OUT_BUF;
        int per = nk * 2;                          // cp16 per A row
        int aTot = 2 * 128 * per;
        for (int i = tid; i < aTot; i += 512) {
            int split = i / (128 * per);
            int r = i - split * 128 * per;
            int m = r / per, kb = r - m * per;
            const __nv_bfloat16* src = (split ? g_h_lo : g_h_hi)
                + (size_t)(mt * 128 + m) * KPAD + k0 + kb * 8;
            cp16(buf + split * OUT_AB + (m * OASTR + kb * 8) * 2, src);
        }
        int rows = nk * 16;
        int bTot = 2 * rows * 32;
        for (int i = tid; i < bTot; i += 512) {
            int split = i / (rows * 32);
            int r = i - split * rows * 32;
            int k = r >> 5, nb = r & 31;
            const __nv_bfloat16* src = (split ? g_w_lo : g_w_hi)
                + (size_t)(k0 + k) * NPADW + nt * 256 + nb * 8;
            cp16(buf + 2 * OUT_AB + split * OUT_BB + (k * OBSTR + nb * 8) * 2, src);
        }
        asm volatile("cp.async.commit_group;" ::: "memory");
    };

    fill(0, 0);

    float acc[4][4][4];
    #pragma unroll
    for (int i = 0; i < 4; ++i)
        #pragma unroll
        for (int j = 0; j < 4; ++j)
            #pragma unroll
            for (int c = 0; c < 4; ++c) acc[i][j][c] = 0.f;

    for (int kc = 0; kc < 4; ++kc) {
        if (kc + 1 < 4) {
            fill(kc + 1, (kc + 1) & 1);
            asm volatile("cp.async.wait_group 1;" ::: "memory");
        } else {
            asm volatile("cp.async.wait_group 0;" ::: "memory");
        }
        __syncthreads();

        uint32_t buf = sbase + (kc & 1) * OUT_BUF;
        const uint32_t sAh32 = buf, sAl32 = buf + OUT_AB;
        const uint32_t sBh32 = buf + 2 * OUT_AB, sBl32 = sBh32 + OUT_BB;
        const int nk = (kc < 3) ? 4 : 1;

        #pragma unroll 4
        for (int ks = 0; ks < nk; ++ks) {
            uint32_t Ah[4][4], Al[4][4];
            #pragma unroll
            for (int fm = 0; fm < 4; ++fm) {
                uint32_t off = ((wm * 64 + fm * 16 + (lane & 15)) * OASTR
                                + ks * 16 + (lane >> 4) * 8) * 2;
                ldmA(Ah[fm], sAh32 + off);
                ldmA(Al[fm], sAl32 + off);
            }
            uint32_t Bh[4][2], Bl[4][2];
            #pragma unroll
            for (int fb = 0; fb < 2; ++fb) {
                uint32_t off = ((ks * 16 + (lane & 15)) * OBSTR
                                + wn * 32 + fb * 16 + (lane >> 4) * 8) * 2;
                uint32_t r[4];
                ldmBT(r, sBh32 + off);
                Bh[fb*2][0] = r[0]; Bh[fb*2][1] = r[1];
                Bh[fb*2+1][0] = r[2]; Bh[fb*2+1][1] = r[3];
                ldmBT(r, sBl32 + off);
                Bl[fb*2][0] = r[0]; Bl[fb*2][1] = r[1];
                Bl[fb*2+1][0] = r[2]; Bl[fb*2+1][1] = r[3];
            }
            #pragma unroll
            for (int fm = 0; fm < 4; ++fm)
                #pragma unroll
                for (int fn = 0; fn < 4; ++fn) {
                    mma_bf16(acc[fm][fn], Ah[fm], Bh[fn]);
                    mma_bf16(acc[fm][fn], Ah[fm], Bl[fn]);
                    mma_bf16(acc[fm][fn], Al[fm], Bh[fn]);
                }
        }
        __syncthreads();
    }

    #pragma unroll
    for (int fm = 0; fm < 4; ++fm) {
        int gm = mt * 128 + wm * 64 + fm * 16 + (lane >> 2);
        #pragma unroll
        for (int fn = 0; fn < 4; ++fn) {
            int gn = nt * 256 + wn * 32 + fn * 8 + (lane & 3) * 2;
            if (gn < NITEMS) {
                float2 bv = __ldg((const float2*)(bout + gn));
                float2 o0 = make_float2(acc[fm][fn][0] + bv.x, acc[fm][fn][1] + bv.y);
                float2 o1 = make_float2(acc[fm][fn][2] + bv.x, acc[fm][fn][3] + bv.y);
                *(float2*)(out + (size_t)gm * NITEMS + gn) = o0;
                *(float2*)(out + (size_t)(gm + 8) * NITEMS + gn) = o1;
            }
        }
    }
}

// ---------------------------------------------------------------------------
extern "C" void kernel_launch(void* const* d_in, const int* in_sizes, int n_in,
                              void* d_out, int out_size) {
    const int*   q    = (const int*)  d_in[0];
    const int*   f    = (const int*)  d_in[1];
    const float* eq   = (const float*)d_in[2];
    const float* ef   = (const float*)d_in[3];
    const float* ic   = (const float*)d_in[4];
    const float* Wi   = (const float*)d_in[5];
    const float* bi   = (const float*)d_in[6];
    const float* Wh   = (const float*)d_in[7];
    const float* bhn  = (const float*)d_in[8];
    const float* Wout = (const float*)d_in[9];
    const float* bout = (const float*)d_in[10];
    float* out = (float*)d_out;

    static bool attr_done = false;
    if (!attr_done) {
        cudaFuncSetAttribute(k_gi_mma,   cudaFuncAttributeMaxDynamicSharedMemorySize, GI3_SMEM);
        cudaFuncSetAttribute(k_scan_mma, cudaFuncAttributeMaxDynamicSharedMemorySize, SCAN_SMEM);
        cudaFuncSetAttribute(k_out_mma,  cudaFuncAttributeMaxDynamicSharedMemorySize, MMA_SMEM);
        attr_done = true;
    }

    // Wout -> bf16 hi/lo (independent)
    {
        dim3 grid((NPADW / 8 + 255) / 256, KPAD);
        k_cvt_w<<<grid, 256>>>(Wout);
    }
    // Wi -> linear bf16 hi/lo
    k_cvt_wi<<<(T_ * GI_KP * 80 + 255) / 256, 256>>>(Wi);
    // Wh -> fragment bf16 hi/lo (38 mtiles used)
    {
        dim3 grid(38, 200);
        k_cvt_whf<<<grid, 128>>>(Wh);
    }
    // GI = (gathered state) @ Wi + bi
    {
        dim3 grid(8, 200);
        k_gi_mma<<<grid, 512, GI3_SMEM>>>(q, f, eq, ef, bi);
    }
    // GRU scan (tensor cores)
    k_scan_mma<<<128, 608, SCAN_SMEM>>>(bhn, ic);
    // out = hT @ Wout + bout (tensor cores, 16 warps, K=208, BN=256)
    {
        dim3 grid(8, NT3);
        k_out_mma<<<grid, 512, MMA_SMEM>>>(bout, out);
    }
}